// round 1
// baseline (speedup 1.0000x reference)
#include <cuda_runtime.h>
#include <cstddef>

// Problem constants
#define HH   200
#define WW   200
#define NQ   40000      // H*W
#define DD   256
#define NHD  8
#define HDD  32
#define NBQ2 2

// Scratch (device globals; allocation-free per harness rules)
__device__ float g_vproj[(size_t)NBQ2 * NQ * DD];   // (2, 40000, 8, 32)
__device__ float g_off  [(size_t)NQ * 128];          // raw offsets (40000, 128)
__device__ float g_aw   [(size_t)NQ * 64];           // raw attn logits (40000, 64)
__device__ float g_samp [(size_t)NQ * DD];           // sampled+meaned (40000, 256)

// ---------------------------------------------------------------------------
// Generic fp32 SGEMM: C[M,N] = A[M,K] @ B[K,N] + bias[N] (+ addend[M,N])
// CAT=true: A is virtual concat along K of A0 (cols 0..255) and A1 (256..511),
// both with row stride 256.
// ---------------------------------------------------------------------------
template<int BM, int BN, int BK, int TM, int TN, bool CAT>
__global__ void __launch_bounds__((BM/TM)*(BN/TN))
sgemm_k(const float* __restrict__ A0, const float* __restrict__ A1,
        const float* __restrict__ B,  const float* __restrict__ bias,
        const float* __restrict__ addend, float* __restrict__ C,
        int M, int N, int K)
{
    constexpr int THREADS = (BM/TM)*(BN/TN);
    __shared__ float As[BK][BM];
    __shared__ float Bs[BK][BN];

    const int tid  = threadIdx.x;
    const int brow = blockIdx.y * BM;
    const int bcol = blockIdx.x * BN;
    const int tcol = (tid % (BN/TN)) * TN;
    const int trow = (tid / (BN/TN)) * TM;

    float acc[TM][TN];
    #pragma unroll
    for (int i = 0; i < TM; i++)
        #pragma unroll
        for (int j = 0; j < TN; j++) acc[i][j] = 0.f;

    for (int k0 = 0; k0 < K; k0 += BK) {
        // --- load A tile (transposed into As[k][m]) ---
        #pragma unroll
        for (int t = 0; t < (BM*BK)/(THREADS*4); t++) {
            int li = (tid + t*THREADS) * 4;
            int m  = li / BK, k = li % BK;
            int row = brow + m;
            float4 v = make_float4(0.f, 0.f, 0.f, 0.f);
            if (row < M) {
                int kg = k0 + k;
                const float* src;
                if (CAT) {
                    src = (kg < 256) ? (A0 + (size_t)row*256 + kg)
                                     : (A1 + (size_t)row*256 + (kg - 256));
                } else {
                    src = A0 + (size_t)row*K + kg;
                }
                v = *reinterpret_cast<const float4*>(src);
            }
            As[k+0][m] = v.x; As[k+1][m] = v.y;
            As[k+2][m] = v.z; As[k+3][m] = v.w;
        }
        // --- load B tile ---
        #pragma unroll
        for (int t = 0; t < (BK*BN)/(THREADS*4); t++) {
            int li = (tid + t*THREADS) * 4;
            int k  = li / BN, n = li % BN;
            *reinterpret_cast<float4*>(&Bs[k][n]) =
                *reinterpret_cast<const float4*>(B + (size_t)(k0+k)*N + bcol + n);
        }
        __syncthreads();

        // --- compute ---
        #pragma unroll
        for (int kk = 0; kk < BK; kk++) {
            float areg[TM], breg[TN];
            #pragma unroll
            for (int m = 0; m < TM; m += 4)
                *reinterpret_cast<float4*>(&areg[m]) =
                    *reinterpret_cast<const float4*>(&As[kk][trow + m]);
            #pragma unroll
            for (int n = 0; n < TN; n += 4)
                *reinterpret_cast<float4*>(&breg[n]) =
                    *reinterpret_cast<const float4*>(&Bs[kk][tcol + n]);
            #pragma unroll
            for (int m = 0; m < TM; m++)
                #pragma unroll
                for (int n = 0; n < TN; n++)
                    acc[m][n] = fmaf(areg[m], breg[n], acc[m][n]);
        }
        __syncthreads();
    }

    // --- epilogue ---
    #pragma unroll
    for (int m = 0; m < TM; m++) {
        int row = brow + trow + m;
        if (row < M) {
            #pragma unroll
            for (int n = 0; n < TN; n += 4) {
                int col = bcol + tcol + n;
                float4 o;
                o.x = acc[m][n+0] + bias[col+0];
                o.y = acc[m][n+1] + bias[col+1];
                o.z = acc[m][n+2] + bias[col+2];
                o.w = acc[m][n+3] + bias[col+3];
                if (addend) {
                    float4 a = *reinterpret_cast<const float4*>(
                        addend + (size_t)row*N + col);
                    o.x += a.x; o.y += a.y; o.z += a.z; o.w += a.w;
                }
                *reinterpret_cast<float4*>(C + (size_t)row*N + col) = o;
            }
        }
    }
}

// ---------------------------------------------------------------------------
// Deformable sampling: one warp per (q, h); lane = channel (HD=32).
// Fuses softmax over the 4 points, bilinear 4-corner gather, the NBQ=2 loop,
// and the mean over NBQ.
// ---------------------------------------------------------------------------
__global__ void deform_sample_k(const float* __restrict__ vproj,
                                const float* __restrict__ offr,
                                const float* __restrict__ awr,
                                const float* __restrict__ refp,
                                float* __restrict__ samp)
{
    int gw   = (blockIdx.x * blockDim.x + threadIdx.x) >> 5;
    int lane = threadIdx.x & 31;
    if (gw >= NQ * NHD) return;
    int h = gw & (NHD - 1);
    int q = gw >> 3;

    float rx = refp[q*2 + 0];
    float ry = refp[q*2 + 1];
    const float* offq = offr + (size_t)q * 128;
    const float* awq  = awr  + (size_t)q * 64;

    float acc = 0.f;
    #pragma unroll
    for (int nbq = 0; nbq < 2; nbq++) {
        int cbase = (h*2 + nbq) * 4;
        // softmax over the 4 points
        float a0 = awq[cbase+0], a1 = awq[cbase+1];
        float a2 = awq[cbase+2], a3 = awq[cbase+3];
        float mx = fmaxf(fmaxf(a0, a1), fmaxf(a2, a3));
        float e0 = __expf(a0-mx), e1 = __expf(a1-mx);
        float e2 = __expf(a2-mx), e3 = __expf(a3-mx);
        float inv = 1.f / (e0 + e1 + e2 + e3);
        float aws[4] = {e0*inv, e1*inv, e2*inv, e3*inv};

        const float* vbase = vproj + (size_t)nbq * NQ * DD + h*HDD + lane;

        #pragma unroll
        for (int p = 0; p < 4; p++) {
            int oc = (cbase + p) * 2;
            // x = (rx + off_x/W)*W - 0.5 = rx*W + off_x - 0.5
            float x = fmaf(rx, (float)WW, offq[oc+0]) - 0.5f;
            float y = fmaf(ry, (float)HH, offq[oc+1]) - 0.5f;
            float x0f = floorf(x), y0f = floorf(y);
            float fx = x - x0f, fy = y - y0f;
            int x0 = (int)x0f, y0 = (int)y0f;
            float w = aws[p];

            #pragma unroll
            for (int dy = 0; dy < 2; dy++) {
                #pragma unroll
                for (int dx = 0; dx < 2; dx++) {
                    int xi = x0 + dx, yi = y0 + dy;
                    if (xi >= 0 && xi < WW && yi >= 0 && yi < HH) {
                        float wgt = w * (dx ? fx : 1.f - fx)
                                      * (dy ? fy : 1.f - fy);
                        acc = fmaf(wgt, vbase[(size_t)(yi*WW + xi) * DD], acc);
                    }
                }
            }
        }
    }
    samp[(size_t)q * DD + h*HDD + lane] = acc * 0.5f;   // mean over NBQ
}

// ---------------------------------------------------------------------------
extern "C" void kernel_launch(void* const* d_in, const int* in_sizes, int n_in,
                              void* d_out, int out_size)
{
    const float* query = (const float*)d_in[0];
    const float* value = (const float*)d_in[1];
    const float* refp  = (const float*)d_in[2];
    // d_in[3] spatial_shapes: constant [200,200], hardcoded
    const float* W_v  = (const float*)d_in[4];
    const float* b_v  = (const float*)d_in[5];
    const float* W_so = (const float*)d_in[6];
    const float* b_so = (const float*)d_in[7];
    const float* W_aw = (const float*)d_in[8];
    const float* b_aw = (const float*)d_in[9];
    const float* W_o  = (const float*)d_in[10];
    const float* b_o  = (const float*)d_in[11];
    float* out = (float*)d_out;

    float *vproj, *offp, *awp, *sampp;
    cudaGetSymbolAddress((void**)&vproj, g_vproj);
    cudaGetSymbolAddress((void**)&offp,  g_off);
    cudaGetSymbolAddress((void**)&awp,   g_aw);
    cudaGetSymbolAddress((void**)&sampp, g_samp);

    // GEMM1: vproj = value @ W_v + b_v          (80000 x 256 x 256)
    sgemm_k<128,128,16,8,8,false><<<dim3(2, 625), 256>>>(
        value, nullptr, W_v, b_v, nullptr, vproj, 2*NQ, 256, 256);

    // GEMM2: off = [value0 | query] @ W_so + b_so   (40000 x 128 x 512)
    sgemm_k<128,128,16,8,8,true><<<dim3(1, 313), 256>>>(
        value, query, W_so, b_so, nullptr, offp, NQ, 128, 512);

    // GEMM3: aw = [value0 | query] @ W_aw + b_aw    (40000 x 64 x 512)
    sgemm_k<128,64,16,8,8,true><<<dim3(1, 313), 128>>>(
        value, query, W_aw, b_aw, nullptr, awp, NQ, 64, 512);

    // Deformable sampling + softmax + NBQ mean: one warp per (q, h)
    deform_sample_k<<<(NQ*NHD)/8, 256>>>(vproj, offp, awp, refp, sampp);

    // GEMM5: out = samp @ W_o + b_o + query     (40000 x 256 x 256)
    sgemm_k<128,128,16,8,8,false><<<dim3(2, 313), 256>>>(
        sampp, nullptr, W_o, b_o, query, out, NQ, 256, 256);
}

// round 2
// speedup vs baseline: 1.3211x; 1.3211x over previous
#include <cuda_runtime.h>
#include <cstddef>

#define HH   200
#define WW   200
#define NQ   40000
#define DD   256
#define NHD  8
#define HDD  32
#define NBQ2 2

__device__ float g_vproj[(size_t)NBQ2 * NQ * DD];
__device__ float g_off  [(size_t)NQ * 128];
__device__ float g_aw   [(size_t)NQ * 64];
__device__ float g_samp [(size_t)NQ * DD];

// ---------------------------------------------------------------------------
// Double-buffered fp32 SGEMM: C = A @ B + bias (+ addend)
// ---------------------------------------------------------------------------
template<int BM, int BN, int BK, int TM, int TN>
__global__ void __launch_bounds__((BM/TM)*(BN/TN))
sgemm_db(const float* __restrict__ A, const float* __restrict__ B,
         const float* __restrict__ bias, const float* __restrict__ addend,
         float* __restrict__ C, int M, int N, int K)
{
    constexpr int THREADS = (BM/TM)*(BN/TN);
    constexpr int NA = (BM*BK)/(THREADS*4);
    constexpr int NB = (BK*BN)/(THREADS*4);
    __shared__ float As[2][BK][BM];
    __shared__ float Bs[2][BK][BN];

    const int tid  = threadIdx.x;
    const int brow = blockIdx.y * BM;
    const int bcol = blockIdx.x * BN;
    const int tcol = (tid % (BN/TN)) * TN;
    const int trow = (tid / (BN/TN)) * TM;

    float acc[TM][TN];
    #pragma unroll
    for (int i = 0; i < TM; i++)
        #pragma unroll
        for (int j = 0; j < TN; j++) acc[i][j] = 0.f;

    float4 ra[NA], rb[NB];

    auto gload = [&](int k0) {
        #pragma unroll
        for (int t = 0; t < NA; t++) {
            int li = (tid + t*THREADS) * 4;
            int m = li / BK, k = li % BK;
            int row = brow + m;
            float4 v = make_float4(0.f,0.f,0.f,0.f);
            if (row < M)
                v = *reinterpret_cast<const float4*>(A + (size_t)row*K + k0 + k);
            ra[t] = v;
        }
        #pragma unroll
        for (int t = 0; t < NB; t++) {
            int li = (tid + t*THREADS) * 4;
            int k = li / BN, n = li % BN;
            rb[t] = *reinterpret_cast<const float4*>(B + (size_t)(k0+k)*N + bcol + n);
        }
    };
    auto sstore = [&](int buf) {
        #pragma unroll
        for (int t = 0; t < NA; t++) {
            int li = (tid + t*THREADS) * 4;
            int m = li / BK, k = li % BK;
            As[buf][k+0][m] = ra[t].x; As[buf][k+1][m] = ra[t].y;
            As[buf][k+2][m] = ra[t].z; As[buf][k+3][m] = ra[t].w;
        }
        #pragma unroll
        for (int t = 0; t < NB; t++) {
            int li = (tid + t*THREADS) * 4;
            int k = li / BN, n = li % BN;
            *reinterpret_cast<float4*>(&Bs[buf][k][n]) = rb[t];
        }
    };
    auto compute = [&](int buf) {
        #pragma unroll
        for (int kk = 0; kk < BK; kk++) {
            float areg[TM], breg[TN];
            #pragma unroll
            for (int m = 0; m < TM; m += 4)
                *reinterpret_cast<float4*>(&areg[m]) =
                    *reinterpret_cast<const float4*>(&As[buf][kk][trow + m]);
            #pragma unroll
            for (int n = 0; n < TN; n += 4)
                *reinterpret_cast<float4*>(&breg[n]) =
                    *reinterpret_cast<const float4*>(&Bs[buf][kk][tcol + n]);
            #pragma unroll
            for (int m = 0; m < TM; m++)
                #pragma unroll
                for (int n = 0; n < TN; n++)
                    acc[m][n] = fmaf(areg[m], breg[n], acc[m][n]);
        }
    };

    gload(0); sstore(0); __syncthreads();
    int buf = 0;
    for (int k0 = BK; k0 < K; k0 += BK) {
        gload(k0);
        compute(buf);
        sstore(buf ^ 1);
        __syncthreads();
        buf ^= 1;
    }
    compute(buf);

    #pragma unroll
    for (int m = 0; m < TM; m++) {
        int row = brow + trow + m;
        if (row < M) {
            #pragma unroll
            for (int n = 0; n < TN; n += 4) {
                int col = bcol + tcol + n;
                float4 o;
                o.x = acc[m][n+0] + bias[col+0];
                o.y = acc[m][n+1] + bias[col+1];
                o.z = acc[m][n+2] + bias[col+2];
                o.w = acc[m][n+3] + bias[col+3];
                if (addend) {
                    float4 a = *reinterpret_cast<const float4*>(addend + (size_t)row*N + col);
                    o.x += a.x; o.y += a.y; o.z += a.z; o.w += a.w;
                }
                *reinterpret_cast<float4*>(C + (size_t)row*N + col) = o;
            }
        }
    }
}

// ---------------------------------------------------------------------------
// Dual SGEMM over virtual concat A = [value0 | query] (K=512):
// block cols 0,1 -> off = A @ W_so + b_so (N=128)
// block col  2   -> aw  = A @ W_aw + b_aw (N=64)
// ---------------------------------------------------------------------------
template<int BM, int BN, int BK, int TM, int TN>
__global__ void __launch_bounds__((BM/TM)*(BN/TN))
sgemm_dual(const float* __restrict__ A0, const float* __restrict__ A1,
           const float* __restrict__ Wso, const float* __restrict__ bso,
           const float* __restrict__ Waw, const float* __restrict__ baw,
           float* __restrict__ Coff, float* __restrict__ Caw, int M)
{
    constexpr int K = 512;
    constexpr int THREADS = (BM/TM)*(BN/TN);
    constexpr int NA = (BM*BK)/(THREADS*4);
    constexpr int NB = (BK*BN)/(THREADS*4);
    __shared__ float As[2][BK][BM];
    __shared__ float Bs[2][BK][BN];

    const int tid  = threadIdx.x;
    const int brow = blockIdx.y * BM;
    const bool is_aw = (blockIdx.x == 2);
    const int bcol   = is_aw ? 0 : blockIdx.x * BN;
    const int Nout   = is_aw ? 64 : 128;
    const float* Bm  = is_aw ? Waw : Wso;
    const float* bi  = is_aw ? baw : bso;
    float* Cm        = is_aw ? Caw : Coff;

    const int tcol = (tid % (BN/TN)) * TN;
    const int trow = (tid / (BN/TN)) * TM;

    float acc[TM][TN];
    #pragma unroll
    for (int i = 0; i < TM; i++)
        #pragma unroll
        for (int j = 0; j < TN; j++) acc[i][j] = 0.f;

    float4 ra[NA], rb[NB];

    auto gload = [&](int k0) {
        #pragma unroll
        for (int t = 0; t < NA; t++) {
            int li = (tid + t*THREADS) * 4;
            int m = li / BK, k = li % BK;
            int row = brow + m;
            float4 v = make_float4(0.f,0.f,0.f,0.f);
            if (row < M) {
                int kg = k0 + k;
                const float* src = (kg < 256) ? (A0 + (size_t)row*256 + kg)
                                              : (A1 + (size_t)row*256 + (kg-256));
                v = *reinterpret_cast<const float4*>(src);
            }
            ra[t] = v;
        }
        #pragma unroll
        for (int t = 0; t < NB; t++) {
            int li = (tid + t*THREADS) * 4;
            int k = li / BN, n = li % BN;
            rb[t] = *reinterpret_cast<const float4*>(Bm + (size_t)(k0+k)*Nout + bcol + n);
        }
    };
    auto sstore = [&](int buf) {
        #pragma unroll
        for (int t = 0; t < NA; t++) {
            int li = (tid + t*THREADS) * 4;
            int m = li / BK, k = li % BK;
            As[buf][k+0][m] = ra[t].x; As[buf][k+1][m] = ra[t].y;
            As[buf][k+2][m] = ra[t].z; As[buf][k+3][m] = ra[t].w;
        }
        #pragma unroll
        for (int t = 0; t < NB; t++) {
            int li = (tid + t*THREADS) * 4;
            int k = li / BN, n = li % BN;
            *reinterpret_cast<float4*>(&Bs[buf][k][n]) = rb[t];
        }
    };
    auto compute = [&](int buf) {
        #pragma unroll
        for (int kk = 0; kk < BK; kk++) {
            float areg[TM], breg[TN];
            #pragma unroll
            for (int m = 0; m < TM; m += 4)
                *reinterpret_cast<float4*>(&areg[m]) =
                    *reinterpret_cast<const float4*>(&As[buf][kk][trow + m]);
            #pragma unroll
            for (int n = 0; n < TN; n += 4)
                *reinterpret_cast<float4*>(&breg[n]) =
                    *reinterpret_cast<const float4*>(&Bs[buf][kk][tcol + n]);
            #pragma unroll
            for (int m = 0; m < TM; m++)
                #pragma unroll
                for (int n = 0; n < TN; n++)
                    acc[m][n] = fmaf(areg[m], breg[n], acc[m][n]);
        }
    };

    gload(0); sstore(0); __syncthreads();
    int buf = 0;
    for (int k0 = BK; k0 < K; k0 += BK) {
        gload(k0);
        compute(buf);
        sstore(buf ^ 1);
        __syncthreads();
        buf ^= 1;
    }
    compute(buf);

    #pragma unroll
    for (int m = 0; m < TM; m++) {
        int row = brow + trow + m;
        if (row < M) {
            #pragma unroll
            for (int n = 0; n < TN; n += 4) {
                int col = bcol + tcol + n;
                float4 o;
                o.x = acc[m][n+0] + bi[col+0];
                o.y = acc[m][n+1] + bi[col+1];
                o.z = acc[m][n+2] + bi[col+2];
                o.w = acc[m][n+3] + bi[col+3];
                *reinterpret_cast<float4*>(Cm + (size_t)row*Nout + col) = o;
            }
        }
    }
}

// ---------------------------------------------------------------------------
// Deformable sampling: 8 lanes per (q,h), lane loads float4 (4 of 32 channels).
// Warp covers 4 heads of one q. Branch-free bilinear, fused softmax + NBQ mean.
// ---------------------------------------------------------------------------
__global__ void __launch_bounds__(256)
deform_sample_k(const float* __restrict__ vproj,
                const float* __restrict__ offr,
                const float* __restrict__ awr,
                const float* __restrict__ refp,
                float* __restrict__ samp)
{
    int wg   = (blockIdx.x * 256 + threadIdx.x) >> 5;
    int lane = threadIdx.x & 31;
    int q = wg >> 1;
    if (q >= NQ) return;
    int g = lane >> 3;          // head within warp (0..3)
    int s = lane & 7;           // float4 channel slot (0..7)
    int h = ((wg & 1) << 2) | g;

    float rx = fmaf(refp[2*q+0], (float)WW, -0.5f);
    float ry = fmaf(refp[2*q+1], (float)HH, -0.5f);
    const float* offh = offr + (size_t)q*128 + h*16;   // [nbq][p][2]
    const float* awh  = awr  + (size_t)q*64  + h*8;    // [nbq][p]

    float4 acc = make_float4(0.f,0.f,0.f,0.f);

    #pragma unroll
    for (int nbq = 0; nbq < 2; nbq++) {
        float a0 = awh[nbq*4+0], a1 = awh[nbq*4+1];
        float a2 = awh[nbq*4+2], a3 = awh[nbq*4+3];
        float mx = fmaxf(fmaxf(a0,a1), fmaxf(a2,a3));
        float e0 = __expf(a0-mx), e1 = __expf(a1-mx);
        float e2 = __expf(a2-mx), e3 = __expf(a3-mx);
        float inv = 1.f / (e0+e1+e2+e3);
        float aws[4] = {e0*inv, e1*inv, e2*inv, e3*inv};

        // float4 view: pixel stride = 64 float4s
        const float4* vb = reinterpret_cast<const float4*>(vproj)
                         + (size_t)nbq*NQ*64 + h*8 + s;

        #pragma unroll
        for (int p = 0; p < 4; p++) {
            float x = rx + offh[nbq*8 + p*2 + 0];
            float y = ry + offh[nbq*8 + p*2 + 1];
            float xf = floorf(x), yf = floorf(y);
            float fx = x - xf, fy = y - yf;
            int x0 = (int)xf, y0 = (int)yf;
            int x1 = x0 + 1,  y1 = y0 + 1;

            float vx0 = ((unsigned)x0 < WW) ? 1.f : 0.f;
            float vx1 = ((unsigned)x1 < WW) ? 1.f : 0.f;
            float vy0 = ((unsigned)y0 < HH) ? 1.f : 0.f;
            float vy1 = ((unsigned)y1 < HH) ? 1.f : 0.f;
            int cx0 = min(max(x0,0), WW-1), cx1 = min(max(x1,0), WW-1);
            int cy0 = min(max(y0,0), HH-1), cy1 = min(max(y1,0), HH-1);

            float w   = aws[p];
            float gx1 = fx, gx0 = 1.f - fx;
            float gy1 = fy, gy0 = 1.f - fy;
            float w00 = w*gx0*gy0*vx0*vy0;
            float w01 = w*gx1*gy0*vx1*vy0;
            float w10 = w*gx0*gy1*vx0*vy1;
            float w11 = w*gx1*gy1*vx1*vy1;

            float4 v00 = vb[(size_t)(cy0*WW + cx0) * 64];
            float4 v01 = vb[(size_t)(cy0*WW + cx1) * 64];
            float4 v10 = vb[(size_t)(cy1*WW + cx0) * 64];
            float4 v11 = vb[(size_t)(cy1*WW + cx1) * 64];

            acc.x = fmaf(w00, v00.x, acc.x); acc.y = fmaf(w00, v00.y, acc.y);
            acc.z = fmaf(w00, v00.z, acc.z); acc.w = fmaf(w00, v00.w, acc.w);
            acc.x = fmaf(w01, v01.x, acc.x); acc.y = fmaf(w01, v01.y, acc.y);
            acc.z = fmaf(w01, v01.z, acc.z); acc.w = fmaf(w01, v01.w, acc.w);
            acc.x = fmaf(w10, v10.x, acc.x); acc.y = fmaf(w10, v10.y, acc.y);
            acc.z = fmaf(w10, v10.z, acc.z); acc.w = fmaf(w10, v10.w, acc.w);
            acc.x = fmaf(w11, v11.x, acc.x); acc.y = fmaf(w11, v11.y, acc.y);
            acc.z = fmaf(w11, v11.z, acc.z); acc.w = fmaf(w11, v11.w, acc.w);
        }
    }
    acc.x *= 0.5f; acc.y *= 0.5f; acc.z *= 0.5f; acc.w *= 0.5f;
    *reinterpret_cast<float4*>(samp + (size_t)q*DD + h*HDD + s*4) = acc;
}

// ---------------------------------------------------------------------------
extern "C" void kernel_launch(void* const* d_in, const int* in_sizes, int n_in,
                              void* d_out, int out_size)
{
    const float* query = (const float*)d_in[0];
    const float* value = (const float*)d_in[1];
    const float* refp  = (const float*)d_in[2];
    const float* W_v  = (const float*)d_in[4];
    const float* b_v  = (const float*)d_in[5];
    const float* W_so = (const float*)d_in[6];
    const float* b_so = (const float*)d_in[7];
    const float* W_aw = (const float*)d_in[8];
    const float* b_aw = (const float*)d_in[9];
    const float* W_o  = (const float*)d_in[10];
    const float* b_o  = (const float*)d_in[11];
    float* out = (float*)d_out;

    float *vproj, *offp, *awp, *sampp;
    cudaGetSymbolAddress((void**)&vproj, g_vproj);
    cudaGetSymbolAddress((void**)&offp,  g_off);
    cudaGetSymbolAddress((void**)&awp,   g_aw);
    cudaGetSymbolAddress((void**)&sampp, g_samp);

    // GEMM1: vproj = value @ W_v + b_v          (80000 x 256 x 256)
    sgemm_db<128,128,16,8,8><<<dim3(2, 625), 256>>>(
        value, W_v, b_v, nullptr, vproj, 2*NQ, 256, 256);

    // GEMM2+3 fused: [value0|query] @ {W_so,W_aw}  (40000 x {128,64} x 512)
    sgemm_dual<128,64,16,8,8><<<dim3(3, 313), 128>>>(
        value, query, W_so, b_so, W_aw, b_aw, offp, awp, NQ);

    // Sampling: 2 warps per q (4 heads each)
    deform_sample_k<<<(NQ*2 + 7)/8, 256>>>(vproj, offp, awp, refp, sampp);

    // GEMM5: out = samp @ W_o + b_o + query     (40000 x 256 x 256)
    sgemm_db<128,128,16,8,8><<<dim3(2, 313), 256>>>(
        sampp, W_o, b_o, query, out, NQ, 256, 256);
}

// round 3
// speedup vs baseline: 1.3255x; 1.0033x over previous
#include <cuda_runtime.h>
#include <cstddef>

#define HH   200
#define WW   200
#define NQ   40000
#define DD   256
#define NHD  8
#define HDD  32
#define NBQ2 2

__device__ float g_vproj[(size_t)NBQ2 * NQ * DD];
__device__ float g_off  [(size_t)NQ * 128];
__device__ float g_aw   [(size_t)NQ * 64];
__device__ float g_samp [(size_t)NQ * DD];

// ---------------------------------------------------------------------------
// Wide-tile fp32 SGEMM. BM=128, BN=64*TNJ, BK=8, 256 threads, thread tile 8x(4*TNJ).
// Thread rows: ridx*4+{0..3} and 64+ridx*4+{0..3}; cols: cidx*4 + j*64.
// DUAL=0: C0[M,BN] = A0[M,K] @ B0[K,BN] + bias0 (+ addend). Row strides = BN.
// DUAL=1: A = concat(A0,A1) along K (each stride 256, K=512);
//         cols 0..127 -> C0 = A@B0(+bias0) [stride 128]; cols 128..191 -> C1 = A@B1(+bias1) [stride 64].
// ---------------------------------------------------------------------------
template<int TNJ, int DUAL>
__global__ void __launch_bounds__(256, 1)
sgemm_wide(const float* __restrict__ A0, const float* __restrict__ A1,
           const float* __restrict__ B0, const float* __restrict__ B1,
           const float* __restrict__ bias0, const float* __restrict__ bias1,
           const float* __restrict__ addend,
           float* __restrict__ C0, float* __restrict__ C1,
           int M, int K)
{
    constexpr int BM = 128, BK = 8, BN = 64 * TNJ;
    constexpr int NB4 = (BK * BN) / 4;          // float4s in B tile
    constexpr int NBLD = (NB4 + 255) / 256;     // B loads per thread

    __shared__ float As[2][BK][BM];
    __shared__ float Bs[2][BK][BN];

    const int tid  = threadIdx.x;
    const int brow = blockIdx.x * BM;
    const int ridx = tid >> 4;        // 0..15
    const int cidx = tid & 15;        // 0..15

    // A global load mapping: one float4 per thread
    const int am = tid >> 1;              // row within tile 0..127
    const int ak = (tid & 1) * 4;         // k offset 0 or 4

    float4 acc[8][TNJ];
    #pragma unroll
    for (int i = 0; i < 8; i++)
        #pragma unroll
        for (int j = 0; j < TNJ; j++) acc[i][j] = make_float4(0.f,0.f,0.f,0.f);

    float4 ra;
    float4 rb[NBLD];

    auto gload = [&](int k0) {
        {
            int row = brow + am;
            float4 v = make_float4(0.f,0.f,0.f,0.f);
            if (row < M) {
                int kg = k0 + ak;
                const float* src;
                if (DUAL) {
                    src = (kg < 256) ? (A0 + (size_t)row*256 + kg)
                                     : (A1 + (size_t)row*256 + (kg-256));
                } else {
                    src = A0 + (size_t)row*K + kg;
                }
                v = *reinterpret_cast<const float4*>(src);
            }
            ra = v;
        }
        #pragma unroll
        for (int t = 0; t < NBLD; t++) {
            int idx = tid + t*256;
            if (NB4 % 256 == 0 || idx < NB4) {
                int k   = idx / (BN/4);
                int col = (idx % (BN/4)) * 4;
                const float* src;
                if (DUAL) {
                    src = (col < 128) ? (B0 + (size_t)(k0+k)*128 + col)
                                      : (B1 + (size_t)(k0+k)*64 + (col-128));
                } else {
                    src = B0 + (size_t)(k0+k)*BN + col;
                }
                rb[t] = *reinterpret_cast<const float4*>(src);
            }
        }
    };
    auto sstore = [&](int buf) {
        As[buf][ak+0][am] = ra.x;
        As[buf][ak+1][am] = ra.y;
        As[buf][ak+2][am] = ra.z;
        As[buf][ak+3][am] = ra.w;
        #pragma unroll
        for (int t = 0; t < NBLD; t++) {
            int idx = tid + t*256;
            if (NB4 % 256 == 0 || idx < NB4) {
                int k   = idx / (BN/4);
                int col = (idx % (BN/4)) * 4;
                *reinterpret_cast<float4*>(&Bs[buf][k][col]) = rb[t];
            }
        }
    };
    auto compute = [&](int buf) {
        #pragma unroll
        for (int kk = 0; kk < BK; kk++) {
            float4 a0 = *reinterpret_cast<const float4*>(&As[buf][kk][ridx*4]);
            float4 a1 = *reinterpret_cast<const float4*>(&As[buf][kk][64 + ridx*4]);
            float4 b[TNJ];
            #pragma unroll
            for (int j = 0; j < TNJ; j++)
                b[j] = *reinterpret_cast<const float4*>(&Bs[buf][kk][cidx*4 + j*64]);
            float am8[8] = {a0.x,a0.y,a0.z,a0.w, a1.x,a1.y,a1.z,a1.w};
            #pragma unroll
            for (int mi = 0; mi < 8; mi++) {
                #pragma unroll
                for (int j = 0; j < TNJ; j++) {
                    acc[mi][j].x = fmaf(am8[mi], b[j].x, acc[mi][j].x);
                    acc[mi][j].y = fmaf(am8[mi], b[j].y, acc[mi][j].y);
                    acc[mi][j].z = fmaf(am8[mi], b[j].z, acc[mi][j].z);
                    acc[mi][j].w = fmaf(am8[mi], b[j].w, acc[mi][j].w);
                }
            }
        }
    };

    gload(0); sstore(0); __syncthreads();
    int buf = 0;
    for (int k0 = BK; k0 < K; k0 += BK) {
        gload(k0);
        compute(buf);
        sstore(buf ^ 1);
        __syncthreads();
        buf ^= 1;
    }
    compute(buf);

    // epilogue
    #pragma unroll
    for (int mi = 0; mi < 8; mi++) {
        int row = brow + (mi >> 2)*64 + ridx*4 + (mi & 3);
        if (row < M) {
            #pragma unroll
            for (int j = 0; j < TNJ; j++) {
                int col = cidx*4 + j*64;
                float4 o = acc[mi][j];
                if (DUAL) {
                    if (col < 128) {
                        o.x += bias0[col+0]; o.y += bias0[col+1];
                        o.z += bias0[col+2]; o.w += bias0[col+3];
                        *reinterpret_cast<float4*>(C0 + (size_t)row*128 + col) = o;
                    } else {
                        int c = col - 128;
                        o.x += bias1[c+0]; o.y += bias1[c+1];
                        o.z += bias1[c+2]; o.w += bias1[c+3];
                        *reinterpret_cast<float4*>(C1 + (size_t)row*64 + c) = o;
                    }
                } else {
                    o.x += bias0[col+0]; o.y += bias0[col+1];
                    o.z += bias0[col+2]; o.w += bias0[col+3];
                    if (addend) {
                        float4 a = *reinterpret_cast<const float4*>(addend + (size_t)row*BN + col);
                        o.x += a.x; o.y += a.y; o.z += a.z; o.w += a.w;
                    }
                    *reinterpret_cast<float4*>(C0 + (size_t)row*BN + col) = o;
                }
            }
        }
    }
}

// ---------------------------------------------------------------------------
// Deformable sampling: 8 lanes per (q,h), lane loads float4 (4 of 32 channels).
// ---------------------------------------------------------------------------
__global__ void __launch_bounds__(256)
deform_sample_k(const float* __restrict__ vproj,
                const float* __restrict__ offr,
                const float* __restrict__ awr,
                const float* __restrict__ refp,
                float* __restrict__ samp)
{
    int wg   = (blockIdx.x * 256 + threadIdx.x) >> 5;
    int lane = threadIdx.x & 31;
    int q = wg >> 1;
    if (q >= NQ) return;
    int g = lane >> 3;
    int s = lane & 7;
    int h = ((wg & 1) << 2) | g;

    float rx = fmaf(refp[2*q+0], (float)WW, -0.5f);
    float ry = fmaf(refp[2*q+1], (float)HH, -0.5f);
    const float* offh = offr + (size_t)q*128 + h*16;
    const float* awh  = awr  + (size_t)q*64  + h*8;

    float4 acc = make_float4(0.f,0.f,0.f,0.f);

    #pragma unroll
    for (int nbq = 0; nbq < 2; nbq++) {
        float a0 = awh[nbq*4+0], a1 = awh[nbq*4+1];
        float a2 = awh[nbq*4+2], a3 = awh[nbq*4+3];
        float mx = fmaxf(fmaxf(a0,a1), fmaxf(a2,a3));
        float e0 = __expf(a0-mx), e1 = __expf(a1-mx);
        float e2 = __expf(a2-mx), e3 = __expf(a3-mx);
        float inv = 1.f / (e0+e1+e2+e3);
        float aws[4] = {e0*inv, e1*inv, e2*inv, e3*inv};

        const float4* vb = reinterpret_cast<const float4*>(vproj)
                         + (size_t)nbq*NQ*64 + h*8 + s;

        #pragma unroll
        for (int p = 0; p < 4; p++) {
            float x = rx + offh[nbq*8 + p*2 + 0];
            float y = ry + offh[nbq*8 + p*2 + 1];
            float xf = floorf(x), yf = floorf(y);
            float fx = x - xf, fy = y - yf;
            int x0 = (int)xf, y0 = (int)yf;
            int x1 = x0 + 1,  y1 = y0 + 1;

            float vx0 = ((unsigned)x0 < WW) ? 1.f : 0.f;
            float vx1 = ((unsigned)x1 < WW) ? 1.f : 0.f;
            float vy0 = ((unsigned)y0 < HH) ? 1.f : 0.f;
            float vy1 = ((unsigned)y1 < HH) ? 1.f : 0.f;
            int cx0 = min(max(x0,0), WW-1), cx1 = min(max(x1,0), WW-1);
            int cy0 = min(max(y0,0), HH-1), cy1 = min(max(y1,0), HH-1);

            float w   = aws[p];
            float gx1 = fx, gx0 = 1.f - fx;
            float gy1 = fy, gy0 = 1.f - fy;
            float w00 = w*gx0*gy0*vx0*vy0;
            float w01 = w*gx1*gy0*vx1*vy0;
            float w10 = w*gx0*gy1*vx0*vy1;
            float w11 = w*gx1*gy1*vx1*vy1;

            float4 v00 = vb[(size_t)(cy0*WW + cx0) * 64];
            float4 v01 = vb[(size_t)(cy0*WW + cx1) * 64];
            float4 v10 = vb[(size_t)(cy1*WW + cx0) * 64];
            float4 v11 = vb[(size_t)(cy1*WW + cx1) * 64];

            acc.x = fmaf(w00, v00.x, acc.x); acc.y = fmaf(w00, v00.y, acc.y);
            acc.z = fmaf(w00, v00.z, acc.z); acc.w = fmaf(w00, v00.w, acc.w);
            acc.x = fmaf(w01, v01.x, acc.x); acc.y = fmaf(w01, v01.y, acc.y);
            acc.z = fmaf(w01, v01.z, acc.z); acc.w = fmaf(w01, v01.w, acc.w);
            acc.x = fmaf(w10, v10.x, acc.x); acc.y = fmaf(w10, v10.y, acc.y);
            acc.z = fmaf(w10, v10.z, acc.z); acc.w = fmaf(w10, v10.w, acc.w);
            acc.x = fmaf(w11, v11.x, acc.x); acc.y = fmaf(w11, v11.y, acc.y);
            acc.z = fmaf(w11, v11.z, acc.z); acc.w = fmaf(w11, v11.w, acc.w);
        }
    }
    acc.x *= 0.5f; acc.y *= 0.5f; acc.z *= 0.5f; acc.w *= 0.5f;
    *reinterpret_cast<float4*>(samp + (size_t)q*DD + h*HDD + s*4) = acc;
}

// ---------------------------------------------------------------------------
extern "C" void kernel_launch(void* const* d_in, const int* in_sizes, int n_in,
                              void* d_out, int out_size)
{
    const float* query = (const float*)d_in[0];
    const float* value = (const float*)d_in[1];
    const float* refp  = (const float*)d_in[2];
    const float* W_v  = (const float*)d_in[4];
    const float* b_v  = (const float*)d_in[5];
    const float* W_so = (const float*)d_in[6];
    const float* b_so = (const float*)d_in[7];
    const float* W_aw = (const float*)d_in[8];
    const float* b_aw = (const float*)d_in[9];
    const float* W_o  = (const float*)d_in[10];
    const float* b_o  = (const float*)d_in[11];
    float* out = (float*)d_out;

    float *vproj, *offp, *awp, *sampp;
    cudaGetSymbolAddress((void**)&vproj, g_vproj);
    cudaGetSymbolAddress((void**)&offp,  g_off);
    cudaGetSymbolAddress((void**)&awp,   g_aw);
    cudaGetSymbolAddress((void**)&sampp, g_samp);

    // GEMM1: vproj = value @ W_v + b_v          (80000 x 256 x 256)
    sgemm_wide<4,0><<<625, 256>>>(
        value, nullptr, W_v, nullptr, b_v, nullptr, nullptr,
        vproj, nullptr, 2*NQ, 256);

    // GEMM2+3 fused: [value0|query] @ {W_so,W_aw}  (40000 x {128,64} x 512)
    sgemm_wide<3,1><<<313, 256>>>(
        value, query, W_so, W_aw, b_so, b_aw, nullptr,
        offp, awp, NQ, 512);

    // Sampling: 2 warps per q (4 heads each)
    deform_sample_k<<<(NQ*2 + 7)/8, 256>>>(vproj, offp, awp, refp, sampp);

    // GEMM5: out = samp @ W_o + b_o + query     (40000 x 256 x 256)
    sgemm_wide<4,0><<<313, 256>>>(
        sampp, nullptr, W_o, nullptr, b_o, nullptr, query,
        out, nullptr, NQ, 256);
}

// round 6
// speedup vs baseline: 1.8716x; 1.4120x over previous
#include <cuda_runtime.h>
#include <cuda_bf16.h>
#include <cstdint>
#include <cstddef>

#define HH   200
#define WW   200
#define NQ   40000
#define DD   256

__device__ float g_vproj[(size_t)2 * NQ * DD];
__device__ float g_off  [(size_t)NQ * 128];
__device__ float g_aw   [(size_t)NQ * 64];
__device__ float g_samp [(size_t)NQ * DD];

// ---------------------------------------------------------------------------
// bf16 split: a = hi + lo (each bf16), packed pairs
// ---------------------------------------------------------------------------
__device__ __forceinline__ void split2(float a, float b, uint32_t& hi, uint32_t& lo) {
    __nv_bfloat162 h = __floats2bfloat162_rn(a, b);
    float ha = __low2float(h), hb = __high2float(h);
    __nv_bfloat162 l = __floats2bfloat162_rn(a - ha, b - hb);
    hi = *reinterpret_cast<uint32_t*>(&h);
    lo = *reinterpret_cast<uint32_t*>(&l);
}
__device__ __forceinline__ void split4(float4 v, uint2& hi, uint2& lo) {
    split2(v.x, v.y, hi.x, lo.x);
    split2(v.z, v.w, hi.y, lo.y);
}

__device__ __forceinline__ void mma_bf16(float* c, const uint32_t* a, const uint32_t* b) {
    asm volatile(
        "mma.sync.aligned.m16n8k16.row.col.f32.bf16.bf16.f32 "
        "{%0,%1,%2,%3}, {%4,%5,%6,%7}, {%8,%9}, {%0,%1,%2,%3};"
        : "+f"(c[0]), "+f"(c[1]), "+f"(c[2]), "+f"(c[3])
        : "r"(a[0]), "r"(a[1]), "r"(a[2]), "r"(a[3]), "r"(b[0]), "r"(b[1]));
}

// ---------------------------------------------------------------------------
// HMMA bf16x2 (3-product) GEMM.
// Block: 128 x BN (BN = 32*NTN), 8 warps = 2(m) x 4(n); warp tile 64 x 8*NTN.
// K chunks of 32. A [m][k] row-major smem; B [n][k] transposed smem; KP=40 pad.
// DUAL: A = concat(A0,A1) (row stride 256 each, KTOT=512); global output cols
// [0,128) -> C0 (stride 128, bias0), [128,192) -> C1 (stride 64, bias1).
// Non-dual: N = 256 total (grid.x * BN), C0 stride 256, optional addend.
// ---------------------------------------------------------------------------
template<int NTN, int DUAL, int KTOT>
__global__ void __launch_bounds__(256, 1)
hmma_gemm(const float* __restrict__ A0, const float* __restrict__ A1,
          const float* __restrict__ B0, const float* __restrict__ B1,
          const float* __restrict__ bias0, const float* __restrict__ bias1,
          const float* __restrict__ addend,
          float* __restrict__ C0, float* __restrict__ C1, int M)
{
    constexpr int BN  = 32 * NTN;
    constexpr int KP  = 40;
    constexpr int NCH = KTOT / 32;

    extern __shared__ __nv_bfloat16 sm[];
    __nv_bfloat16* Ahs = sm;
    __nv_bfloat16* Als = sm + 128 * KP;
    __nv_bfloat16* Bhs = sm + 256 * KP;
    __nv_bfloat16* Bls = sm + 256 * KP + BN * KP;

    const int tid = threadIdx.x;
    const int wid = tid >> 5, lane = tid & 31;
    const int g = lane >> 2, t = lane & 3;
    const int warp_m = wid >> 2, warp_n = wid & 3;
    const int brow = blockIdx.y * 128;
    const int bcol = blockIdx.x * BN;

    float acc[4][NTN][4];
    #pragma unroll
    for (int i = 0; i < 4; i++)
        #pragma unroll
        for (int j = 0; j < NTN; j++)
            #pragma unroll
            for (int k = 0; k < 4; k++) acc[i][j][k] = 0.f;

    // staging registers (converted bf16 pairs)
    uint2 sAh[4], sAl[4];
    uint2 sBh[4], sBl[4];
    const int am = tid >> 3, akq = tid & 7;   // fixed per-thread A map base (j adds 256)
    const int bkq = tid & 7, bnq = tid >> 3;  // B task map (task = tid)
    const bool bact = (tid < 2 * BN);

    auto gload = [&](int ch) {
        const int k0 = ch * 32;
        #pragma unroll
        for (int j = 0; j < 4; j++) {
            int idx = tid + j * 256;
            int m = idx >> 3, kq = idx & 7;
            int row = brow + m;
            float4 v = make_float4(0.f, 0.f, 0.f, 0.f);
            if (row < M) {
                int kg = k0 + kq * 4;
                const float* src;
                if (DUAL)
                    src = (kg < 256) ? (A0 + (size_t)row * 256 + kg)
                                     : (A1 + (size_t)row * 256 + (kg - 256));
                else
                    src = A0 + (size_t)row * KTOT + kg;
                v = *reinterpret_cast<const float4*>(src);
            }
            split4(v, sAh[j], sAl[j]);
        }
        if (bact) {
            float4 r[4];
            #pragma unroll
            for (int i = 0; i < 4; i++) {
                int krow = k0 + bkq * 4 + i;
                int n = bcol + bnq * 4;
                const float* src;
                if (DUAL)
                    src = (n < 128) ? (B0 + (size_t)krow * 128 + n)
                                    : (B1 + (size_t)krow * 64 + (n - 128));
                else
                    src = B0 + (size_t)krow * 256 + n;
                r[i] = *reinterpret_cast<const float4*>(src);
            }
            #pragma unroll
            for (int j = 0; j < 4; j++) {
                float4 kv = make_float4((&r[0].x)[j], (&r[1].x)[j],
                                        (&r[2].x)[j], (&r[3].x)[j]);
                split4(kv, sBh[j], sBl[j]);
            }
        }
    };
    auto sstore = [&]() {
        #pragma unroll
        for (int j = 0; j < 4; j++) {
            int idx = tid + j * 256;
            int m = idx >> 3, kq = idx & 7;
            *reinterpret_cast<uint2*>(&Ahs[m * KP + kq * 4]) = sAh[j];
            *reinterpret_cast<uint2*>(&Als[m * KP + kq * 4]) = sAl[j];
        }
        if (bact) {
            #pragma unroll
            for (int j = 0; j < 4; j++) {
                int n = bnq * 4 + j;
                *reinterpret_cast<uint2*>(&Bhs[n * KP + bkq * 4]) = sBh[j];
                *reinterpret_cast<uint2*>(&Bls[n * KP + bkq * 4]) = sBl[j];
            }
        }
    };
    auto compute = [&]() {
        #pragma unroll
        for (int ks = 0; ks < 2; ks++) {
            const int bk = ks * 16;
            uint32_t Ahf[4][4], Alf[4][4];
            #pragma unroll
            for (int mt = 0; mt < 4; mt++) {
                int r0 = (warp_m * 64 + mt * 16 + g) * KP + bk + 2 * t;
                int r1 = r0 + 8 * KP;
                Ahf[mt][0] = *reinterpret_cast<const uint32_t*>(&Ahs[r0]);
                Ahf[mt][1] = *reinterpret_cast<const uint32_t*>(&Ahs[r1]);
                Ahf[mt][2] = *reinterpret_cast<const uint32_t*>(&Ahs[r0 + 8]);
                Ahf[mt][3] = *reinterpret_cast<const uint32_t*>(&Ahs[r1 + 8]);
                Alf[mt][0] = *reinterpret_cast<const uint32_t*>(&Als[r0]);
                Alf[mt][1] = *reinterpret_cast<const uint32_t*>(&Als[r1]);
                Alf[mt][2] = *reinterpret_cast<const uint32_t*>(&Als[r0 + 8]);
                Alf[mt][3] = *reinterpret_cast<const uint32_t*>(&Als[r1 + 8]);
            }
            uint32_t Bhf[NTN][2], Blf[NTN][2];
            #pragma unroll
            for (int nt = 0; nt < NTN; nt++) {
                int o = (warp_n * 8 * NTN + nt * 8 + g) * KP + bk + 2 * t;
                Bhf[nt][0] = *reinterpret_cast<const uint32_t*>(&Bhs[o]);
                Bhf[nt][1] = *reinterpret_cast<const uint32_t*>(&Bhs[o + 8]);
                Blf[nt][0] = *reinterpret_cast<const uint32_t*>(&Bls[o]);
                Blf[nt][1] = *reinterpret_cast<const uint32_t*>(&Bls[o + 8]);
            }
            #pragma unroll
            for (int mt = 0; mt < 4; mt++)
                #pragma unroll
                for (int nt = 0; nt < NTN; nt++)
                    mma_bf16(acc[mt][nt], Ahf[mt], Bhf[nt]);
            #pragma unroll
            for (int mt = 0; mt < 4; mt++)
                #pragma unroll
                for (int nt = 0; nt < NTN; nt++)
                    mma_bf16(acc[mt][nt], Ahf[mt], Blf[nt]);
            #pragma unroll
            for (int mt = 0; mt < 4; mt++)
                #pragma unroll
                for (int nt = 0; nt < NTN; nt++)
                    mma_bf16(acc[mt][nt], Alf[mt], Bhf[nt]);
        }
    };

    gload(0);
    sstore();
    __syncthreads();
    for (int ch = 1; ch < NCH; ch++) {
        gload(ch);
        compute();
        __syncthreads();
        sstore();
        __syncthreads();
    }
    compute();

    // ---- epilogue ----
    #pragma unroll
    for (int mt = 0; mt < 4; mt++) {
        int r0 = brow + warp_m * 64 + mt * 16 + g;
        #pragma unroll
        for (int nt = 0; nt < NTN; nt++) {
            int c = bcol + warp_n * 8 * NTN + nt * 8 + 2 * t;
            float2 v0 = make_float2(acc[mt][nt][0], acc[mt][nt][1]);
            float2 v1 = make_float2(acc[mt][nt][2], acc[mt][nt][3]);
            if (DUAL) {
                if (c < 128) {
                    float2 b = *reinterpret_cast<const float2*>(bias0 + c);
                    v0.x += b.x; v0.y += b.y; v1.x += b.x; v1.y += b.y;
                    if (r0 < M)
                        *reinterpret_cast<float2*>(C0 + (size_t)r0 * 128 + c) = v0;
                    if (r0 + 8 < M)
                        *reinterpret_cast<float2*>(C0 + (size_t)(r0 + 8) * 128 + c) = v1;
                } else {
                    int cc = c - 128;
                    float2 b = *reinterpret_cast<const float2*>(bias1 + cc);
                    v0.x += b.x; v0.y += b.y; v1.x += b.x; v1.y += b.y;
                    if (r0 < M)
                        *reinterpret_cast<float2*>(C1 + (size_t)r0 * 64 + cc) = v0;
                    if (r0 + 8 < M)
                        *reinterpret_cast<float2*>(C1 + (size_t)(r0 + 8) * 64 + cc) = v1;
                }
            } else {
                float2 b = *reinterpret_cast<const float2*>(bias0 + c);
                v0.x += b.x; v0.y += b.y; v1.x += b.x; v1.y += b.y;
                if (r0 < M) {
                    if (addend) {
                        float2 a = *reinterpret_cast<const float2*>(
                            addend + (size_t)r0 * 256 + c);
                        v0.x += a.x; v0.y += a.y;
                    }
                    *reinterpret_cast<float2*>(C0 + (size_t)r0 * 256 + c) = v0;
                }
                if (r0 + 8 < M) {
                    if (addend) {
                        float2 a = *reinterpret_cast<const float2*>(
                            addend + (size_t)(r0 + 8) * 256 + c);
                        v1.x += a.x; v1.y += a.y;
                    }
                    *reinterpret_cast<float2*>(C0 + (size_t)(r0 + 8) * 256 + c) = v1;
                }
            }
        }
    }
}

// ---------------------------------------------------------------------------
// Deformable sampling (unchanged)
// ---------------------------------------------------------------------------
__global__ void __launch_bounds__(256)
deform_sample_k(const float* __restrict__ vproj,
                const float* __restrict__ offr,
                const float* __restrict__ awr,
                const float* __restrict__ refp,
                float* __restrict__ samp)
{
    int wg   = (blockIdx.x * 256 + threadIdx.x) >> 5;
    int lane = threadIdx.x & 31;
    int q = wg >> 1;
    if (q >= NQ) return;
    int g = lane >> 3;
    int s = lane & 7;
    int h = ((wg & 1) << 2) | g;

    float rx = fmaf(refp[2*q+0], (float)WW, -0.5f);
    float ry = fmaf(refp[2*q+1], (float)HH, -0.5f);
    const float* offh = offr + (size_t)q*128 + h*16;
    const float* awh  = awr  + (size_t)q*64  + h*8;

    float4 acc = make_float4(0.f,0.f,0.f,0.f);

    #pragma unroll
    for (int nbq = 0; nbq < 2; nbq++) {
        float a0 = awh[nbq*4+0], a1 = awh[nbq*4+1];
        float a2 = awh[nbq*4+2], a3 = awh[nbq*4+3];
        float mx = fmaxf(fmaxf(a0,a1), fmaxf(a2,a3));
        float e0 = __expf(a0-mx), e1 = __expf(a1-mx);
        float e2 = __expf(a2-mx), e3 = __expf(a3-mx);
        float inv = 1.f / (e0+e1+e2+e3);
        float aws[4] = {e0*inv, e1*inv, e2*inv, e3*inv};

        const float4* vb = reinterpret_cast<const float4*>(vproj)
                         + (size_t)nbq*NQ*64 + h*8 + s;

        #pragma unroll
        for (int p = 0; p < 4; p++) {
            float x = rx + offh[nbq*8 + p*2 + 0];
            float y = ry + offh[nbq*8 + p*2 + 1];
            float xf = floorf(x), yf = floorf(y);
            float fx = x - xf, fy = y - yf;
            int x0 = (int)xf, y0 = (int)yf;
            int x1 = x0 + 1,  y1 = y0 + 1;

            float vx0 = ((unsigned)x0 < WW) ? 1.f : 0.f;
            float vx1 = ((unsigned)x1 < WW) ? 1.f : 0.f;
            float vy0 = ((unsigned)y0 < HH) ? 1.f : 0.f;
            float vy1 = ((unsigned)y1 < HH) ? 1.f : 0.f;
            int cx0 = min(max(x0,0), WW-1), cx1 = min(max(x1,0), WW-1);
            int cy0 = min(max(y0,0), HH-1), cy1 = min(max(y1,0), HH-1);

            float w   = aws[p];
            float gx1 = fx, gx0 = 1.f - fx;
            float gy1 = fy, gy0 = 1.f - fy;
            float w00 = w*gx0*gy0*vx0*vy0;
            float w01 = w*gx1*gy0*vx1*vy0;
            float w10 = w*gx0*gy1*vx0*vy1;
            float w11 = w*gx1*gy1*vx1*vy1;

            float4 v00 = vb[(size_t)(cy0*WW + cx0) * 64];
            float4 v01 = vb[(size_t)(cy0*WW + cx1) * 64];
            float4 v10 = vb[(size_t)(cy1*WW + cx0) * 64];
            float4 v11 = vb[(size_t)(cy1*WW + cx1) * 64];

            acc.x = fmaf(w00, v00.x, acc.x); acc.y = fmaf(w00, v00.y, acc.y);
            acc.z = fmaf(w00, v00.z, acc.z); acc.w = fmaf(w00, v00.w, acc.w);
            acc.x = fmaf(w01, v01.x, acc.x); acc.y = fmaf(w01, v01.y, acc.y);
            acc.z = fmaf(w01, v01.z, acc.z); acc.w = fmaf(w01, v01.w, acc.w);
            acc.x = fmaf(w10, v10.x, acc.x); acc.y = fmaf(w10, v10.y, acc.y);
            acc.z = fmaf(w10, v10.z, acc.z); acc.w = fmaf(w10, v10.w, acc.w);
            acc.x = fmaf(w11, v11.x, acc.x); acc.y = fmaf(w11, v11.y, acc.y);
            acc.z = fmaf(w11, v11.z, acc.z); acc.w = fmaf(w11, v11.w, acc.w);
        }
    }
    acc.x *= 0.5f; acc.y *= 0.5f; acc.z *= 0.5f; acc.w *= 0.5f;
    *reinterpret_cast<float4*>(samp + (size_t)q*DD + h*32 + s*4) = acc;
}

// ---------------------------------------------------------------------------
extern "C" void kernel_launch(void* const* d_in, const int* in_sizes, int n_in,
                              void* d_out, int out_size)
{
    const float* query = (const float*)d_in[0];
    const float* value = (const float*)d_in[1];
    const float* refp  = (const float*)d_in[2];
    const float* W_v  = (const float*)d_in[4];
    const float* b_v  = (const float*)d_in[5];
    const float* W_so = (const float*)d_in[6];
    const float* b_so = (const float*)d_in[7];
    const float* W_aw = (const float*)d_in[8];
    const float* b_aw = (const float*)d_in[9];
    const float* W_o  = (const float*)d_in[10];
    const float* b_o  = (const float*)d_in[11];
    float* out = (float*)d_out;

    float *vproj, *offp, *awp, *sampp;
    cudaGetSymbolAddress((void**)&vproj, g_vproj);
    cudaGetSymbolAddress((void**)&offp,  g_off);
    cudaGetSymbolAddress((void**)&awp,   g_aw);
    cudaGetSymbolAddress((void**)&sampp, g_samp);

    constexpr int KP = 40;
    constexpr int SM128 = (256 + 2 * 128) * KP * 2;  // 40960 B
    constexpr int SM96  = (256 + 2 * 96)  * KP * 2;  // 35840 B
    cudaFuncSetAttribute(hmma_gemm<4,0,256>,
        cudaFuncAttributeMaxDynamicSharedMemorySize, SM128);
    cudaFuncSetAttribute(hmma_gemm<3,1,512>,
        cudaFuncAttributeMaxDynamicSharedMemorySize, SM96);

    // GEMM1: vproj = value @ W_v + b_v          (80000 x 256 x 256)
    hmma_gemm<4,0,256><<<dim3(2, 625), 256, SM128>>>(
        value, nullptr, W_v, nullptr, b_v, nullptr, nullptr,
        vproj, nullptr, 2*NQ);

    // GEMM2+3: [value0|query] @ {W_so,W_aw}     (40000 x {128,64} x 512)
    hmma_gemm<3,1,512><<<dim3(2, 313), 256, SM96>>>(
        value, query, W_so, W_aw, b_so, b_aw, nullptr,
        offp, awp, NQ);

    // Sampling
    deform_sample_k<<<(NQ*2 + 7)/8, 256>>>(vproj, offp, awp, refp, sampp);

    // GEMM5: out = samp @ W_o + b_o + query     (40000 x 256 x 256)
    hmma_gemm<4,0,256><<<dim3(2, 313), 256, SM128>>>(
        sampp, nullptr, W_o, nullptr, b_o, nullptr, query,
        out, nullptr, NQ);
}

// round 7
// speedup vs baseline: 1.9218x; 1.0268x over previous
#include <cuda_runtime.h>
#include <cuda_bf16.h>
#include <cstdint>
#include <cstddef>

#define HH   200
#define WW   200
#define NQ   40000
#define DD   256

__device__ float g_vproj[(size_t)2 * NQ * DD];
__device__ float g_off  [(size_t)NQ * 128];
__device__ float g_aw   [(size_t)NQ * 64];
__device__ float g_samp [(size_t)NQ * DD];

// ---------------------------------------------------------------------------
// helpers
// ---------------------------------------------------------------------------
__device__ __forceinline__ uint32_t smem_u32(const void* p) {
    uint32_t a;
    asm("{ .reg .u64 t; cvta.to.shared.u64 t, %1; cvt.u32.u64 %0, t; }"
        : "=r"(a) : "l"(p));
    return a;
}
__device__ __forceinline__ void split2(float a, float b, uint32_t& hi, uint32_t& lo) {
    __nv_bfloat162 h = __floats2bfloat162_rn(a, b);
    float ha = __low2float(h), hb = __high2float(h);
    __nv_bfloat162 l = __floats2bfloat162_rn(a - ha, b - hb);
    hi = *reinterpret_cast<uint32_t*>(&h);
    lo = *reinterpret_cast<uint32_t*>(&l);
}
__device__ __forceinline__ void split4(float4 v, uint2& hi, uint2& lo) {
    split2(v.x, v.y, hi.x, lo.x);
    split2(v.z, v.w, hi.y, lo.y);
}
__device__ __forceinline__ void mma_bf16(float* c, const uint32_t* a, const uint32_t* b) {
    asm volatile(
        "mma.sync.aligned.m16n8k16.row.col.f32.bf16.bf16.f32 "
        "{%0,%1,%2,%3}, {%4,%5,%6,%7}, {%8,%9}, {%0,%1,%2,%3};"
        : "+f"(c[0]), "+f"(c[1]), "+f"(c[2]), "+f"(c[3])
        : "r"(a[0]), "r"(a[1]), "r"(a[2]), "r"(a[3]), "r"(b[0]), "r"(b[1]));
}
__device__ __forceinline__ void ldm_x4(uint32_t* r, uint32_t a) {
    asm volatile("ldmatrix.sync.aligned.m8n8.x4.shared.b16 {%0,%1,%2,%3}, [%4];"
        : "=r"(r[0]), "=r"(r[1]), "=r"(r[2]), "=r"(r[3]) : "r"(a));
}
__device__ __forceinline__ void ldm_x2(uint32_t* r, uint32_t a) {
    asm volatile("ldmatrix.sync.aligned.m8n8.x2.shared.b16 {%0,%1}, [%2];"
        : "=r"(r[0]), "=r"(r[1]) : "r"(a));
}

// ---------------------------------------------------------------------------
// HMMA bf16x2 (3-product) GEMM, ldmatrix fragments + double-buffered smem.
// Block: 128 x BN (BN=32*NTN), 8 warps = 2(m) x 4(n); warp tile 64 x 8*NTN.
// K chunks of 32. A [m][k] smem; B [n][k] smem (transposed); KP=40 pad.
// DUAL: A = concat(A0,A1) (stride 256 each, KTOT=512); output cols
// [0,128)->C0 (stride 128, bias0), [128,192)->C1 (stride 64, bias1).
// ---------------------------------------------------------------------------
template<int NTN, int DUAL, int KTOT>
__global__ void __launch_bounds__(256, 1)
hmma_gemm(const float* __restrict__ A0, const float* __restrict__ A1,
          const float* __restrict__ B0, const float* __restrict__ B1,
          const float* __restrict__ bias0, const float* __restrict__ bias1,
          const float* __restrict__ addend,
          float* __restrict__ C0, float* __restrict__ C1, int M)
{
    constexpr int BN  = 32 * NTN;
    constexpr int KP  = 40;                 // row pad (elements); 80 B = 5*16B
    constexpr int NCH = KTOT / 32;
    constexpr uint32_t AH_OFF = 0;
    constexpr uint32_t AL_OFF = 128 * KP * 2;           // 10240
    constexpr uint32_t BH_OFF = 256 * KP * 2;           // 20480
    constexpr uint32_t BL_OFF = BH_OFF + BN * KP * 2;
    constexpr uint32_t SBUF   = BH_OFF + 2u * BN * KP * 2;

    extern __shared__ char smc[];
    const uint32_t sb = smem_u32(smc);

    const int tid = threadIdx.x;
    const int wid = tid >> 5, lane = tid & 31;
    const int g = lane >> 2, t = lane & 3;
    const int warp_m = wid >> 2, warp_n = wid & 3;
    const int brow = blockIdx.y * 128;
    const int bcol = blockIdx.x * BN;

    float acc[4][NTN][4];
    #pragma unroll
    for (int i = 0; i < 4; i++)
        #pragma unroll
        for (int j = 0; j < NTN; j++)
            #pragma unroll
            for (int k = 0; k < 4; k++) acc[i][j][k] = 0.f;

    uint2 sAh[4], sAl[4], sBh[4], sBl[4];
    const int bkq = tid & 7, bnq = tid >> 3;
    const bool bact = (tid < 2 * BN);

    // per-lane ldmatrix base addresses (buffer 0)
    const uint32_t aBase = sb + AH_OFF
        + (uint32_t)(warp_m * 64 + (lane & 15)) * (KP * 2)
        + (uint32_t)((lane >> 4) << 4);            // k-half: +8 elems = +16 B
    const uint32_t bBase = sb + BH_OFF
        + (uint32_t)(warp_n * 8 * NTN + (lane & 7)) * (KP * 2)
        + (uint32_t)(((lane >> 3) & 1) << 4);

    auto gload = [&](int ch) {
        const int k0 = ch * 32;
        #pragma unroll
        for (int j = 0; j < 4; j++) {
            int idx = tid + j * 256;
            int m = idx >> 3, kq = idx & 7;
            int row = brow + m;
            float4 v = make_float4(0.f, 0.f, 0.f, 0.f);
            if (row < M) {
                int kg = k0 + kq * 4;
                const float* src;
                if (DUAL)
                    src = (kg < 256) ? (A0 + (size_t)row * 256 + kg)
                                     : (A1 + (size_t)row * 256 + (kg - 256));
                else
                    src = A0 + (size_t)row * KTOT + kg;
                v = *reinterpret_cast<const float4*>(src);
            }
            split4(v, sAh[j], sAl[j]);
        }
        if (bact) {
            float4 r[4];
            #pragma unroll
            for (int i = 0; i < 4; i++) {
                int krow = k0 + bkq * 4 + i;
                int n = bcol + bnq * 4;
                const float* src;
                if (DUAL)
                    src = (n < 128) ? (B0 + (size_t)krow * 128 + n)
                                    : (B1 + (size_t)krow * 64 + (n - 128));
                else
                    src = B0 + (size_t)krow * 256 + n;
                r[i] = *reinterpret_cast<const float4*>(src);
            }
            #pragma unroll
            for (int j = 0; j < 4; j++) {
                float4 kv = make_float4((&r[0].x)[j], (&r[1].x)[j],
                                        (&r[2].x)[j], (&r[3].x)[j]);
                split4(kv, sBh[j], sBl[j]);
            }
        }
    };
    auto sstore = [&](int buf) {
        char* base = smc + (uint32_t)buf * SBUF;
        #pragma unroll
        for (int j = 0; j < 4; j++) {
            int idx = tid + j * 256;
            int m = idx >> 3, kq = idx & 7;
            *reinterpret_cast<uint2*>(base + AH_OFF + m * (KP*2) + kq * 8) = sAh[j];
            *reinterpret_cast<uint2*>(base + AL_OFF + m * (KP*2) + kq * 8) = sAl[j];
        }
        if (bact) {
            #pragma unroll
            for (int j = 0; j < 4; j++) {
                int n = bnq * 4 + j;
                *reinterpret_cast<uint2*>(base + BH_OFF + n * (KP*2) + bkq * 8) = sBh[j];
                *reinterpret_cast<uint2*>(base + BL_OFF + n * (KP*2) + bkq * 8) = sBl[j];
            }
        }
    };
    auto compute = [&](int buf) {
        const uint32_t bo = (uint32_t)buf * SBUF;
        #pragma unroll
        for (int ks = 0; ks < 2; ks++) {
            uint32_t Ahf[4][4], Alf[4][4], Bhf[NTN][2], Blf[NTN][2];
            #pragma unroll
            for (int mt = 0; mt < 4; mt++) {
                uint32_t a = aBase + bo + (uint32_t)(mt * 16 * KP * 2) + (uint32_t)(ks * 32);
                ldm_x4(Ahf[mt], a);
                ldm_x4(Alf[mt], a + AL_OFF);
            }
            #pragma unroll
            for (int nt = 0; nt < NTN; nt++) {
                uint32_t b = bBase + bo + (uint32_t)(nt * 8 * KP * 2) + (uint32_t)(ks * 32);
                ldm_x2(Bhf[nt], b);
                ldm_x2(Blf[nt], b + (BL_OFF - BH_OFF));
            }
            #pragma unroll
            for (int mt = 0; mt < 4; mt++)
                #pragma unroll
                for (int nt = 0; nt < NTN; nt++)
                    mma_bf16(acc[mt][nt], Ahf[mt], Bhf[nt]);
            #pragma unroll
            for (int mt = 0; mt < 4; mt++)
                #pragma unroll
                for (int nt = 0; nt < NTN; nt++)
                    mma_bf16(acc[mt][nt], Ahf[mt], Blf[nt]);
            #pragma unroll
            for (int mt = 0; mt < 4; mt++)
                #pragma unroll
                for (int nt = 0; nt < NTN; nt++)
                    mma_bf16(acc[mt][nt], Alf[mt], Bhf[nt]);
        }
    };

    gload(0);
    sstore(0);
    __syncthreads();
    int buf = 0;
    for (int ch = 1; ch < NCH; ch++) {
        gload(ch);
        compute(buf);
        sstore(buf ^ 1);
        __syncthreads();
        buf ^= 1;
    }
    compute(buf);

    // ---- epilogue ----
    #pragma unroll
    for (int mt = 0; mt < 4; mt++) {
        int r0 = brow + warp_m * 64 + mt * 16 + g;
        #pragma unroll
        for (int nt = 0; nt < NTN; nt++) {
            int c = bcol + warp_n * 8 * NTN + nt * 8 + 2 * t;
            float2 v0 = make_float2(acc[mt][nt][0], acc[mt][nt][1]);
            float2 v1 = make_float2(acc[mt][nt][2], acc[mt][nt][3]);
            if (DUAL) {
                if (c < 128) {
                    float2 b = *reinterpret_cast<const float2*>(bias0 + c);
                    v0.x += b.x; v0.y += b.y; v1.x += b.x; v1.y += b.y;
                    if (r0 < M)
                        *reinterpret_cast<float2*>(C0 + (size_t)r0 * 128 + c) = v0;
                    if (r0 + 8 < M)
                        *reinterpret_cast<float2*>(C0 + (size_t)(r0 + 8) * 128 + c) = v1;
                } else {
                    int cc = c - 128;
                    float2 b = *reinterpret_cast<const float2*>(bias1 + cc);
                    v0.x += b.x; v0.y += b.y; v1.x += b.x; v1.y += b.y;
                    if (r0 < M)
                        *reinterpret_cast<float2*>(C1 + (size_t)r0 * 64 + cc) = v0;
                    if (r0 + 8 < M)
                        *reinterpret_cast<float2*>(C1 + (size_t)(r0 + 8) * 64 + cc) = v1;
                }
            } else {
                float2 b = *reinterpret_cast<const float2*>(bias0 + c);
                v0.x += b.x; v0.y += b.y; v1.x += b.x; v1.y += b.y;
                if (r0 < M) {
                    if (addend) {
                        float2 a = *reinterpret_cast<const float2*>(
                            addend + (size_t)r0 * 256 + c);
                        v0.x += a.x; v0.y += a.y;
                    }
                    *reinterpret_cast<float2*>(C0 + (size_t)r0 * 256 + c) = v0;
                }
                if (r0 + 8 < M) {
                    if (addend) {
                        float2 a = *reinterpret_cast<const float2*>(
                            addend + (size_t)(r0 + 8) * 256 + c);
                        v1.x += a.x; v1.y += a.y;
                    }
                    *reinterpret_cast<float2*>(C0 + (size_t)(r0 + 8) * 256 + c) = v1;
                }
            }
        }
    }
}

// ---------------------------------------------------------------------------
// Deformable sampling (unchanged)
// ---------------------------------------------------------------------------
__global__ void __launch_bounds__(256)
deform_sample_k(const float* __restrict__ vproj,
                const float* __restrict__ offr,
                const float* __restrict__ awr,
                const float* __restrict__ refp,
                float* __restrict__ samp)
{
    int wg   = (blockIdx.x * 256 + threadIdx.x) >> 5;
    int lane = threadIdx.x & 31;
    int q = wg >> 1;
    if (q >= NQ) return;
    int g = lane >> 3;
    int s = lane & 7;
    int h = ((wg & 1) << 2) | g;

    float rx = fmaf(refp[2*q+0], (float)WW, -0.5f);
    float ry = fmaf(refp[2*q+1], (float)HH, -0.5f);
    const float* offh = offr + (size_t)q*128 + h*16;
    const float* awh  = awr  + (size_t)q*64  + h*8;

    float4 acc = make_float4(0.f,0.f,0.f,0.f);

    #pragma unroll
    for (int nbq = 0; nbq < 2; nbq++) {
        float a0 = awh[nbq*4+0], a1 = awh[nbq*4+1];
        float a2 = awh[nbq*4+2], a3 = awh[nbq*4+3];
        float mx = fmaxf(fmaxf(a0,a1), fmaxf(a2,a3));
        float e0 = __expf(a0-mx), e1 = __expf(a1-mx);
        float e2 = __expf(a2-mx), e3 = __expf(a3-mx);
        float inv = 1.f / (e0+e1+e2+e3);
        float aws[4] = {e0*inv, e1*inv, e2*inv, e3*inv};

        const float4* vb = reinterpret_cast<const float4*>(vproj)
                         + (size_t)nbq*NQ*64 + h*8 + s;

        #pragma unroll
        for (int p = 0; p < 4; p++) {
            float x = rx + offh[nbq*8 + p*2 + 0];
            float y = ry + offh[nbq*8 + p*2 + 1];
            float xf = floorf(x), yf = floorf(y);
            float fx = x - xf, fy = y - yf;
            int x0 = (int)xf, y0 = (int)yf;
            int x1 = x0 + 1,  y1 = y0 + 1;

            float vx0 = ((unsigned)x0 < WW) ? 1.f : 0.f;
            float vx1 = ((unsigned)x1 < WW) ? 1.f : 0.f;
            float vy0 = ((unsigned)y0 < HH) ? 1.f : 0.f;
            float vy1 = ((unsigned)y1 < HH) ? 1.f : 0.f;
            int cx0 = min(max(x0,0), WW-1), cx1 = min(max(x1,0), WW-1);
            int cy0 = min(max(y0,0), HH-1), cy1 = min(max(y1,0), HH-1);

            float w   = aws[p];
            float gx1 = fx, gx0 = 1.f - fx;
            float gy1 = fy, gy0 = 1.f - fy;
            float w00 = w*gx0*gy0*vx0*vy0;
            float w01 = w*gx1*gy0*vx1*vy0;
            float w10 = w*gx0*gy1*vx0*vy1;
            float w11 = w*gx1*gy1*vx1*vy1;

            float4 v00 = vb[(size_t)(cy0*WW + cx0) * 64];
            float4 v01 = vb[(size_t)(cy0*WW + cx1) * 64];
            float4 v10 = vb[(size_t)(cy1*WW + cx0) * 64];
            float4 v11 = vb[(size_t)(cy1*WW + cx1) * 64];

            acc.x = fmaf(w00, v00.x, acc.x); acc.y = fmaf(w00, v00.y, acc.y);
            acc.z = fmaf(w00, v00.z, acc.z); acc.w = fmaf(w00, v00.w, acc.w);
            acc.x = fmaf(w01, v01.x, acc.x); acc.y = fmaf(w01, v01.y, acc.y);
            acc.z = fmaf(w01, v01.z, acc.z); acc.w = fmaf(w01, v01.w, acc.w);
            acc.x = fmaf(w10, v10.x, acc.x); acc.y = fmaf(w10, v10.y, acc.y);
            acc.z = fmaf(w10, v10.z, acc.z); acc.w = fmaf(w10, v10.w, acc.w);
            acc.x = fmaf(w11, v11.x, acc.x); acc.y = fmaf(w11, v11.y, acc.y);
            acc.z = fmaf(w11, v11.z, acc.z); acc.w = fmaf(w11, v11.w, acc.w);
        }
    }
    acc.x *= 0.5f; acc.y *= 0.5f; acc.z *= 0.5f; acc.w *= 0.5f;
    *reinterpret_cast<float4*>(samp + (size_t)q*DD + h*32 + s*4) = acc;
}

// ---------------------------------------------------------------------------
extern "C" void kernel_launch(void* const* d_in, const int* in_sizes, int n_in,
                              void* d_out, int out_size)
{
    const float* query = (const float*)d_in[0];
    const float* value = (const float*)d_in[1];
    const float* refp  = (const float*)d_in[2];
    const float* W_v  = (const float*)d_in[4];
    const float* b_v  = (const float*)d_in[5];
    const float* W_so = (const float*)d_in[6];
    const float* b_so = (const float*)d_in[7];
    const float* W_aw = (const float*)d_in[8];
    const float* b_aw = (const float*)d_in[9];
    const float* W_o  = (const float*)d_in[10];
    const float* b_o  = (const float*)d_in[11];
    float* out = (float*)d_out;

    float *vproj, *offp, *awp, *sampp;
    cudaGetSymbolAddress((void**)&vproj, g_vproj);
    cudaGetSymbolAddress((void**)&offp,  g_off);
    cudaGetSymbolAddress((void**)&awp,   g_aw);
    cudaGetSymbolAddress((void**)&sampp, g_samp);

    constexpr int KP = 40;
    constexpr int SM128 = 2 * ((256 + 2 * 128) * KP * 2);  // 81920 B
    constexpr int SM96  = 2 * ((256 + 2 * 96)  * KP * 2);  // 71680 B
    cudaFuncSetAttribute(hmma_gemm<4,0,256>,
        cudaFuncAttributeMaxDynamicSharedMemorySize, SM128);
    cudaFuncSetAttribute(hmma_gemm<3,1,512>,
        cudaFuncAttributeMaxDynamicSharedMemorySize, SM96);

    // GEMM1: vproj = value @ W_v + b_v          (80000 x 256 x 256)
    hmma_gemm<4,0,256><<<dim3(2, 625), 256, SM128>>>(
        value, nullptr, W_v, nullptr, b_v, nullptr, nullptr,
        vproj, nullptr, 2*NQ);

    // GEMM2+3: [value0|query] @ {W_so,W_aw}     (40000 x {128,64} x 512)
    hmma_gemm<3,1,512><<<dim3(2, 313), 256, SM96>>>(
        value, query, W_so, W_aw, b_so, b_aw, nullptr,
        offp, awp, NQ);

    // Sampling
    deform_sample_k<<<(NQ*2 + 7)/8, 256>>>(vproj, offp, awp, refp, sampp);

    // GEMM5: out = samp @ W_o + b_o + query     (40000 x 256 x 256)
    hmma_gemm<4,0,256><<<dim3(2, 313), 256, SM128>>>(
        sampp, nullptr, W_o, nullptr, b_o, nullptr, query,
        out, nullptr, NQ);
}

// round 8
// speedup vs baseline: 2.0282x; 1.0554x over previous
#include <cuda_runtime.h>
#include <cuda_bf16.h>
#include <cstdint>
#include <cstddef>

#define HH   200
#define WW   200
#define NQ   40000
#define DD   256

__device__ float g_vproj[(size_t)2 * NQ * DD];
__device__ float g_off  [(size_t)NQ * 128];
__device__ float g_aw   [(size_t)NQ * 64];
__device__ float g_samp [(size_t)NQ * DD];

// ---------------------------------------------------------------------------
// helpers
// ---------------------------------------------------------------------------
__device__ __forceinline__ uint32_t smem_u32(const void* p) {
    uint32_t a;
    asm("{ .reg .u64 t; cvta.to.shared.u64 t, %1; cvt.u32.u64 %0, t; }"
        : "=r"(a) : "l"(p));
    return a;
}
__device__ __forceinline__ void split2(float a, float b, uint32_t& hi, uint32_t& lo) {
    __nv_bfloat162 h = __floats2bfloat162_rn(a, b);
    float ha = __low2float(h), hb = __high2float(h);
    __nv_bfloat162 l = __floats2bfloat162_rn(a - ha, b - hb);
    hi = *reinterpret_cast<uint32_t*>(&h);
    lo = *reinterpret_cast<uint32_t*>(&l);
}
__device__ __forceinline__ void split4(float4 v, uint2& hi, uint2& lo) {
    split2(v.x, v.y, hi.x, lo.x);
    split2(v.z, v.w, hi.y, lo.y);
}
__device__ __forceinline__ void mma_bf16(float* c, const uint32_t* a, const uint32_t* b) {
    asm volatile(
        "mma.sync.aligned.m16n8k16.row.col.f32.bf16.bf16.f32 "
        "{%0,%1,%2,%3}, {%4,%5,%6,%7}, {%8,%9}, {%0,%1,%2,%3};"
        : "+f"(c[0]), "+f"(c[1]), "+f"(c[2]), "+f"(c[3])
        : "r"(a[0]), "r"(a[1]), "r"(a[2]), "r"(a[3]), "r"(b[0]), "r"(b[1]));
}
__device__ __forceinline__ void ldm_x4(uint32_t* r, uint32_t a) {
    asm volatile("ldmatrix.sync.aligned.m8n8.x4.shared.b16 {%0,%1,%2,%3}, [%4];"
        : "=r"(r[0]), "=r"(r[1]), "=r"(r[2]), "=r"(r[3]) : "r"(a));
}
__device__ __forceinline__ void ldm_x2(uint32_t* r, uint32_t a) {
    asm volatile("ldmatrix.sync.aligned.m8n8.x2.shared.b16 {%0,%1}, [%2];"
        : "=r"(r[0]), "=r"(r[1]) : "r"(a));
}

// ---------------------------------------------------------------------------
// HMMA bf16x2 (3-product) GEMM, ldmatrix fragments + double-buffered smem.
// KEY CHANGE vs R7: gload stages RAW float4s (no dependent math); the bf16
// split happens in csstore AFTER compute(), so MMA work covers LDG latency.
// Block: 128 x BN (BN=32*NTN), 8 warps = 2(m) x 4(n); warp tile 64 x 8*NTN.
// K chunks of 32. A [m][k] smem; B [n][k] smem (transposed); KP=40 pad.
// DUAL: A = concat(A0,A1) (stride 256 each, KTOT=512); output cols
// [0,128)->C0 (stride 128, bias0), [128,192)->C1 (stride 64, bias1).
// ---------------------------------------------------------------------------
template<int NTN, int DUAL, int KTOT>
__global__ void __launch_bounds__(256, 1)
hmma_gemm(const float* __restrict__ A0, const float* __restrict__ A1,
          const float* __restrict__ B0, const float* __restrict__ B1,
          const float* __restrict__ bias0, const float* __restrict__ bias1,
          const float* __restrict__ addend,
          float* __restrict__ C0, float* __restrict__ C1, int M)
{
    constexpr int BN  = 32 * NTN;
    constexpr int KP  = 40;                 // row pad (elements); 80 B = 5*16B
    constexpr int NCH = KTOT / 32;
    constexpr uint32_t AH_OFF = 0;
    constexpr uint32_t AL_OFF = 128 * KP * 2;           // 10240
    constexpr uint32_t BH_OFF = 256 * KP * 2;           // 20480
    constexpr uint32_t BL_OFF = BH_OFF + BN * KP * 2;
    constexpr uint32_t SBUF   = BH_OFF + 2u * BN * KP * 2;

    extern __shared__ char smc[];
    const uint32_t sb = smem_u32(smc);

    const int tid = threadIdx.x;
    const int wid = tid >> 5, lane = tid & 31;
    const int g = lane >> 2, t = lane & 3;
    const int warp_m = wid >> 2, warp_n = wid & 3;
    const int brow = blockIdx.y * 128;
    const int bcol = blockIdx.x * BN;

    float acc[4][NTN][4];
    #pragma unroll
    for (int i = 0; i < 4; i++)
        #pragma unroll
        for (int j = 0; j < NTN; j++)
            #pragma unroll
            for (int k = 0; k < 4; k++) acc[i][j][k] = 0.f;

    // RAW staging registers — no math depends on these until csstore.
    float4 rA[4], rB[4];
    const int bkq = tid & 7, bnq = tid >> 3;
    const bool bact = (tid < 2 * BN);

    // per-lane ldmatrix base addresses (buffer 0)
    const uint32_t aBase = sb + AH_OFF
        + (uint32_t)(warp_m * 64 + (lane & 15)) * (KP * 2)
        + (uint32_t)((lane >> 4) << 4);            // k-half: +8 elems = +16 B
    const uint32_t bBase = sb + BH_OFF
        + (uint32_t)(warp_n * 8 * NTN + (lane & 7)) * (KP * 2)
        + (uint32_t)(((lane >> 3) & 1) << 4);

    auto gload = [&](int ch) {
        const int k0 = ch * 32;
        #pragma unroll
        for (int j = 0; j < 4; j++) {
            int idx = tid + j * 256;
            int m = idx >> 3, kq = idx & 7;
            int row = brow + m;
            float4 v = make_float4(0.f, 0.f, 0.f, 0.f);
            if (row < M) {
                int kg = k0 + kq * 4;
                const float* src;
                if (DUAL)
                    src = (kg < 256) ? (A0 + (size_t)row * 256 + kg)
                                     : (A1 + (size_t)row * 256 + (kg - 256));
                else
                    src = A0 + (size_t)row * KTOT + kg;
                v = *reinterpret_cast<const float4*>(src);
            }
            rA[j] = v;
        }
        if (bact) {
            #pragma unroll
            for (int i = 0; i < 4; i++) {
                int krow = k0 + bkq * 4 + i;
                int n = bcol + bnq * 4;
                const float* src;
                if (DUAL)
                    src = (n < 128) ? (B0 + (size_t)krow * 128 + n)
                                    : (B1 + (size_t)krow * 64 + (n - 128));
                else
                    src = B0 + (size_t)krow * 256 + n;
                rB[i] = *reinterpret_cast<const float4*>(src);
            }
        }
    };
    auto csstore = [&](int buf) {   // convert + store (after compute)
        char* base = smc + (uint32_t)buf * SBUF;
        #pragma unroll
        for (int j = 0; j < 4; j++) {
            int idx = tid + j * 256;
            int m = idx >> 3, kq = idx & 7;
            uint2 hi, lo;
            split4(rA[j], hi, lo);
            *reinterpret_cast<uint2*>(base + AH_OFF + m * (KP*2) + kq * 8) = hi;
            *reinterpret_cast<uint2*>(base + AL_OFF + m * (KP*2) + kq * 8) = lo;
        }
        if (bact) {
            #pragma unroll
            for (int j = 0; j < 4; j++) {
                int n = bnq * 4 + j;
                float4 kv = make_float4((&rB[0].x)[j], (&rB[1].x)[j],
                                        (&rB[2].x)[j], (&rB[3].x)[j]);
                uint2 hi, lo;
                split4(kv, hi, lo);
                *reinterpret_cast<uint2*>(base + BH_OFF + n * (KP*2) + bkq * 8) = hi;
                *reinterpret_cast<uint2*>(base + BL_OFF + n * (KP*2) + bkq * 8) = lo;
            }
        }
    };
    auto compute = [&](int buf) {
        const uint32_t bo = (uint32_t)buf * SBUF;
        #pragma unroll
        for (int ks = 0; ks < 2; ks++) {
            uint32_t Ahf[4][4], Alf[4][4], Bhf[NTN][2], Blf[NTN][2];
            #pragma unroll
            for (int mt = 0; mt < 4; mt++) {
                uint32_t a = aBase + bo + (uint32_t)(mt * 16 * KP * 2) + (uint32_t)(ks * 32);
                ldm_x4(Ahf[mt], a);
                ldm_x4(Alf[mt], a + AL_OFF);
            }
            #pragma unroll
            for (int nt = 0; nt < NTN; nt++) {
                uint32_t b = bBase + bo + (uint32_t)(nt * 8 * KP * 2) + (uint32_t)(ks * 32);
                ldm_x2(Bhf[nt], b);
                ldm_x2(Blf[nt], b + (BL_OFF - BH_OFF));
            }
            #pragma unroll
            for (int mt = 0; mt < 4; mt++)
                #pragma unroll
                for (int nt = 0; nt < NTN; nt++)
                    mma_bf16(acc[mt][nt], Ahf[mt], Bhf[nt]);
            #pragma unroll
            for (int mt = 0; mt < 4; mt++)
                #pragma unroll
                for (int nt = 0; nt < NTN; nt++)
                    mma_bf16(acc[mt][nt], Ahf[mt], Blf[nt]);
            #pragma unroll
            for (int mt = 0; mt < 4; mt++)
                #pragma unroll
                for (int nt = 0; nt < NTN; nt++)
                    mma_bf16(acc[mt][nt], Alf[mt], Bhf[nt]);
        }
    };

    gload(0);
    csstore(0);
    __syncthreads();
    int buf = 0;
    for (int ch = 1; ch < NCH; ch++) {
        gload(ch);            // raw LDGs in flight…
        compute(buf);         // …covered by MMA work on the previous chunk
        csstore(buf ^ 1);     // convert + store once loads have landed
        __syncthreads();
        buf ^= 1;
    }
    compute(buf);

    // ---- epilogue ----
    #pragma unroll
    for (int mt = 0; mt < 4; mt++) {
        int r0 = brow + warp_m * 64 + mt * 16 + g;
        #pragma unroll
        for (int nt = 0; nt < NTN; nt++) {
            int c = bcol + warp_n * 8 * NTN + nt * 8 + 2 * t;
            float2 v0 = make_float2(acc[mt][nt][0], acc[mt][nt][1]);
            float2 v1 = make_float2(acc[mt][nt][2], acc[mt][nt][3]);
            if (DUAL) {
                if (c < 128) {
                    float2 b = *reinterpret_cast<const float2*>(bias0 + c);
                    v0.x += b.x; v0.y += b.y; v1.x += b.x; v1.y += b.y;
                    if (r0 < M)
                        *reinterpret_cast<float2*>(C0 + (size_t)r0 * 128 + c) = v0;
                    if (r0 + 8 < M)
                        *reinterpret_cast<float2*>(C0 + (size_t)(r0 + 8) * 128 + c) = v1;
                } else {
                    int cc = c - 128;
                    float2 b = *reinterpret_cast<const float2*>(bias1 + cc);
                    v0.x += b.x; v0.y += b.y; v1.x += b.x; v1.y += b.y;
                    if (r0 < M)
                        *reinterpret_cast<float2*>(C1 + (size_t)r0 * 64 + cc) = v0;
                    if (r0 + 8 < M)
                        *reinterpret_cast<float2*>(C1 + (size_t)(r0 + 8) * 64 + cc) = v1;
                }
            } else {
                float2 b = *reinterpret_cast<const float2*>(bias0 + c);
                v0.x += b.x; v0.y += b.y; v1.x += b.x; v1.y += b.y;
                if (r0 < M) {
                    if (addend) {
                        float2 a = *reinterpret_cast<const float2*>(
                            addend + (size_t)r0 * 256 + c);
                        v0.x += a.x; v0.y += a.y;
                    }
                    *reinterpret_cast<float2*>(C0 + (size_t)r0 * 256 + c) = v0;
                }
                if (r0 + 8 < M) {
                    if (addend) {
                        float2 a = *reinterpret_cast<const float2*>(
                            addend + (size_t)(r0 + 8) * 256 + c);
                        v1.x += a.x; v1.y += a.y;
                    }
                    *reinterpret_cast<float2*>(C0 + (size_t)(r0 + 8) * 256 + c) = v1;
                }
            }
        }
    }
}

// ---------------------------------------------------------------------------
// Deformable sampling (unchanged)
// ---------------------------------------------------------------------------
__global__ void __launch_bounds__(256)
deform_sample_k(const float* __restrict__ vproj,
                const float* __restrict__ offr,
                const float* __restrict__ awr,
                const float* __restrict__ refp,
                float* __restrict__ samp)
{
    int wg   = (blockIdx.x * 256 + threadIdx.x) >> 5;
    int lane = threadIdx.x & 31;
    int q = wg >> 1;
    if (q >= NQ) return;
    int g = lane >> 3;
    int s = lane & 7;
    int h = ((wg & 1) << 2) | g;

    float rx = fmaf(refp[2*q+0], (float)WW, -0.5f);
    float ry = fmaf(refp[2*q+1], (float)HH, -0.5f);
    const float* offh = offr + (size_t)q*128 + h*16;
    const float* awh  = awr  + (size_t)q*64  + h*8;

    float4 acc = make_float4(0.f,0.f,0.f,0.f);

    #pragma unroll
    for (int nbq = 0; nbq < 2; nbq++) {
        float a0 = awh[nbq*4+0], a1 = awh[nbq*4+1];
        float a2 = awh[nbq*4+2], a3 = awh[nbq*4+3];
        float mx = fmaxf(fmaxf(a0,a1), fmaxf(a2,a3));
        float e0 = __expf(a0-mx), e1 = __expf(a1-mx);
        float e2 = __expf(a2-mx), e3 = __expf(a3-mx);
        float inv = 1.f / (e0+e1+e2+e3);
        float aws[4] = {e0*inv, e1*inv, e2*inv, e3*inv};

        const float4* vb = reinterpret_cast<const float4*>(vproj)
                         + (size_t)nbq*NQ*64 + h*8 + s;

        #pragma unroll
        for (int p = 0; p < 4; p++) {
            float x = rx + offh[nbq*8 + p*2 + 0];
            float y = ry + offh[nbq*8 + p*2 + 1];
            float xf = floorf(x), yf = floorf(y);
            float fx = x - xf, fy = y - yf;
            int x0 = (int)xf, y0 = (int)yf;
            int x1 = x0 + 1,  y1 = y0 + 1;

            float vx0 = ((unsigned)x0 < WW) ? 1.f : 0.f;
            float vx1 = ((unsigned)x1 < WW) ? 1.f : 0.f;
            float vy0 = ((unsigned)y0 < HH) ? 1.f : 0.f;
            float vy1 = ((unsigned)y1 < HH) ? 1.f : 0.f;
            int cx0 = min(max(x0,0), WW-1), cx1 = min(max(x1,0), WW-1);
            int cy0 = min(max(y0,0), HH-1), cy1 = min(max(y1,0), HH-1);

            float w   = aws[p];
            float gx1 = fx, gx0 = 1.f - fx;
            float gy1 = fy, gy0 = 1.f - fy;
            float w00 = w*gx0*gy0*vx0*vy0;
            float w01 = w*gx1*gy0*vx1*vy0;
            float w10 = w*gx0*gy1*vx0*vy1;
            float w11 = w*gx1*gy1*vx1*vy1;

            float4 v00 = vb[(size_t)(cy0*WW + cx0) * 64];
            float4 v01 = vb[(size_t)(cy0*WW + cx1) * 64];
            float4 v10 = vb[(size_t)(cy1*WW + cx0) * 64];
            float4 v11 = vb[(size_t)(cy1*WW + cx1) * 64];

            acc.x = fmaf(w00, v00.x, acc.x); acc.y = fmaf(w00, v00.y, acc.y);
            acc.z = fmaf(w00, v00.z, acc.z); acc.w = fmaf(w00, v00.w, acc.w);
            acc.x = fmaf(w01, v01.x, acc.x); acc.y = fmaf(w01, v01.y, acc.y);
            acc.z = fmaf(w01, v01.z, acc.z); acc.w = fmaf(w01, v01.w, acc.w);
            acc.x = fmaf(w10, v10.x, acc.x); acc.y = fmaf(w10, v10.y, acc.y);
            acc.z = fmaf(w10, v10.z, acc.z); acc.w = fmaf(w10, v10.w, acc.w);
            acc.x = fmaf(w11, v11.x, acc.x); acc.y = fmaf(w11, v11.y, acc.y);
            acc.z = fmaf(w11, v11.z, acc.z); acc.w = fmaf(w11, v11.w, acc.w);
        }
    }
    acc.x *= 0.5f; acc.y *= 0.5f; acc.z *= 0.5f; acc.w *= 0.5f;
    *reinterpret_cast<float4*>(samp + (size_t)q*DD + h*32 + s*4) = acc;
}

// ---------------------------------------------------------------------------
extern "C" void kernel_launch(void* const* d_in, const int* in_sizes, int n_in,
                              void* d_out, int out_size)
{
    const float* query = (const float*)d_in[0];
    const float* value = (const float*)d_in[1];
    const float* refp  = (const float*)d_in[2];
    const float* W_v  = (const float*)d_in[4];
    const float* b_v  = (const float*)d_in[5];
    const float* W_so = (const float*)d_in[6];
    const float* b_so = (const float*)d_in[7];
    const float* W_aw = (const float*)d_in[8];
    const float* b_aw = (const float*)d_in[9];
    const float* W_o  = (const float*)d_in[10];
    const float* b_o  = (const float*)d_in[11];
    float* out = (float*)d_out;

    float *vproj, *offp, *awp, *sampp;
    cudaGetSymbolAddress((void**)&vproj, g_vproj);
    cudaGetSymbolAddress((void**)&offp,  g_off);
    cudaGetSymbolAddress((void**)&awp,   g_aw);
    cudaGetSymbolAddress((void**)&sampp, g_samp);

    constexpr int KP = 40;
    constexpr int SM128 = 2 * ((256 + 2 * 128) * KP * 2);  // 81920 B
    constexpr int SM96  = 2 * ((256 + 2 * 96)  * KP * 2);  // 71680 B
    cudaFuncSetAttribute(hmma_gemm<4,0,256>,
        cudaFuncAttributeMaxDynamicSharedMemorySize, SM128);
    cudaFuncSetAttribute(hmma_gemm<3,1,512>,
        cudaFuncAttributeMaxDynamicSharedMemorySize, SM96);

    // GEMM1: vproj = value @ W_v + b_v          (80000 x 256 x 256)
    hmma_gemm<4,0,256><<<dim3(2, 625), 256, SM128>>>(
        value, nullptr, W_v, nullptr, b_v, nullptr, nullptr,
        vproj, nullptr, 2*NQ);

    // GEMM2+3: [value0|query] @ {W_so,W_aw}     (40000 x {128,64} x 512)
    hmma_gemm<3,1,512><<<dim3(2, 313), 256, SM96>>>(
        value, query, W_so, W_aw, b_so, b_aw, nullptr,
        offp, awp, NQ);

    // Sampling
    deform_sample_k<<<(NQ*2 + 7)/8, 256>>>(vproj, offp, awp, refp, sampp);

    // GEMM5: out = samp @ W_o + b_o + query     (40000 x 256 x 256)
    hmma_gemm<4,0,256><<<dim3(2, 313), 256, SM128>>>(
        sampp, nullptr, W_o, nullptr, b_o, nullptr, query,
        out, nullptr, NQ);
}

// round 9
// speedup vs baseline: 2.1122x; 1.0414x over previous
#include <cuda_runtime.h>
#include <cuda_bf16.h>
#include <cstdint>
#include <cstddef>

#define HH   200
#define WW   200
#define NQ   40000
#define DD   256

__device__ float g_vproj[(size_t)2 * NQ * DD];
__device__ float g_off  [(size_t)NQ * 128];
__device__ float g_aw   [(size_t)NQ * 64];
__device__ float g_samp [(size_t)NQ * DD];

// ---------------------------------------------------------------------------
// helpers
// ---------------------------------------------------------------------------
__device__ __forceinline__ uint32_t smem_u32(const void* p) {
    uint32_t a;
    asm("{ .reg .u64 t; cvta.to.shared.u64 t, %1; cvt.u32.u64 %0, t; }"
        : "=r"(a) : "l"(p));
    return a;
}
__device__ __forceinline__ void split2(float a, float b, uint32_t& hi, uint32_t& lo) {
    __nv_bfloat162 h = __floats2bfloat162_rn(a, b);
    float ha = __low2float(h), hb = __high2float(h);
    __nv_bfloat162 l = __floats2bfloat162_rn(a - ha, b - hb);
    hi = *reinterpret_cast<uint32_t*>(&h);
    lo = *reinterpret_cast<uint32_t*>(&l);
}
__device__ __forceinline__ void split4(float4 v, uint2& hi, uint2& lo) {
    split2(v.x, v.y, hi.x, lo.x);
    split2(v.z, v.w, hi.y, lo.y);
}
__device__ __forceinline__ void mma_bf16(float* c, const uint32_t* a, const uint32_t* b) {
    asm volatile(
        "mma.sync.aligned.m16n8k16.row.col.f32.bf16.bf16.f32 "
        "{%0,%1,%2,%3}, {%4,%5,%6,%7}, {%8,%9}, {%0,%1,%2,%3};"
        : "+f"(c[0]), "+f"(c[1]), "+f"(c[2]), "+f"(c[3])
        : "r"(a[0]), "r"(a[1]), "r"(a[2]), "r"(a[3]), "r"(b[0]), "r"(b[1]));
}
__device__ __forceinline__ void ldm_x4(uint32_t* r, uint32_t a) {
    asm volatile("ldmatrix.sync.aligned.m8n8.x4.shared.b16 {%0,%1,%2,%3}, [%4];"
        : "=r"(r[0]), "=r"(r[1]), "=r"(r[2]), "=r"(r[3]) : "r"(a));
}
__device__ __forceinline__ void ldm_x2(uint32_t* r, uint32_t a) {
    asm volatile("ldmatrix.sync.aligned.m8n8.x2.shared.b16 {%0,%1}, [%2];"
        : "=r"(r[0]), "=r"(r[1]) : "r"(a));
}

// ---------------------------------------------------------------------------
// HMMA bf16x2 (3-product) GEMM — 512 threads, 16 warps (4m x 4n),
// warp tile 32 x 8*NTN; double-buffered smem; ldmatrix fragments.
// Block covers 128 x BN (BN = 32*NTN). K chunks of 32; KP=40 row pad.
// DUAL: A = concat(A0,A1) (stride 256 each, KTOT=512); output cols
// [0,128)->C0 (stride 128, bias0), [128,192)->C1 (stride 64, bias1).
// ---------------------------------------------------------------------------
template<int NTN, int DUAL, int KTOT>
__global__ void __launch_bounds__(512, 1)
hmma_gemm(const float* __restrict__ A0, const float* __restrict__ A1,
          const float* __restrict__ B0, const float* __restrict__ B1,
          const float* __restrict__ bias0, const float* __restrict__ bias1,
          const float* __restrict__ addend,
          float* __restrict__ C0, float* __restrict__ C1, int M)
{
    constexpr int BN  = 32 * NTN;
    constexpr int KP  = 40;                 // row pad (elements); 80 B
    constexpr int NCH = KTOT / 32;
    constexpr uint32_t AH_OFF = 0;
    constexpr uint32_t AL_OFF = 128 * KP * 2;
    constexpr uint32_t BH_OFF = 256 * KP * 2;
    constexpr uint32_t BL_OFF = BH_OFF + BN * KP * 2;
    constexpr uint32_t SBUF   = BH_OFF + 2u * BN * KP * 2;

    extern __shared__ char smc[];
    const uint32_t sb = smem_u32(smc);

    const int tid = threadIdx.x;
    const int wid = tid >> 5, lane = tid & 31;
    const int g = lane >> 2, t = lane & 3;
    const int warp_m = wid >> 2, warp_n = wid & 3;   // 4 x 4 warp grid
    const int brow = blockIdx.y * 128;
    const int bcol = blockIdx.x * BN;

    float acc[2][NTN][4];
    #pragma unroll
    for (int i = 0; i < 2; i++)
        #pragma unroll
        for (int j = 0; j < NTN; j++)
            #pragma unroll
            for (int k = 0; k < 4; k++) acc[i][j][k] = 0.f;

    // RAW staging registers
    float4 rA[2], rB[4];
    const int bkq = tid & 7, bnq = tid >> 3;
    const bool bact = (tid < 2 * BN);

    // per-lane ldmatrix base addresses (buffer 0)
    const uint32_t aBase = sb + AH_OFF
        + (uint32_t)(warp_m * 32 + (lane & 15)) * (KP * 2)
        + (uint32_t)((lane >> 4) << 4);
    const uint32_t bBase = sb + BH_OFF
        + (uint32_t)(warp_n * 8 * NTN + (lane & 7)) * (KP * 2)
        + (uint32_t)(((lane >> 3) & 1) << 4);

    auto gload = [&](int ch) {
        const int k0 = ch * 32;
        #pragma unroll
        for (int j = 0; j < 2; j++) {
            int idx = tid + j * 512;
            int m = idx >> 3, kq = idx & 7;
            int row = brow + m;
            float4 v = make_float4(0.f, 0.f, 0.f, 0.f);
            if (row < M) {
                int kg = k0 + kq * 4;
                const float* src;
                if (DUAL)
                    src = (kg < 256) ? (A0 + (size_t)row * 256 + kg)
                                     : (A1 + (size_t)row * 256 + (kg - 256));
                else
                    src = A0 + (size_t)row * KTOT + kg;
                v = *reinterpret_cast<const float4*>(src);
            }
            rA[j] = v;
        }
        if (bact) {
            #pragma unroll
            for (int i = 0; i < 4; i++) {
                int krow = k0 + bkq * 4 + i;
                int n = bcol + bnq * 4;
                const float* src;
                if (DUAL)
                    src = (n < 128) ? (B0 + (size_t)krow * 128 + n)
                                    : (B1 + (size_t)krow * 64 + (n - 128));
                else
                    src = B0 + (size_t)krow * 256 + n;
                rB[i] = *reinterpret_cast<const float4*>(src);
            }
        }
    };
    auto csstore = [&](int buf) {   // convert + store (after compute)
        char* base = smc + (uint32_t)buf * SBUF;
        #pragma unroll
        for (int j = 0; j < 2; j++) {
            int idx = tid + j * 512;
            int m = idx >> 3, kq = idx & 7;
            uint2 hi, lo;
            split4(rA[j], hi, lo);
            *reinterpret_cast<uint2*>(base + AH_OFF + m * (KP*2) + kq * 8) = hi;
            *reinterpret_cast<uint2*>(base + AL_OFF + m * (KP*2) + kq * 8) = lo;
        }
        if (bact) {
            #pragma unroll
            for (int j = 0; j < 4; j++) {
                int n = bnq * 4 + j;
                float4 kv = make_float4((&rB[0].x)[j], (&rB[1].x)[j],
                                        (&rB[2].x)[j], (&rB[3].x)[j]);
                uint2 hi, lo;
                split4(kv, hi, lo);
                *reinterpret_cast<uint2*>(base + BH_OFF + n * (KP*2) + bkq * 8) = hi;
                *reinterpret_cast<uint2*>(base + BL_OFF + n * (KP*2) + bkq * 8) = lo;
            }
        }
    };
    auto compute = [&](int buf) {
        const uint32_t bo = (uint32_t)buf * SBUF;
        #pragma unroll
        for (int ks = 0; ks < 2; ks++) {
            uint32_t Ahf[2][4], Alf[2][4], Bhf[NTN][2], Blf[NTN][2];
            #pragma unroll
            for (int mt = 0; mt < 2; mt++) {
                uint32_t a = aBase + bo + (uint32_t)(mt * 16 * KP * 2) + (uint32_t)(ks * 32);
                ldm_x4(Ahf[mt], a);
                ldm_x4(Alf[mt], a + AL_OFF);
            }
            #pragma unroll
            for (int nt = 0; nt < NTN; nt++) {
                uint32_t b = bBase + bo + (uint32_t)(nt * 8 * KP * 2) + (uint32_t)(ks * 32);
                ldm_x2(Bhf[nt], b);
                ldm_x2(Blf[nt], b + (BL_OFF - BH_OFF));
            }
            #pragma unroll
            for (int mt = 0; mt < 2; mt++)
                #pragma unroll
                for (int nt = 0; nt < NTN; nt++)
                    mma_bf16(acc[mt][nt], Ahf[mt], Bhf[nt]);
            #pragma unroll
            for (int mt = 0; mt < 2; mt++)
                #pragma unroll
                for (int nt = 0; nt < NTN; nt++)
                    mma_bf16(acc[mt][nt], Ahf[mt], Blf[nt]);
            #pragma unroll
            for (int mt = 0; mt < 2; mt++)
                #pragma unroll
                for (int nt = 0; nt < NTN; nt++)
                    mma_bf16(acc[mt][nt], Alf[mt], Bhf[nt]);
        }
    };

    gload(0);
    csstore(0);
    __syncthreads();
    int buf = 0;
    for (int ch = 1; ch < NCH; ch++) {
        gload(ch);
        compute(buf);
        csstore(buf ^ 1);
        __syncthreads();
        buf ^= 1;
    }
    compute(buf);

    // ---- epilogue ----
    #pragma unroll
    for (int mt = 0; mt < 2; mt++) {
        int r0 = brow + warp_m * 32 + mt * 16 + g;
        #pragma unroll
        for (int nt = 0; nt < NTN; nt++) {
            int c = bcol + warp_n * 8 * NTN + nt * 8 + 2 * t;
            float2 v0 = make_float2(acc[mt][nt][0], acc[mt][nt][1]);
            float2 v1 = make_float2(acc[mt][nt][2], acc[mt][nt][3]);
            if (DUAL) {
                if (c < 128) {
                    float2 b = *reinterpret_cast<const float2*>(bias0 + c);
                    v0.x += b.x; v0.y += b.y; v1.x += b.x; v1.y += b.y;
                    if (r0 < M)
                        *reinterpret_cast<float2*>(C0 + (size_t)r0 * 128 + c) = v0;
                    if (r0 + 8 < M)
                        *reinterpret_cast<float2*>(C0 + (size_t)(r0 + 8) * 128 + c) = v1;
                } else {
                    int cc = c - 128;
                    float2 b = *reinterpret_cast<const float2*>(bias1 + cc);
                    v0.x += b.x; v0.y += b.y; v1.x += b.x; v1.y += b.y;
                    if (r0 < M)
                        *reinterpret_cast<float2*>(C1 + (size_t)r0 * 64 + cc) = v0;
                    if (r0 + 8 < M)
                        *reinterpret_cast<float2*>(C1 + (size_t)(r0 + 8) * 64 + cc) = v1;
                }
            } else {
                float2 b = *reinterpret_cast<const float2*>(bias0 + c);
                v0.x += b.x; v0.y += b.y; v1.x += b.x; v1.y += b.y;
                if (r0 < M) {
                    if (addend) {
                        float2 a = *reinterpret_cast<const float2*>(
                            addend + (size_t)r0 * 256 + c);
                        v0.x += a.x; v0.y += a.y;
                    }
                    *reinterpret_cast<float2*>(C0 + (size_t)r0 * 256 + c) = v0;
                }
                if (r0 + 8 < M) {
                    if (addend) {
                        float2 a = *reinterpret_cast<const float2*>(
                            addend + (size_t)(r0 + 8) * 256 + c);
                        v1.x += a.x; v1.y += a.y;
                    }
                    *reinterpret_cast<float2*>(C0 + (size_t)(r0 + 8) * 256 + c) = v1;
                }
            }
        }
    }
}

// ---------------------------------------------------------------------------
// Deformable sampling (unchanged)
// ---------------------------------------------------------------------------
__global__ void __launch_bounds__(256)
deform_sample_k(const float* __restrict__ vproj,
                const float* __restrict__ offr,
                const float* __restrict__ awr,
                const float* __restrict__ refp,
                float* __restrict__ samp)
{
    int wg   = (blockIdx.x * 256 + threadIdx.x) >> 5;
    int lane = threadIdx.x & 31;
    int q = wg >> 1;
    if (q >= NQ) return;
    int g = lane >> 3;
    int s = lane & 7;
    int h = ((wg & 1) << 2) | g;

    float rx = fmaf(refp[2*q+0], (float)WW, -0.5f);
    float ry = fmaf(refp[2*q+1], (float)HH, -0.5f);
    const float* offh = offr + (size_t)q*128 + h*16;
    const float* awh  = awr  + (size_t)q*64  + h*8;

    float4 acc = make_float4(0.f,0.f,0.f,0.f);

    #pragma unroll
    for (int nbq = 0; nbq < 2; nbq++) {
        float a0 = awh[nbq*4+0], a1 = awh[nbq*4+1];
        float a2 = awh[nbq*4+2], a3 = awh[nbq*4+3];
        float mx = fmaxf(fmaxf(a0,a1), fmaxf(a2,a3));
        float e0 = __expf(a0-mx), e1 = __expf(a1-mx);
        float e2 = __expf(a2-mx), e3 = __expf(a3-mx);
        float inv = 1.f / (e0+e1+e2+e3);
        float aws[4] = {e0*inv, e1*inv, e2*inv, e3*inv};

        const float4* vb = reinterpret_cast<const float4*>(vproj)
                         + (size_t)nbq*NQ*64 + h*8 + s;

        #pragma unroll
        for (int p = 0; p < 4; p++) {
            float x = rx + offh[nbq*8 + p*2 + 0];
            float y = ry + offh[nbq*8 + p*2 + 1];
            float xf = floorf(x), yf = floorf(y);
            float fx = x - xf, fy = y - yf;
            int x0 = (int)xf, y0 = (int)yf;
            int x1 = x0 + 1,  y1 = y0 + 1;

            float vx0 = ((unsigned)x0 < WW) ? 1.f : 0.f;
            float vx1 = ((unsigned)x1 < WW) ? 1.f : 0.f;
            float vy0 = ((unsigned)y0 < HH) ? 1.f : 0.f;
            float vy1 = ((unsigned)y1 < HH) ? 1.f : 0.f;
            int cx0 = min(max(x0,0), WW-1), cx1 = min(max(x1,0), WW-1);
            int cy0 = min(max(y0,0), HH-1), cy1 = min(max(y1,0), HH-1);

            float w   = aws[p];
            float gx1 = fx, gx0 = 1.f - fx;
            float gy1 = fy, gy0 = 1.f - fy;
            float w00 = w*gx0*gy0*vx0*vy0;
            float w01 = w*gx1*gy0*vx1*vy0;
            float w10 = w*gx0*gy1*vx0*vy1;
            float w11 = w*gx1*gy1*vx1*vy1;

            float4 v00 = vb[(size_t)(cy0*WW + cx0) * 64];
            float4 v01 = vb[(size_t)(cy0*WW + cx1) * 64];
            float4 v10 = vb[(size_t)(cy1*WW + cx0) * 64];
            float4 v11 = vb[(size_t)(cy1*WW + cx1) * 64];

            acc.x = fmaf(w00, v00.x, acc.x); acc.y = fmaf(w00, v00.y, acc.y);
            acc.z = fmaf(w00, v00.z, acc.z); acc.w = fmaf(w00, v00.w, acc.w);
            acc.x = fmaf(w01, v01.x, acc.x); acc.y = fmaf(w01, v01.y, acc.y);
            acc.z = fmaf(w01, v01.z, acc.z); acc.w = fmaf(w01, v01.w, acc.w);
            acc.x = fmaf(w10, v10.x, acc.x); acc.y = fmaf(w10, v10.y, acc.y);
            acc.z = fmaf(w10, v10.z, acc.z); acc.w = fmaf(w10, v10.w, acc.w);
            acc.x = fmaf(w11, v11.x, acc.x); acc.y = fmaf(w11, v11.y, acc.y);
            acc.z = fmaf(w11, v11.z, acc.z); acc.w = fmaf(w11, v11.w, acc.w);
        }
    }
    acc.x *= 0.5f; acc.y *= 0.5f; acc.z *= 0.5f; acc.w *= 0.5f;
    *reinterpret_cast<float4*>(samp + (size_t)q*DD + h*32 + s*4) = acc;
}

// ---------------------------------------------------------------------------
extern "C" void kernel_launch(void* const* d_in, const int* in_sizes, int n_in,
                              void* d_out, int out_size)
{
    const float* query = (const float*)d_in[0];
    const float* value = (const float*)d_in[1];
    const float* refp  = (const float*)d_in[2];
    const float* W_v  = (const float*)d_in[4];
    const float* b_v  = (const float*)d_in[5];
    const float* W_so = (const float*)d_in[6];
    const float* b_so = (const float*)d_in[7];
    const float* W_aw = (const float*)d_in[8];
    const float* b_aw = (const float*)d_in[9];
    const float* W_o  = (const float*)d_in[10];
    const float* b_o  = (const float*)d_in[11];
    float* out = (float*)d_out;

    float *vproj, *offp, *awp, *sampp;
    cudaGetSymbolAddress((void**)&vproj, g_vproj);
    cudaGetSymbolAddress((void**)&offp,  g_off);
    cudaGetSymbolAddress((void**)&awp,   g_aw);
    cudaGetSymbolAddress((void**)&sampp, g_samp);

    constexpr int KP = 40;
    constexpr int SM128 = 2 * ((256 + 2 * 128) * KP * 2);  // 81920 B
    constexpr int SM96  = 2 * ((256 + 2 * 96)  * KP * 2);  // 71680 B
    cudaFuncSetAttribute(hmma_gemm<4,0,256>,
        cudaFuncAttributeMaxDynamicSharedMemorySize, SM128);
    cudaFuncSetAttribute(hmma_gemm<3,1,512>,
        cudaFuncAttributeMaxDynamicSharedMemorySize, SM96);

    // GEMM1: vproj = value @ W_v + b_v          (80000 x 256 x 256)
    hmma_gemm<4,0,256><<<dim3(2, 625), 512, SM128>>>(
        value, nullptr, W_v, nullptr, b_v, nullptr, nullptr,
        vproj, nullptr, 2*NQ);

    // GEMM2+3: [value0|query] @ {W_so,W_aw}     (40000 x {128,64} x 512)
    hmma_gemm<3,1,512><<<dim3(2, 313), 512, SM96>>>(
        value, query, W_so, W_aw, b_so, b_aw, nullptr,
        offp, awp, NQ);

    // Sampling
    deform_sample_k<<<(NQ*2 + 7)/8, 256>>>(vproj, offp, awp, refp, sampp);

    // GEMM5: out = samp @ W_o + b_o + query     (40000 x 256 x 256)
    hmma_gemm<4,0,256><<<dim3(2, 313), 512, SM128>>>(
        sampp, nullptr, W_o, nullptr, b_o, nullptr, query,
        out, nullptr, NQ);
}

// round 10
// speedup vs baseline: 2.1214x; 1.0044x over previous
#include <cuda_runtime.h>
#include <cuda_bf16.h>
#include <cstdint>
#include <cstddef>

#define HH   200
#define WW   200
#define NQ   40000
#define DD   256

__device__ float g_vproj[(size_t)2 * NQ * DD];
__device__ float g_off  [(size_t)NQ * 128];
__device__ float g_aw   [(size_t)NQ * 64];
__device__ float g_samp [(size_t)NQ * DD];

// ---------------------------------------------------------------------------
// helpers
// ---------------------------------------------------------------------------
__device__ __forceinline__ uint32_t smem_u32(const void* p) {
    uint32_t a;
    asm("{ .reg .u64 t; cvta.to.shared.u64 t, %1; cvt.u32.u64 %0, t; }"
        : "=r"(a) : "l"(p));
    return a;
}
__device__ __forceinline__ void split2(float a, float b, uint32_t& hi, uint32_t& lo) {
    __nv_bfloat162 h = __floats2bfloat162_rn(a, b);
    float ha = __low2float(h), hb = __high2float(h);
    __nv_bfloat162 l = __floats2bfloat162_rn(a - ha, b - hb);
    hi = *reinterpret_cast<uint32_t*>(&h);
    lo = *reinterpret_cast<uint32_t*>(&l);
}
__device__ __forceinline__ void split4(float4 v, uint2& hi, uint2& lo) {
    split2(v.x, v.y, hi.x, lo.x);
    split2(v.z, v.w, hi.y, lo.y);
}
__device__ __forceinline__ void mma_bf16(float* c, const uint32_t* a, const uint32_t* b) {
    asm volatile(
        "mma.sync.aligned.m16n8k16.row.col.f32.bf16.bf16.f32 "
        "{%0,%1,%2,%3}, {%4,%5,%6,%7}, {%8,%9}, {%0,%1,%2,%3};"
        : "+f"(c[0]), "+f"(c[1]), "+f"(c[2]), "+f"(c[3])
        : "r"(a[0]), "r"(a[1]), "r"(a[2]), "r"(a[3]), "r"(b[0]), "r"(b[1]));
}
__device__ __forceinline__ void ldm_x4(uint32_t* r, uint32_t a) {
    asm volatile("ldmatrix.sync.aligned.m8n8.x4.shared.b16 {%0,%1,%2,%3}, [%4];"
        : "=r"(r[0]), "=r"(r[1]), "=r"(r[2]), "=r"(r[3]) : "r"(a));
}
__device__ __forceinline__ void ldm_x2(uint32_t* r, uint32_t a) {
    asm volatile("ldmatrix.sync.aligned.m8n8.x2.shared.b16 {%0,%1}, [%2];"
        : "=r"(r[0]), "=r"(r[1]) : "r"(a));
}
#define BAR_SYNC(id)   asm volatile("bar.sync %0, 512;"   :: "r"(id) : "memory")
#define BAR_ARRIVE(id) asm volatile("bar.arrive %0, 512;" :: "r"(id) : "memory")

// ---------------------------------------------------------------------------
// Warp-specialized HMMA bf16x2 (3-product) GEMM.
// 512 threads: warps 0-7 consumers (2m x 4n, warp tile 64 x 8*NTN),
// warps 8-15 producers (LDG -> split -> STS). 3-stage smem ring of converted
// bf16 tiles; named-barrier FULL/EMPTY handshakes. K chunks of 32, KP=40 pad.
// Block covers 128 x BN (BN = 32*NTN).
// DUAL: A = concat(A0,A1) (stride 256 each, KTOT=512); output cols (global)
// [0,128)->C0 (stride 128, bias0), [128,192)->C1 (stride 64, bias1).
// ---------------------------------------------------------------------------
template<int NTN, int DUAL, int KTOT>
__global__ void __launch_bounds__(512, 1)
hmma_gemm(const float* __restrict__ A0, const float* __restrict__ A1,
          const float* __restrict__ B0, const float* __restrict__ B1,
          const float* __restrict__ bias0, const float* __restrict__ bias1,
          const float* __restrict__ addend,
          float* __restrict__ C0, float* __restrict__ C1, int M)
{
    constexpr int BN  = 32 * NTN;
    constexpr int KP  = 40;                     // padded row: 80 B
    constexpr int NCH = KTOT / 32;
    constexpr int S   = 3;                      // ring stages
    constexpr uint32_t AH_OFF = 0;
    constexpr uint32_t AL_OFF = 128u * KP * 2;              // 10240
    constexpr uint32_t BH_OFF = 256u * KP * 2;              // 20480
    constexpr uint32_t BL_OFF = BH_OFF + (uint32_t)BN * KP * 2;
    constexpr uint32_t SSTAGE = BH_OFF + 2u * BN * KP * 2;

    extern __shared__ char smc[];
    const uint32_t sb = smem_u32(smc);

    const int tid = threadIdx.x;
    const int wid = tid >> 5, lane = tid & 31;
    const int brow = blockIdx.y * 128;
    const int bcol = blockIdx.x * BN;

    if (wid < 8) {
        // ================= CONSUMERS =================
        const int g = lane >> 2, t = lane & 3;
        const int warp_m = wid >> 2, warp_n = wid & 3;

        float acc[4][NTN][4];
        #pragma unroll
        for (int i = 0; i < 4; i++)
            #pragma unroll
            for (int j = 0; j < NTN; j++)
                #pragma unroll
                for (int k = 0; k < 4; k++) acc[i][j][k] = 0.f;

        // lane-resolved fragment base addresses (stage 0)
        const uint32_t aFrag = sb + AH_OFF
            + (uint32_t)(warp_m * 64 + (lane & 15)) * (KP * 2)
            + (uint32_t)((lane >> 4) << 4);
        const uint32_t bFragX4 = sb + BH_OFF
            + (uint32_t)(warp_n * 8 * NTN + (lane >> 4) * 8 + (lane & 7)) * (KP * 2)
            + (uint32_t)(((lane >> 3) & 1) << 4);
        const uint32_t bFragX2 = sb + BH_OFF
            + (uint32_t)(warp_n * 8 * NTN + (NTN - 1) * 8 + (lane & 7)) * (KP * 2)
            + (uint32_t)(((lane >> 3) & 1) << 4);

        uint32_t stBase = 0;
        for (int ch = 0; ch < NCH; ch++) {
            int s = ch % S;
            BAR_SYNC(1 + s);
            #pragma unroll
            for (int ks = 0; ks < 2; ks++) {
                uint32_t Bh[NTN][2], Bl[NTN][2];
                #pragma unroll
                for (int ntp = 0; ntp < NTN / 2; ntp++) {
                    uint32_t addr = bFragX4 + stBase
                        + (uint32_t)(ntp * 16 * KP * 2) + (uint32_t)(ks * 32);
                    uint32_t r[4];
                    ldm_x4(r, addr);
                    Bh[2*ntp][0] = r[0]; Bh[2*ntp][1] = r[1];
                    Bh[2*ntp+1][0] = r[2]; Bh[2*ntp+1][1] = r[3];
                    ldm_x4(r, addr + (BL_OFF - BH_OFF));
                    Bl[2*ntp][0] = r[0]; Bl[2*ntp][1] = r[1];
                    Bl[2*ntp+1][0] = r[2]; Bl[2*ntp+1][1] = r[3];
                }
                if (NTN & 1) {
                    uint32_t addr = bFragX2 + stBase + (uint32_t)(ks * 32);
                    ldm_x2(Bh[NTN-1], addr);
                    ldm_x2(Bl[NTN-1], addr + (BL_OFF - BH_OFF));
                }
                #pragma unroll
                for (int mt = 0; mt < 4; mt++) {
                    uint32_t Ah[4], Al[4];
                    uint32_t aa = aFrag + stBase
                        + (uint32_t)(mt * 16 * KP * 2) + (uint32_t)(ks * 32);
                    ldm_x4(Ah, aa);
                    ldm_x4(Al, aa + AL_OFF);
                    #pragma unroll
                    for (int nt = 0; nt < NTN; nt++)
                        mma_bf16(acc[mt][nt], Ah, Bh[nt]);
                    #pragma unroll
                    for (int nt = 0; nt < NTN; nt++)
                        mma_bf16(acc[mt][nt], Ah, Bl[nt]);
                    #pragma unroll
                    for (int nt = 0; nt < NTN; nt++)
                        mma_bf16(acc[mt][nt], Al, Bh[nt]);
                }
            }
            BAR_ARRIVE(1 + S + s);
            stBase += SSTAGE;
            if (stBase == S * SSTAGE) stBase = 0;
        }

        // ---- epilogue ----
        #pragma unroll
        for (int mt = 0; mt < 4; mt++) {
            int r0 = brow + warp_m * 64 + mt * 16 + g;
            #pragma unroll
            for (int nt = 0; nt < NTN; nt++) {
                int c = bcol + warp_n * 8 * NTN + nt * 8 + 2 * t;
                float2 v0 = make_float2(acc[mt][nt][0], acc[mt][nt][1]);
                float2 v1 = make_float2(acc[mt][nt][2], acc[mt][nt][3]);
                if (DUAL) {
                    if (c < 128) {
                        float2 b = *reinterpret_cast<const float2*>(bias0 + c);
                        v0.x += b.x; v0.y += b.y; v1.x += b.x; v1.y += b.y;
                        if (r0 < M)
                            *reinterpret_cast<float2*>(C0 + (size_t)r0 * 128 + c) = v0;
                        if (r0 + 8 < M)
                            *reinterpret_cast<float2*>(C0 + (size_t)(r0 + 8) * 128 + c) = v1;
                    } else {
                        int cc = c - 128;
                        float2 b = *reinterpret_cast<const float2*>(bias1 + cc);
                        v0.x += b.x; v0.y += b.y; v1.x += b.x; v1.y += b.y;
                        if (r0 < M)
                            *reinterpret_cast<float2*>(C1 + (size_t)r0 * 64 + cc) = v0;
                        if (r0 + 8 < M)
                            *reinterpret_cast<float2*>(C1 + (size_t)(r0 + 8) * 64 + cc) = v1;
                    }
                } else {
                    float2 b = *reinterpret_cast<const float2*>(bias0 + c);
                    v0.x += b.x; v0.y += b.y; v1.x += b.x; v1.y += b.y;
                    if (r0 < M) {
                        if (addend) {
                            float2 a = *reinterpret_cast<const float2*>(
                                addend + (size_t)r0 * 256 + c);
                            v0.x += a.x; v0.y += a.y;
                        }
                        *reinterpret_cast<float2*>(C0 + (size_t)r0 * 256 + c) = v0;
                    }
                    if (r0 + 8 < M) {
                        if (addend) {
                            float2 a = *reinterpret_cast<const float2*>(
                                addend + (size_t)(r0 + 8) * 256 + c);
                            v1.x += a.x; v1.y += a.y;
                        }
                        *reinterpret_cast<float2*>(C0 + (size_t)(r0 + 8) * 256 + c) = v1;
                    }
                }
            }
        }
    } else {
        // ================= PRODUCERS =================
        const int p = tid - 256;                  // 0..255
        const int am = p >> 1;                    // A rows handled: idx mapping
        const int bkq = p & 7, bnq = p >> 3;      // B task
        const bool bact = (p < 2 * BN);

        uint32_t stBase = 0;
        for (int ch = 0; ch < NCH; ch++) {
            int s = ch % S;
            const int k0 = ch * 32;
            if (ch >= S) BAR_SYNC(1 + S + s);

            // --- raw loads ---
            float4 rA[4];
            #pragma unroll
            for (int j = 0; j < 4; j++) {
                int idx = p + j * 256;            // 0..1023
                int m = idx >> 3, kq = idx & 7;
                int row = brow + m;
                float4 v = make_float4(0.f, 0.f, 0.f, 0.f);
                if (row < M) {
                    int kg = k0 + kq * 4;
                    const float* src;
                    if (DUAL)
                        src = (kg < 256) ? (A0 + (size_t)row * 256 + kg)
                                         : (A1 + (size_t)row * 256 + (kg - 256));
                    else
                        src = A0 + (size_t)row * KTOT + kg;
                    v = *reinterpret_cast<const float4*>(src);
                }
                rA[j] = v;
            }
            float4 rB[4];
            if (bact) {
                #pragma unroll
                for (int i = 0; i < 4; i++) {
                    int krow = k0 + bkq * 4 + i;
                    int n = bcol + bnq * 4;
                    const float* src;
                    if (DUAL)
                        src = (n < 128) ? (B0 + (size_t)krow * 128 + n)
                                        : (B1 + (size_t)krow * 64 + (n - 128));
                    else
                        src = B0 + (size_t)krow * 256 + n;
                    rB[i] = *reinterpret_cast<const float4*>(src);
                }
            }

            // --- convert + STS into stage s ---
            char* base = smc + stBase;
            #pragma unroll
            for (int j = 0; j < 4; j++) {
                int idx = p + j * 256;
                int m = idx >> 3, kq = idx & 7;
                uint2 hi, lo;
                split4(rA[j], hi, lo);
                *reinterpret_cast<uint2*>(base + AH_OFF + m * (KP*2) + kq * 8) = hi;
                *reinterpret_cast<uint2*>(base + AL_OFF + m * (KP*2) + kq * 8) = lo;
            }
            if (bact) {
                #pragma unroll
                for (int j = 0; j < 4; j++) {
                    int n = bnq * 4 + j;
                    float4 kv = make_float4((&rB[0].x)[j], (&rB[1].x)[j],
                                            (&rB[2].x)[j], (&rB[3].x)[j]);
                    uint2 hi, lo;
                    split4(kv, hi, lo);
                    *reinterpret_cast<uint2*>(base + BH_OFF + n * (KP*2) + bkq * 8) = hi;
                    *reinterpret_cast<uint2*>(base + BL_OFF + n * (KP*2) + bkq * 8) = lo;
                }
            }
            BAR_ARRIVE(1 + s);
            stBase += SSTAGE;
            if (stBase == S * SSTAGE) stBase = 0;
        }
        (void)am;
    }
}

// ---------------------------------------------------------------------------
// Deformable sampling (unchanged)
// ---------------------------------------------------------------------------
__global__ void __launch_bounds__(256)
deform_sample_k(const float* __restrict__ vproj,
                const float* __restrict__ offr,
                const float* __restrict__ awr,
                const float* __restrict__ refp,
                float* __restrict__ samp)
{
    int wg   = (blockIdx.x * 256 + threadIdx.x) >> 5;
    int lane = threadIdx.x & 31;
    int q = wg >> 1;
    if (q >= NQ) return;
    int g = lane >> 3;
    int s = lane & 7;
    int h = ((wg & 1) << 2) | g;

    float rx = fmaf(refp[2*q+0], (float)WW, -0.5f);
    float ry = fmaf(refp[2*q+1], (float)HH, -0.5f);
    const float* offh = offr + (size_t)q*128 + h*16;
    const float* awh  = awr  + (size_t)q*64  + h*8;

    float4 acc = make_float4(0.f,0.f,0.f,0.f);

    #pragma unroll
    for (int nbq = 0; nbq < 2; nbq++) {
        float a0 = awh[nbq*4+0], a1 = awh[nbq*4+1];
        float a2 = awh[nbq*4+2], a3 = awh[nbq*4+3];
        float mx = fmaxf(fmaxf(a0,a1), fmaxf(a2,a3));
        float e0 = __expf(a0-mx), e1 = __expf(a1-mx);
        float e2 = __expf(a2-mx), e3 = __expf(a3-mx);
        float inv = 1.f / (e0+e1+e2+e3);
        float aws[4] = {e0*inv, e1*inv, e2*inv, e3*inv};

        const float4* vb = reinterpret_cast<const float4*>(vproj)
                         + (size_t)nbq*NQ*64 + h*8 + s;

        #pragma unroll
        for (int p = 0; p < 4; p++) {
            float x = rx + offh[nbq*8 + p*2 + 0];
            float y = ry + offh[nbq*8 + p*2 + 1];
            float xf = floorf(x), yf = floorf(y);
            float fx = x - xf, fy = y - yf;
            int x0 = (int)xf, y0 = (int)yf;
            int x1 = x0 + 1,  y1 = y0 + 1;

            float vx0 = ((unsigned)x0 < WW) ? 1.f : 0.f;
            float vx1 = ((unsigned)x1 < WW) ? 1.f : 0.f;
            float vy0 = ((unsigned)y0 < HH) ? 1.f : 0.f;
            float vy1 = ((unsigned)y1 < HH) ? 1.f : 0.f;
            int cx0 = min(max(x0,0), WW-1), cx1 = min(max(x1,0), WW-1);
            int cy0 = min(max(y0,0), HH-1), cy1 = min(max(y1,0), HH-1);

            float w   = aws[p];
            float gx1 = fx, gx0 = 1.f - fx;
            float gy1 = fy, gy0 = 1.f - fy;
            float w00 = w*gx0*gy0*vx0*vy0;
            float w01 = w*gx1*gy0*vx1*vy0;
            float w10 = w*gx0*gy1*vx0*vy1;
            float w11 = w*gx1*gy1*vx1*vy1;

            float4 v00 = vb[(size_t)(cy0*WW + cx0) * 64];
            float4 v01 = vb[(size_t)(cy0*WW + cx1) * 64];
            float4 v10 = vb[(size_t)(cy1*WW + cx0) * 64];
            float4 v11 = vb[(size_t)(cy1*WW + cx1) * 64];

            acc.x = fmaf(w00, v00.x, acc.x); acc.y = fmaf(w00, v00.y, acc.y);
            acc.z = fmaf(w00, v00.z, acc.z); acc.w = fmaf(w00, v00.w, acc.w);
            acc.x = fmaf(w01, v01.x, acc.x); acc.y = fmaf(w01, v01.y, acc.y);
            acc.z = fmaf(w01, v01.z, acc.z); acc.w = fmaf(w01, v01.w, acc.w);
            acc.x = fmaf(w10, v10.x, acc.x); acc.y = fmaf(w10, v10.y, acc.y);
            acc.z = fmaf(w10, v10.z, acc.z); acc.w = fmaf(w10, v10.w, acc.w);
            acc.x = fmaf(w11, v11.x, acc.x); acc.y = fmaf(w11, v11.y, acc.y);
            acc.z = fmaf(w11, v11.z, acc.z); acc.w = fmaf(w11, v11.w, acc.w);
        }
    }
    acc.x *= 0.5f; acc.y *= 0.5f; acc.z *= 0.5f; acc.w *= 0.5f;
    *reinterpret_cast<float4*>(samp + (size_t)q*DD + h*32 + s*4) = acc;
}

// ---------------------------------------------------------------------------
extern "C" void kernel_launch(void* const* d_in, const int* in_sizes, int n_in,
                              void* d_out, int out_size)
{
    const float* query = (const float*)d_in[0];
    const float* value = (const float*)d_in[1];
    const float* refp  = (const float*)d_in[2];
    const float* W_v  = (const float*)d_in[4];
    const float* b_v  = (const float*)d_in[5];
    const float* W_so = (const float*)d_in[6];
    const float* b_so = (const float*)d_in[7];
    const float* W_aw = (const float*)d_in[8];
    const float* b_aw = (const float*)d_in[9];
    const float* W_o  = (const float*)d_in[10];
    const float* b_o  = (const float*)d_in[11];
    float* out = (float*)d_out;

    float *vproj, *offp, *awp, *sampp;
    cudaGetSymbolAddress((void**)&vproj, g_vproj);
    cudaGetSymbolAddress((void**)&offp,  g_off);
    cudaGetSymbolAddress((void**)&awp,   g_aw);
    cudaGetSymbolAddress((void**)&sampp, g_samp);

    // stage sizes: (256 + 2*BN) * 80 bytes; 3 stages
    constexpr int SM128 = 3 * ((256 + 2 * 128) * 80);  // 122880 B (NTN=4)
    constexpr int SM96  = 3 * ((256 + 2 * 96)  * 80);  // 107520 B (NTN=3)
    cudaFuncSetAttribute(hmma_gemm<4,0,256>,
        cudaFuncAttributeMaxDynamicSharedMemorySize, SM128);
    cudaFuncSetAttribute(hmma_gemm<3,1,512>,
        cudaFuncAttributeMaxDynamicSharedMemorySize, SM96);

    // GEMM1: vproj = value @ W_v + b_v          (80000 x 256 x 256)
    hmma_gemm<4,0,256><<<dim3(2, 625), 512, SM128>>>(
        value, nullptr, W_v, nullptr, b_v, nullptr, nullptr,
        vproj, nullptr, 2*NQ);

    // GEMM2+3: [value0|query] @ {W_so,W_aw}     (40000 x {128,64} x 512)
    hmma_gemm<3,1,512><<<dim3(2, 313), 512, SM96>>>(
        value, query, W_so, W_aw, b_so, b_aw, nullptr,
        offp, awp, NQ);

    // Sampling
    deform_sample_k<<<(NQ*2 + 7)/8, 256>>>(vproj, offp, awp, refp, sampp);

    // GEMM5: out = samp @ W_o + b_o + query     (40000 x 256 x 256)
    hmma_gemm<4,0,256><<<dim3(2, 313), 512, SM128>>>(
        sampp, nullptr, W_o, nullptr, b_o, nullptr, query,
        out, nullptr, NQ);
}

// round 11
// speedup vs baseline: 2.3098x; 1.0888x over previous
#include <cuda_runtime.h>
#include <cuda_fp16.h>
#include <cstdint>
#include <cstddef>

#define HH   200
#define WW   200
#define NQ   40000
#define DD   256

__device__ float g_vproj[(size_t)2 * NQ * DD];
__device__ float g_off  [(size_t)NQ * 128];
__device__ float g_aw   [(size_t)NQ * 64];
__device__ float g_samp [(size_t)NQ * DD];

// ---------------------------------------------------------------------------
// helpers
// ---------------------------------------------------------------------------
__device__ __forceinline__ uint32_t smem_u32(const void* p) {
    uint32_t a;
    asm("{ .reg .u64 t; cvta.to.shared.u64 t, %1; cvt.u32.u64 %0, t; }"
        : "=r"(a) : "l"(p));
    return a;
}
// A: fp16 hi/lo split (residual ~2^-22)
__device__ __forceinline__ void splitA2(float a, float b, uint32_t& hi, uint32_t& lo) {
    __half2 h = __floats2half2_rn(a, b);
    float ha = __low2float(h), hb = __high2float(h);
    __half2 l = __floats2half2_rn(a - ha, b - hb);
    hi = *reinterpret_cast<uint32_t*>(&h);
    lo = *reinterpret_cast<uint32_t*>(&l);
}
__device__ __forceinline__ void splitA4(float4 v, uint2& hi, uint2& lo) {
    splitA2(v.x, v.y, hi.x, lo.x);
    splitA2(v.z, v.w, hi.y, lo.y);
}
// B: single fp16 (error ~2^-12)
__device__ __forceinline__ uint2 cvtB4(float4 v) {
    __half2 h01 = __floats2half2_rn(v.x, v.y);
    __half2 h23 = __floats2half2_rn(v.z, v.w);
    uint2 r;
    r.x = *reinterpret_cast<uint32_t*>(&h01);
    r.y = *reinterpret_cast<uint32_t*>(&h23);
    return r;
}
__device__ __forceinline__ void mma_f16(float* c, const uint32_t* a, const uint32_t* b) {
    asm volatile(
        "mma.sync.aligned.m16n8k16.row.col.f32.f16.f16.f32 "
        "{%0,%1,%2,%3}, {%4,%5,%6,%7}, {%8,%9}, {%0,%1,%2,%3};"
        : "+f"(c[0]), "+f"(c[1]), "+f"(c[2]), "+f"(c[3])
        : "r"(a[0]), "r"(a[1]), "r"(a[2]), "r"(a[3]), "r"(b[0]), "r"(b[1]));
}
__device__ __forceinline__ void ldm_x4(uint32_t* r, uint32_t a) {
    asm volatile("ldmatrix.sync.aligned.m8n8.x4.shared.b16 {%0,%1,%2,%3}, [%4];"
        : "=r"(r[0]), "=r"(r[1]), "=r"(r[2]), "=r"(r[3]) : "r"(a));
}
__device__ __forceinline__ void ldm_x2(uint32_t* r, uint32_t a) {
    asm volatile("ldmatrix.sync.aligned.m8n8.x2.shared.b16 {%0,%1}, [%2];"
        : "=r"(r[0]), "=r"(r[1]) : "r"(a));
}
#define BAR_SYNC(id)   asm volatile("bar.sync %0, 512;"   :: "r"(id) : "memory")
#define BAR_ARRIVE(id) asm volatile("bar.arrive %0, 512;" :: "r"(id) : "memory")

// ---------------------------------------------------------------------------
// Warp-specialized HMMA fp16 asymmetric-split GEMM (A = hi+lo, B = single).
// 2 MMA passes: Ah*B + Al*B. 512 threads: warps 0-7 consumers (2m x 4n,
// warp tile 64 x 8*NTN), warps 8-15 producers. 3-stage smem ring.
// K chunks of 32, KP=40 pad. Block covers 128 x BN (BN = 32*NTN).
// DUAL: A = concat(A0,A1) (stride 256 each, KTOT=512); output cols (global)
// [0,128)->C0 (stride 128, bias0), [128,192)->C1 (stride 64, bias1).
// ---------------------------------------------------------------------------
template<int NTN, int DUAL, int KTOT>
__global__ void __launch_bounds__(512, 1)
hmma_gemm(const float* __restrict__ A0, const float* __restrict__ A1,
          const float* __restrict__ B0, const float* __restrict__ B1,
          const float* __restrict__ bias0, const float* __restrict__ bias1,
          const float* __restrict__ addend,
          float* __restrict__ C0, float* __restrict__ C1, int M)
{
    constexpr int BN  = 32 * NTN;
    constexpr int KP  = 40;                     // padded row: 80 B
    constexpr int NCH = KTOT / 32;
    constexpr int S   = 3;                      // ring stages
    constexpr uint32_t AH_OFF = 0;
    constexpr uint32_t AL_OFF = 128u * KP * 2;              // 10240
    constexpr uint32_t B_OFF  = 256u * KP * 2;              // 20480
    constexpr uint32_t SSTAGE = B_OFF + (uint32_t)BN * KP * 2;

    extern __shared__ char smc[];
    const uint32_t sb = smem_u32(smc);

    const int tid = threadIdx.x;
    const int wid = tid >> 5, lane = tid & 31;
    const int brow = blockIdx.y * 128;
    const int bcol = blockIdx.x * BN;

    if (wid < 8) {
        // ================= CONSUMERS =================
        const int g = lane >> 2, t = lane & 3;
        const int warp_m = wid >> 2, warp_n = wid & 3;

        float acc[4][NTN][4];
        #pragma unroll
        for (int i = 0; i < 4; i++)
            #pragma unroll
            for (int j = 0; j < NTN; j++)
                #pragma unroll
                for (int k = 0; k < 4; k++) acc[i][j][k] = 0.f;

        const uint32_t aFrag = sb + AH_OFF
            + (uint32_t)(warp_m * 64 + (lane & 15)) * (KP * 2)
            + (uint32_t)((lane >> 4) << 4);
        const uint32_t bFragX4 = sb + B_OFF
            + (uint32_t)(warp_n * 8 * NTN + (lane >> 4) * 8 + (lane & 7)) * (KP * 2)
            + (uint32_t)(((lane >> 3) & 1) << 4);
        const uint32_t bFragX2 = sb + B_OFF
            + (uint32_t)(warp_n * 8 * NTN + (NTN - 1) * 8 + (lane & 7)) * (KP * 2)
            + (uint32_t)(((lane >> 3) & 1) << 4);

        uint32_t stBase = 0;
        for (int ch = 0; ch < NCH; ch++) {
            int s = ch % S;
            BAR_SYNC(1 + s);
            #pragma unroll
            for (int ks = 0; ks < 2; ks++) {
                uint32_t Bf[NTN][2];
                #pragma unroll
                for (int ntp = 0; ntp < NTN / 2; ntp++) {
                    uint32_t addr = bFragX4 + stBase
                        + (uint32_t)(ntp * 16 * KP * 2) + (uint32_t)(ks * 32);
                    uint32_t r[4];
                    ldm_x4(r, addr);
                    Bf[2*ntp][0] = r[0]; Bf[2*ntp][1] = r[1];
                    Bf[2*ntp+1][0] = r[2]; Bf[2*ntp+1][1] = r[3];
                }
                if (NTN & 1) {
                    uint32_t addr = bFragX2 + stBase + (uint32_t)(ks * 32);
                    ldm_x2(Bf[NTN-1], addr);
                }
                #pragma unroll
                for (int mt = 0; mt < 4; mt++) {
                    uint32_t Ah[4], Al[4];
                    uint32_t aa = aFrag + stBase
                        + (uint32_t)(mt * 16 * KP * 2) + (uint32_t)(ks * 32);
                    ldm_x4(Ah, aa);
                    ldm_x4(Al, aa + AL_OFF);
                    #pragma unroll
                    for (int nt = 0; nt < NTN; nt++)
                        mma_f16(acc[mt][nt], Ah, Bf[nt]);
                    #pragma unroll
                    for (int nt = 0; nt < NTN; nt++)
                        mma_f16(acc[mt][nt], Al, Bf[nt]);
                }
            }
            BAR_ARRIVE(1 + S + s);
            stBase += SSTAGE;
            if (stBase == S * SSTAGE) stBase = 0;
        }

        // ---- epilogue ----
        #pragma unroll
        for (int mt = 0; mt < 4; mt++) {
            int r0 = brow + warp_m * 64 + mt * 16 + g;
            #pragma unroll
            for (int nt = 0; nt < NTN; nt++) {
                int c = bcol + warp_n * 8 * NTN + nt * 8 + 2 * t;
                float2 v0 = make_float2(acc[mt][nt][0], acc[mt][nt][1]);
                float2 v1 = make_float2(acc[mt][nt][2], acc[mt][nt][3]);
                if (DUAL) {
                    if (c < 128) {
                        float2 b = *reinterpret_cast<const float2*>(bias0 + c);
                        v0.x += b.x; v0.y += b.y; v1.x += b.x; v1.y += b.y;
                        if (r0 < M)
                            *reinterpret_cast<float2*>(C0 + (size_t)r0 * 128 + c) = v0;
                        if (r0 + 8 < M)
                            *reinterpret_cast<float2*>(C0 + (size_t)(r0 + 8) * 128 + c) = v1;
                    } else {
                        int cc = c - 128;
                        float2 b = *reinterpret_cast<const float2*>(bias1 + cc);
                        v0.x += b.x; v0.y += b.y; v1.x += b.x; v1.y += b.y;
                        if (r0 < M)
                            *reinterpret_cast<float2*>(C1 + (size_t)r0 * 64 + cc) = v0;
                        if (r0 + 8 < M)
                            *reinterpret_cast<float2*>(C1 + (size_t)(r0 + 8) * 64 + cc) = v1;
                    }
                } else {
                    float2 b = *reinterpret_cast<const float2*>(bias0 + c);
                    v0.x += b.x; v0.y += b.y; v1.x += b.x; v1.y += b.y;
                    if (r0 < M) {
                        if (addend) {
                            float2 a = *reinterpret_cast<const float2*>(
                                addend + (size_t)r0 * 256 + c);
                            v0.x += a.x; v0.y += a.y;
                        }
                        *reinterpret_cast<float2*>(C0 + (size_t)r0 * 256 + c) = v0;
                    }
                    if (r0 + 8 < M) {
                        if (addend) {
                            float2 a = *reinterpret_cast<const float2*>(
                                addend + (size_t)(r0 + 8) * 256 + c);
                            v1.x += a.x; v1.y += a.y;
                        }
                        *reinterpret_cast<float2*>(C0 + (size_t)(r0 + 8) * 256 + c) = v1;
                    }
                }
            }
        }
    } else {
        // ================= PRODUCERS =================
        const int p = tid - 256;                  // 0..255
        const int bkq = p & 7, bnq = p >> 3;      // B task
        const bool bact = (p < 2 * BN);

        uint32_t stBase = 0;
        for (int ch = 0; ch < NCH; ch++) {
            int s = ch % S;
            const int k0 = ch * 32;
            if (ch >= S) BAR_SYNC(1 + S + s);

            // --- raw loads ---
            float4 rA[4];
            #pragma unroll
            for (int j = 0; j < 4; j++) {
                int idx = p + j * 256;            // 0..1023
                int m = idx >> 3, kq = idx & 7;
                int row = brow + m;
                float4 v = make_float4(0.f, 0.f, 0.f, 0.f);
                if (row < M) {
                    int kg = k0 + kq * 4;
                    const float* src;
                    if (DUAL)
                        src = (kg < 256) ? (A0 + (size_t)row * 256 + kg)
                                         : (A1 + (size_t)row * 256 + (kg - 256));
                    else
                        src = A0 + (size_t)row * KTOT + kg;
                    v = *reinterpret_cast<const float4*>(src);
                }
                rA[j] = v;
            }
            float4 rB[4];
            if (bact) {
                #pragma unroll
                for (int i = 0; i < 4; i++) {
                    int krow = k0 + bkq * 4 + i;
                    int n = bcol + bnq * 4;
                    const float* src;
                    if (DUAL)
                        src = (n < 128) ? (B0 + (size_t)krow * 128 + n)
                                        : (B1 + (size_t)krow * 64 + (n - 128));
                    else
                        src = B0 + (size_t)krow * 256 + n;
                    rB[i] = *reinterpret_cast<const float4*>(src);
                }
            }

            // --- convert + STS into stage s ---
            char* base = smc + stBase;
            #pragma unroll
            for (int j = 0; j < 4; j++) {
                int idx = p + j * 256;
                int m = idx >> 3, kq = idx & 7;
                uint2 hi, lo;
                splitA4(rA[j], hi, lo);
                *reinterpret_cast<uint2*>(base + AH_OFF + m * (KP*2) + kq * 8) = hi;
                *reinterpret_cast<uint2*>(base + AL_OFF + m * (KP*2) + kq * 8) = lo;
            }
            if (bact) {
                #pragma unroll
                for (int j = 0; j < 4; j++) {
                    int n = bnq * 4 + j;
                    float4 kv = make_float4((&rB[0].x)[j], (&rB[1].x)[j],
                                            (&rB[2].x)[j], (&rB[3].x)[j]);
                    uint2 bb = cvtB4(kv);
                    *reinterpret_cast<uint2*>(base + B_OFF + n * (KP*2) + bkq * 8) = bb;
                }
            }
            BAR_ARRIVE(1 + s);
            stBase += SSTAGE;
            if (stBase == S * SSTAGE) stBase = 0;
        }
    }
}

// ---------------------------------------------------------------------------
// Deformable sampling (unchanged)
// ---------------------------------------------------------------------------
__global__ void __launch_bounds__(256)
deform_sample_k(const float* __restrict__ vproj,
                const float* __restrict__ offr,
                const float* __restrict__ awr,
                const float* __restrict__ refp,
                float* __restrict__ samp)
{
    int wg   = (blockIdx.x * 256 + threadIdx.x) >> 5;
    int lane = threadIdx.x & 31;
    int q = wg >> 1;
    if (q >= NQ) return;
    int g = lane >> 3;
    int s = lane & 7;
    int h = ((wg & 1) << 2) | g;

    float rx = fmaf(refp[2*q+0], (float)WW, -0.5f);
    float ry = fmaf(refp[2*q+1], (float)HH, -0.5f);
    const float* offh = offr + (size_t)q*128 + h*16;
    const float* awh  = awr  + (size_t)q*64  + h*8;

    float4 acc = make_float4(0.f,0.f,0.f,0.f);

    #pragma unroll
    for (int nbq = 0; nbq < 2; nbq++) {
        float a0 = awh[nbq*4+0], a1 = awh[nbq*4+1];
        float a2 = awh[nbq*4+2], a3 = awh[nbq*4+3];
        float mx = fmaxf(fmaxf(a0,a1), fmaxf(a2,a3));
        float e0 = __expf(a0-mx), e1 = __expf(a1-mx);
        float e2 = __expf(a2-mx), e3 = __expf(a3-mx);
        float inv = 1.f / (e0+e1+e2+e3);
        float aws[4] = {e0*inv, e1*inv, e2*inv, e3*inv};

        const float4* vb = reinterpret_cast<const float4*>(vproj)
                         + (size_t)nbq*NQ*64 + h*8 + s;

        #pragma unroll
        for (int p = 0; p < 4; p++) {
            float x = rx + offh[nbq*8 + p*2 + 0];
            float y = ry + offh[nbq*8 + p*2 + 1];
            float xf = floorf(x), yf = floorf(y);
            float fx = x - xf, fy = y - yf;
            int x0 = (int)xf, y0 = (int)yf;
            int x1 = x0 + 1,  y1 = y0 + 1;

            float vx0 = ((unsigned)x0 < WW) ? 1.f : 0.f;
            float vx1 = ((unsigned)x1 < WW) ? 1.f : 0.f;
            float vy0 = ((unsigned)y0 < HH) ? 1.f : 0.f;
            float vy1 = ((unsigned)y1 < HH) ? 1.f : 0.f;
            int cx0 = min(max(x0,0), WW-1), cx1 = min(max(x1,0), WW-1);
            int cy0 = min(max(y0,0), HH-1), cy1 = min(max(y1,0), HH-1);

            float w   = aws[p];
            float gx1 = fx, gx0 = 1.f - fx;
            float gy1 = fy, gy0 = 1.f - fy;
            float w00 = w*gx0*gy0*vx0*vy0;
            float w01 = w*gx1*gy0*vx1*vy0;
            float w10 = w*gx0*gy1*vx0*vy1;
            float w11 = w*gx1*gy1*vx1*vy1;

            float4 v00 = vb[(size_t)(cy0*WW + cx0) * 64];
            float4 v01 = vb[(size_t)(cy0*WW + cx1) * 64];
            float4 v10 = vb[(size_t)(cy1*WW + cx0) * 64];
            float4 v11 = vb[(size_t)(cy1*WW + cx1) * 64];

            acc.x = fmaf(w00, v00.x, acc.x); acc.y = fmaf(w00, v00.y, acc.y);
            acc.z = fmaf(w00, v00.z, acc.z); acc.w = fmaf(w00, v00.w, acc.w);
            acc.x = fmaf(w01, v01.x, acc.x); acc.y = fmaf(w01, v01.y, acc.y);
            acc.z = fmaf(w01, v01.z, acc.z); acc.w = fmaf(w01, v01.w, acc.w);
            acc.x = fmaf(w10, v10.x, acc.x); acc.y = fmaf(w10, v10.y, acc.y);
            acc.z = fmaf(w10, v10.z, acc.z); acc.w = fmaf(w10, v10.w, acc.w);
            acc.x = fmaf(w11, v11.x, acc.x); acc.y = fmaf(w11, v11.y, acc.y);
            acc.z = fmaf(w11, v11.z, acc.z); acc.w = fmaf(w11, v11.w, acc.w);
        }
    }
    acc.x *= 0.5f; acc.y *= 0.5f; acc.z *= 0.5f; acc.w *= 0.5f;
    *reinterpret_cast<float4*>(samp + (size_t)q*DD + h*32 + s*4) = acc;
}

// ---------------------------------------------------------------------------
extern "C" void kernel_launch(void* const* d_in, const int* in_sizes, int n_in,
                              void* d_out, int out_size)
{
    const float* query = (const float*)d_in[0];
    const float* value = (const float*)d_in[1];
    const float* refp  = (const float*)d_in[2];
    const float* W_v  = (const float*)d_in[4];
    const float* b_v  = (const float*)d_in[5];
    const float* W_so = (const float*)d_in[6];
    const float* b_so = (const float*)d_in[7];
    const float* W_aw = (const float*)d_in[8];
    const float* b_aw = (const float*)d_in[9];
    const float* W_o  = (const float*)d_in[10];
    const float* b_o  = (const float*)d_in[11];
    float* out = (float*)d_out;

    float *vproj, *offp, *awp, *sampp;
    cudaGetSymbolAddress((void**)&vproj, g_vproj);
    cudaGetSymbolAddress((void**)&offp,  g_off);
    cudaGetSymbolAddress((void**)&awp,   g_aw);
    cudaGetSymbolAddress((void**)&sampp, g_samp);

    // stage sizes: (256 + BN) * 80 bytes; 3 stages
    constexpr int SM128 = 3 * ((256 + 128) * 80);  // 92160 B (NTN=4)
    constexpr int SM96  = 3 * ((256 + 96)  * 80);  // 84480 B (NTN=3)
    cudaFuncSetAttribute(hmma_gemm<4,0,256>,
        cudaFuncAttributeMaxDynamicSharedMemorySize, SM128);
    cudaFuncSetAttribute(hmma_gemm<3,1,512>,
        cudaFuncAttributeMaxDynamicSharedMemorySize, SM96);

    // GEMM1: vproj = value @ W_v + b_v          (80000 x 256 x 256)
    hmma_gemm<4,0,256><<<dim3(2, 625), 512, SM128>>>(
        value, nullptr, W_v, nullptr, b_v, nullptr, nullptr,
        vproj, nullptr, 2*NQ);

    // GEMM2+3: [value0|query] @ {W_so,W_aw}     (40000 x {128,64} x 512)
    hmma_gemm<3,1,512><<<dim3(2, 313), 512, SM96>>>(
        value, query, W_so, W_aw, b_so, b_aw, nullptr,
        offp, awp, NQ);

    // Sampling
    deform_sample_k<<<(NQ*2 + 7)/8, 256>>>(vproj, offp, awp, refp, sampp);

    // GEMM5: out = samp @ W_o + b_o + query     (40000 x 256 x 256)
    hmma_gemm<4,0,256><<<dim3(2, 313), 512, SM128>>>(
        sampp, nullptr, W_o, nullptr, b_o, nullptr, query,
        out, nullptr, NQ);
}

// round 12
// speedup vs baseline: 2.5846x; 1.1190x over previous
#include <cuda_runtime.h>
#include <cuda_fp16.h>
#include <cstdint>
#include <cstddef>

#define HH   200
#define WW   200
#define NQ   40000
#define DD   256

__device__ float g_vproj[(size_t)2 * NQ * DD];   // used as fp16 (half occupied)
__device__ float g_off  [(size_t)NQ * 128];
__device__ float g_aw   [(size_t)NQ * 64];
__device__ float g_samp [(size_t)NQ * DD];

// ---------------------------------------------------------------------------
// helpers
// ---------------------------------------------------------------------------
__device__ __forceinline__ uint32_t smem_u32(const void* p) {
    uint32_t a;
    asm("{ .reg .u64 t; cvta.to.shared.u64 t, %1; cvt.u32.u64 %0, t; }"
        : "=r"(a) : "l"(p));
    return a;
}
// hi/lo fp16 split (residual ~2^-22)
__device__ __forceinline__ void split_h2(float a, float b, uint32_t& hi, uint32_t& lo) {
    __half2 h = __floats2half2_rn(a, b);
    float ha = __low2float(h), hb = __high2float(h);
    __half2 l = __floats2half2_rn(a - ha, b - hb);
    hi = *reinterpret_cast<uint32_t*>(&h);
    lo = *reinterpret_cast<uint32_t*>(&l);
}
__device__ __forceinline__ void split_h4(float4 v, uint2& hi, uint2& lo) {
    split_h2(v.x, v.y, hi.x, lo.x);
    split_h2(v.z, v.w, hi.y, lo.y);
}
// single fp16 (error ~2^-12)
__device__ __forceinline__ uint2 cvt_h4(float4 v) {
    __half2 h01 = __floats2half2_rn(v.x, v.y);
    __half2 h23 = __floats2half2_rn(v.z, v.w);
    uint2 r;
    r.x = *reinterpret_cast<uint32_t*>(&h01);
    r.y = *reinterpret_cast<uint32_t*>(&h23);
    return r;
}
__device__ __forceinline__ void mma_f16(float* c, const uint32_t* a, const uint32_t* b) {
    asm volatile(
        "mma.sync.aligned.m16n8k16.row.col.f32.f16.f16.f32 "
        "{%0,%1,%2,%3}, {%4,%5,%6,%7}, {%8,%9}, {%0,%1,%2,%3};"
        : "+f"(c[0]), "+f"(c[1]), "+f"(c[2]), "+f"(c[3])
        : "r"(a[0]), "r"(a[1]), "r"(a[2]), "r"(a[3]), "r"(b[0]), "r"(b[1]));
}
__device__ __forceinline__ void ldm_x4(uint32_t* r, uint32_t a) {
    asm volatile("ldmatrix.sync.aligned.m8n8.x4.shared.b16 {%0,%1,%2,%3}, [%4];"
        : "=r"(r[0]), "=r"(r[1]), "=r"(r[2]), "=r"(r[3]) : "r"(a));
}
__device__ __forceinline__ void ldm_x2(uint32_t* r, uint32_t a) {
    asm volatile("ldmatrix.sync.aligned.m8n8.x2.shared.b16 {%0,%1}, [%2];"
        : "=r"(r[0]), "=r"(r[1]) : "r"(a));
}
#define BAR_SYNC(id)   asm volatile("bar.sync %0, 512;"   :: "r"(id) : "memory")
#define BAR_ARRIVE(id) asm volatile("bar.arrive %0, 512;" :: "r"(id) : "memory")

// ---------------------------------------------------------------------------
// Warp-specialized HMMA fp16 GEMM with asymmetric split on B (weights):
// A single fp16 (activation quant ~2^-12), B = bh + bl. 2 MMA passes.
// 512 threads: warps 0-7 consumers (2m x 4n, warp tile 64 x 8*NTN),
// warps 8-15 producers. 3-stage smem ring, K chunks of 32, KP=40 pad.
// Block covers 128 x BN (BN = 32*NTN).
// DUAL: A = concat(A0,A1) (stride 256 each, KTOT=512); output cols (global)
// [0,128)->C0 (stride 128, bias0), [128,192)->C1 (stride 64, bias1).
// HOUT: non-dual only; C0 is __half* (stride 256), no addend.
// ---------------------------------------------------------------------------
template<int NTN, int DUAL, int KTOT, int HOUT>
__global__ void __launch_bounds__(512, 1)
hmma_gemm(const float* __restrict__ A0, const float* __restrict__ A1,
          const float* __restrict__ B0, const float* __restrict__ B1,
          const float* __restrict__ bias0, const float* __restrict__ bias1,
          const float* __restrict__ addend,
          float* __restrict__ C0, float* __restrict__ C1, int M)
{
    constexpr int BN  = 32 * NTN;
    constexpr int KP  = 40;                     // padded row: 80 B
    constexpr int NCH = KTOT / 32;
    constexpr int S   = 3;                      // ring stages
    constexpr uint32_t A_OFF  = 0;
    constexpr uint32_t BH_OFF = 128u * KP * 2;              // 10240
    constexpr uint32_t BL_OFF = BH_OFF + (uint32_t)BN * KP * 2;
    constexpr uint32_t SSTAGE = BH_OFF + 2u * (uint32_t)BN * KP * 2;

    extern __shared__ char smc[];
    const uint32_t sb = smem_u32(smc);

    const int tid = threadIdx.x;
    const int wid = tid >> 5, lane = tid & 31;
    const int brow = blockIdx.y * 128;
    const int bcol = blockIdx.x * BN;

    if (wid < 8) {
        // ================= CONSUMERS =================
        const int g = lane >> 2, t = lane & 3;
        const int warp_m = wid >> 2, warp_n = wid & 3;

        float acc[4][NTN][4];
        #pragma unroll
        for (int i = 0; i < 4; i++)
            #pragma unroll
            for (int j = 0; j < NTN; j++)
                #pragma unroll
                for (int k = 0; k < 4; k++) acc[i][j][k] = 0.f;

        const uint32_t aFrag = sb + A_OFF
            + (uint32_t)(warp_m * 64 + (lane & 15)) * (KP * 2)
            + (uint32_t)((lane >> 4) << 4);
        const uint32_t bFragX4 = sb + BH_OFF
            + (uint32_t)(warp_n * 8 * NTN + (lane >> 4) * 8 + (lane & 7)) * (KP * 2)
            + (uint32_t)(((lane >> 3) & 1) << 4);
        const uint32_t bFragX2 = sb + BH_OFF
            + (uint32_t)(warp_n * 8 * NTN + (NTN - 1) * 8 + (lane & 7)) * (KP * 2)
            + (uint32_t)(((lane >> 3) & 1) << 4);
        constexpr uint32_t BLD = (uint32_t)BN * KP * 2;   // hi->lo delta

        uint32_t stBase = 0;
        for (int ch = 0; ch < NCH; ch++) {
            int s = ch % S;
            BAR_SYNC(1 + s);
            #pragma unroll
            for (int ks = 0; ks < 2; ks++) {
                uint32_t Bh[NTN][2], Bl[NTN][2];
                #pragma unroll
                for (int ntp = 0; ntp < NTN / 2; ntp++) {
                    uint32_t addr = bFragX4 + stBase
                        + (uint32_t)(ntp * 16 * KP * 2) + (uint32_t)(ks * 32);
                    uint32_t r[4];
                    ldm_x4(r, addr);
                    Bh[2*ntp][0] = r[0]; Bh[2*ntp][1] = r[1];
                    Bh[2*ntp+1][0] = r[2]; Bh[2*ntp+1][1] = r[3];
                    ldm_x4(r, addr + BLD);
                    Bl[2*ntp][0] = r[0]; Bl[2*ntp][1] = r[1];
                    Bl[2*ntp+1][0] = r[2]; Bl[2*ntp+1][1] = r[3];
                }
                if (NTN & 1) {
                    uint32_t addr = bFragX2 + stBase + (uint32_t)(ks * 32);
                    ldm_x2(Bh[NTN-1], addr);
                    ldm_x2(Bl[NTN-1], addr + BLD);
                }
                #pragma unroll
                for (int mt = 0; mt < 4; mt++) {
                    uint32_t Af[4];
                    uint32_t aa = aFrag + stBase
                        + (uint32_t)(mt * 16 * KP * 2) + (uint32_t)(ks * 32);
                    ldm_x4(Af, aa);
                    #pragma unroll
                    for (int nt = 0; nt < NTN; nt++)
                        mma_f16(acc[mt][nt], Af, Bh[nt]);
                    #pragma unroll
                    for (int nt = 0; nt < NTN; nt++)
                        mma_f16(acc[mt][nt], Af, Bl[nt]);
                }
            }
            BAR_ARRIVE(1 + S + s);
            stBase += SSTAGE;
            if (stBase == S * SSTAGE) stBase = 0;
        }

        // ---- epilogue ----
        #pragma unroll
        for (int mt = 0; mt < 4; mt++) {
            int r0 = brow + warp_m * 64 + mt * 16 + g;
            #pragma unroll
            for (int nt = 0; nt < NTN; nt++) {
                int c = bcol + warp_n * 8 * NTN + nt * 8 + 2 * t;
                float2 v0 = make_float2(acc[mt][nt][0], acc[mt][nt][1]);
                float2 v1 = make_float2(acc[mt][nt][2], acc[mt][nt][3]);
                if (DUAL) {
                    if (c < 128) {
                        float2 b = *reinterpret_cast<const float2*>(bias0 + c);
                        v0.x += b.x; v0.y += b.y; v1.x += b.x; v1.y += b.y;
                        if (r0 < M)
                            *reinterpret_cast<float2*>(C0 + (size_t)r0 * 128 + c) = v0;
                        if (r0 + 8 < M)
                            *reinterpret_cast<float2*>(C0 + (size_t)(r0 + 8) * 128 + c) = v1;
                    } else {
                        int cc = c - 128;
                        float2 b = *reinterpret_cast<const float2*>(bias1 + cc);
                        v0.x += b.x; v0.y += b.y; v1.x += b.x; v1.y += b.y;
                        if (r0 < M)
                            *reinterpret_cast<float2*>(C1 + (size_t)r0 * 64 + cc) = v0;
                        if (r0 + 8 < M)
                            *reinterpret_cast<float2*>(C1 + (size_t)(r0 + 8) * 64 + cc) = v1;
                    }
                } else {
                    float2 b = *reinterpret_cast<const float2*>(bias0 + c);
                    v0.x += b.x; v0.y += b.y; v1.x += b.x; v1.y += b.y;
                    if (HOUT) {
                        __half* H = reinterpret_cast<__half*>(C0);
                        __half2 h0 = __floats2half2_rn(v0.x, v0.y);
                        __half2 h1 = __floats2half2_rn(v1.x, v1.y);
                        if (r0 < M)
                            *reinterpret_cast<uint32_t*>(H + (size_t)r0 * 256 + c) =
                                *reinterpret_cast<uint32_t*>(&h0);
                        if (r0 + 8 < M)
                            *reinterpret_cast<uint32_t*>(H + (size_t)(r0 + 8) * 256 + c) =
                                *reinterpret_cast<uint32_t*>(&h1);
                    } else {
                        if (r0 < M) {
                            if (addend) {
                                float2 a = *reinterpret_cast<const float2*>(
                                    addend + (size_t)r0 * 256 + c);
                                v0.x += a.x; v0.y += a.y;
                            }
                            *reinterpret_cast<float2*>(C0 + (size_t)r0 * 256 + c) = v0;
                        }
                        if (r0 + 8 < M) {
                            if (addend) {
                                float2 a = *reinterpret_cast<const float2*>(
                                    addend + (size_t)(r0 + 8) * 256 + c);
                                v1.x += a.x; v1.y += a.y;
                            }
                            *reinterpret_cast<float2*>(C0 + (size_t)(r0 + 8) * 256 + c) = v1;
                        }
                    }
                }
            }
        }
    } else {
        // ================= PRODUCERS =================
        const int p = tid - 256;                  // 0..255
        const int bkq = p & 7, bnq = p >> 3;      // B task
        const bool bact = (p < 2 * BN);

        uint32_t stBase = 0;
        for (int ch = 0; ch < NCH; ch++) {
            int s = ch % S;
            const int k0 = ch * 32;
            if (ch >= S) BAR_SYNC(1 + S + s);

            // --- raw loads ---
            float4 rA[4];
            #pragma unroll
            for (int j = 0; j < 4; j++) {
                int idx = p + j * 256;            // 0..1023
                int m = idx >> 3, kq = idx & 7;
                int row = brow + m;
                float4 v = make_float4(0.f, 0.f, 0.f, 0.f);
                if (row < M) {
                    int kg = k0 + kq * 4;
                    const float* src;
                    if (DUAL)
                        src = (kg < 256) ? (A0 + (size_t)row * 256 + kg)
                                         : (A1 + (size_t)row * 256 + (kg - 256));
                    else
                        src = A0 + (size_t)row * KTOT + kg;
                    v = *reinterpret_cast<const float4*>(src);
                }
                rA[j] = v;
            }
            float4 rB[4];
            if (bact) {
                #pragma unroll
                for (int i = 0; i < 4; i++) {
                    int krow = k0 + bkq * 4 + i;
                    int n = bcol + bnq * 4;
                    const float* src;
                    if (DUAL)
                        src = (n < 128) ? (B0 + (size_t)krow * 128 + n)
                                        : (B1 + (size_t)krow * 64 + (n - 128));
                    else
                        src = B0 + (size_t)krow * 256 + n;
                    rB[i] = *reinterpret_cast<const float4*>(src);
                }
            }

            // --- convert + STS into stage s ---
            char* base = smc + stBase;
            #pragma unroll
            for (int j = 0; j < 4; j++) {
                int idx = p + j * 256;
                int m = idx >> 3, kq = idx & 7;
                uint2 av = cvt_h4(rA[j]);
                *reinterpret_cast<uint2*>(base + A_OFF + m * (KP*2) + kq * 8) = av;
            }
            if (bact) {
                #pragma unroll
                for (int j = 0; j < 4; j++) {
                    int n = bnq * 4 + j;
                    float4 kv = make_float4((&rB[0].x)[j], (&rB[1].x)[j],
                                            (&rB[2].x)[j], (&rB[3].x)[j]);
                    uint2 hi, lo;
                    split_h4(kv, hi, lo);
                    *reinterpret_cast<uint2*>(base + BH_OFF + n * (KP*2) + bkq * 8) = hi;
                    *reinterpret_cast<uint2*>(base + BL_OFF + n * (KP*2) + bkq * 8) = lo;
                }
            }
            BAR_ARRIVE(1 + s);
            stBase += SSTAGE;
            if (stBase == S * SSTAGE) stBase = 0;
        }
    }
}

// ---------------------------------------------------------------------------
// Deformable sampling — vproj is fp16 now; lane loads uint2 = 4 channels.
// ---------------------------------------------------------------------------
__device__ __forceinline__ void accum_h(float4& acc, float w, uint2 u) {
    float2 p0 = __half22float2(*reinterpret_cast<__half2*>(&u.x));
    float2 p1 = __half22float2(*reinterpret_cast<__half2*>(&u.y));
    acc.x = fmaf(w, p0.x, acc.x); acc.y = fmaf(w, p0.y, acc.y);
    acc.z = fmaf(w, p1.x, acc.z); acc.w = fmaf(w, p1.y, acc.w);
}

__global__ void __launch_bounds__(256)
deform_sample_k(const float* __restrict__ vproj,   // fp16 data
                const float* __restrict__ offr,
                const float* __restrict__ awr,
                const float* __restrict__ refp,
                float* __restrict__ samp)
{
    int wg   = (blockIdx.x * 256 + threadIdx.x) >> 5;
    int lane = threadIdx.x & 31;
    int q = wg >> 1;
    if (q >= NQ) return;
    int g = lane >> 3;
    int s = lane & 7;
    int h = ((wg & 1) << 2) | g;

    float rx = fmaf(refp[2*q+0], (float)WW, -0.5f);
    float ry = fmaf(refp[2*q+1], (float)HH, -0.5f);
    const float* offh = offr + (size_t)q*128 + h*16;
    const float* awh  = awr  + (size_t)q*64  + h*8;

    float4 acc = make_float4(0.f,0.f,0.f,0.f);

    #pragma unroll
    for (int nbq = 0; nbq < 2; nbq++) {
        float a0 = awh[nbq*4+0], a1 = awh[nbq*4+1];
        float a2 = awh[nbq*4+2], a3 = awh[nbq*4+3];
        float mx = fmaxf(fmaxf(a0,a1), fmaxf(a2,a3));
        float e0 = __expf(a0-mx), e1 = __expf(a1-mx);
        float e2 = __expf(a2-mx), e3 = __expf(a3-mx);
        float inv = 1.f / (e0+e1+e2+e3);
        float aws[4] = {e0*inv, e1*inv, e2*inv, e3*inv};

        // fp16 layout: 256 ch = 64 uint2 per pixel; lane slot h*8+s
        const uint2* vb = reinterpret_cast<const uint2*>(vproj)
                        + ((size_t)nbq*NQ)*64 + h*8 + s;

        #pragma unroll
        for (int p = 0; p < 4; p++) {
            float x = rx + offh[nbq*8 + p*2 + 0];
            float y = ry + offh[nbq*8 + p*2 + 1];
            float xf = floorf(x), yf = floorf(y);
            float fx = x - xf, fy = y - yf;
            int x0 = (int)xf, y0 = (int)yf;
            int x1 = x0 + 1,  y1 = y0 + 1;

            float vx0 = ((unsigned)x0 < WW) ? 1.f : 0.f;
            float vx1 = ((unsigned)x1 < WW) ? 1.f : 0.f;
            float vy0 = ((unsigned)y0 < HH) ? 1.f : 0.f;
            float vy1 = ((unsigned)y1 < HH) ? 1.f : 0.f;
            int cx0 = min(max(x0,0), WW-1), cx1 = min(max(x1,0), WW-1);
            int cy0 = min(max(y0,0), HH-1), cy1 = min(max(y1,0), HH-1);

            float w   = aws[p];
            float gx1 = fx, gx0 = 1.f - fx;
            float gy1 = fy, gy0 = 1.f - fy;
            float w00 = w*gx0*gy0*vx0*vy0;
            float w01 = w*gx1*gy0*vx1*vy0;
            float w10 = w*gx0*gy1*vx0*vy1;
            float w11 = w*gx1*gy1*vx1*vy1;

            uint2 u00 = vb[(size_t)(cy0*WW + cx0) * 64];
            uint2 u01 = vb[(size_t)(cy0*WW + cx1) * 64];
            uint2 u10 = vb[(size_t)(cy1*WW + cx0) * 64];
            uint2 u11 = vb[(size_t)(cy1*WW + cx1) * 64];

            accum_h(acc, w00, u00);
            accum_h(acc, w01, u01);
            accum_h(acc, w10, u10);
            accum_h(acc, w11, u11);
        }
    }
    acc.x *= 0.5f; acc.y *= 0.5f; acc.z *= 0.5f; acc.w *= 0.5f;
    *reinterpret_cast<float4*>(samp + (size_t)q*DD + h*32 + s*4) = acc;
}

// ---------------------------------------------------------------------------
extern "C" void kernel_launch(void* const* d_in, const int* in_sizes, int n_in,
                              void* d_out, int out_size)
{
    const float* query = (const float*)d_in[0];
    const float* value = (const float*)d_in[1];
    const float* refp  = (const float*)d_in[2];
    const float* W_v  = (const float*)d_in[4];
    const float* b_v  = (const float*)d_in[5];
    const float* W_so = (const float*)d_in[6];
    const float* b_so = (const float*)d_in[7];
    const float* W_aw = (const float*)d_in[8];
    const float* b_aw = (const float*)d_in[9];
    const float* W_o  = (const float*)d_in[10];
    const float* b_o  = (const float*)d_in[11];
    float* out = (float*)d_out;

    float *vproj, *offp, *awp, *sampp;
    cudaGetSymbolAddress((void**)&vproj, g_vproj);
    cudaGetSymbolAddress((void**)&offp,  g_off);
    cudaGetSymbolAddress((void**)&awp,   g_aw);
    cudaGetSymbolAddress((void**)&sampp, g_samp);

    // stage: A 128*80 + B hi/lo 2*BN*80 bytes; 3 stages
    constexpr int SM128 = 3 * (128 * 80 + 2 * 128 * 80);  // 92160 (NTN=4)
    constexpr int SM96  = 3 * (128 * 80 + 2 * 96 * 80);   // 76800 (NTN=3)
    cudaFuncSetAttribute(hmma_gemm<4,0,256,1>,
        cudaFuncAttributeMaxDynamicSharedMemorySize, SM128);
    cudaFuncSetAttribute(hmma_gemm<3,1,512,0>,
        cudaFuncAttributeMaxDynamicSharedMemorySize, SM96);
    cudaFuncSetAttribute(hmma_gemm<4,0,256,0>,
        cudaFuncAttributeMaxDynamicSharedMemorySize, SM128);

    // GEMM1: vproj(fp16) = value @ W_v + b_v    (80000 x 256 x 256)
    hmma_gemm<4,0,256,1><<<dim3(2, 625), 512, SM128>>>(
        value, nullptr, W_v, nullptr, b_v, nullptr, nullptr,
        vproj, nullptr, 2*NQ);

    // GEMM2+3: [value0|query] @ {W_so,W_aw}     (40000 x {128,64} x 512)
    hmma_gemm<3,1,512,0><<<dim3(2, 313), 512, SM96>>>(
        value, query, W_so, W_aw, b_so, b_aw, nullptr,
        offp, awp, NQ);

    // Sampling (fp16 vproj)
    deform_sample_k<<<(NQ*2 + 7)/8, 256>>>(vproj, offp, awp, refp, sampp);

    // GEMM5: out = samp @ W_o + b_o + query     (40000 x 256 x 256)
    hmma_gemm<4,0,256,0><<<dim3(2, 313), 512, SM128>>>(
        sampp, nullptr, W_o, nullptr, b_o, nullptr, query,
        out, nullptr, NQ);
}

// round 13
// speedup vs baseline: 2.7297x; 1.0561x over previous
#include <cuda_runtime.h>
#include <cuda_fp16.h>
#include <cstdint>
#include <cstddef>

#define HH   200
#define WW   200
#define NQ   40000
#define DD   256

__device__ float g_vproj[(size_t)2 * NQ * DD];   // used as fp16 (half occupied)
__device__ float g_off  [(size_t)NQ * 128];
__device__ float g_aw   [(size_t)NQ * 64];
__device__ float g_samp [(size_t)NQ * DD];

// ---------------------------------------------------------------------------
// helpers
// ---------------------------------------------------------------------------
__device__ __forceinline__ uint32_t smem_u32(const void* p) {
    uint32_t a;
    asm("{ .reg .u64 t; cvta.to.shared.u64 t, %1; cvt.u32.u64 %0, t; }"
        : "=r"(a) : "l"(p));
    return a;
}
// single fp16 conversion (error ~2^-12)
__device__ __forceinline__ uint2 cvt_h4(float4 v) {
    __half2 h01 = __floats2half2_rn(v.x, v.y);
    __half2 h23 = __floats2half2_rn(v.z, v.w);
    uint2 r;
    r.x = *reinterpret_cast<uint32_t*>(&h01);
    r.y = *reinterpret_cast<uint32_t*>(&h23);
    return r;
}
__device__ __forceinline__ void mma_f16(float* c, const uint32_t* a, const uint32_t* b) {
    asm volatile(
        "mma.sync.aligned.m16n8k16.row.col.f32.f16.f16.f32 "
        "{%0,%1,%2,%3}, {%4,%5,%6,%7}, {%8,%9}, {%0,%1,%2,%3};"
        : "+f"(c[0]), "+f"(c[1]), "+f"(c[2]), "+f"(c[3])
        : "r"(a[0]), "r"(a[1]), "r"(a[2]), "r"(a[3]), "r"(b[0]), "r"(b[1]));
}
__device__ __forceinline__ void ldm_x4(uint32_t* r, uint32_t a) {
    asm volatile("ldmatrix.sync.aligned.m8n8.x4.shared.b16 {%0,%1,%2,%3}, [%4];"
        : "=r"(r[0]), "=r"(r[1]), "=r"(r[2]), "=r"(r[3]) : "r"(a));
}
__device__ __forceinline__ void ldm_x2(uint32_t* r, uint32_t a) {
    asm volatile("ldmatrix.sync.aligned.m8n8.x2.shared.b16 {%0,%1}, [%2];"
        : "=r"(r[0]), "=r"(r[1]) : "r"(a));
}
#define BAR_SYNC(id)   asm volatile("bar.sync %0, 512;"   :: "r"(id) : "memory")
#define BAR_ARRIVE(id) asm volatile("bar.arrive %0, 512;" :: "r"(id) : "memory")

// ---------------------------------------------------------------------------
// Warp-specialized plain-fp16 HMMA GEMM (single pass; both operands fp16).
// 512 threads: warps 0-7 consumers (2m x 4n, warp tile 64 x 8*NTN),
// warps 8-15 producers (LDG -> cvt -> STS). 3-stage smem ring.
// K chunks of 32, KP=40 pad. Block covers 128 x BN (BN = 32*NTN).
// DUAL: A = concat(A0,A1) (stride 256 each, KTOT=512); output cols (global)
// [0,128)->C0 (stride 128, bias0), [128,192)->C1 (stride 64, bias1).
// HOUT: non-dual only; C0 is __half* (stride 256), no addend.
// ---------------------------------------------------------------------------
template<int NTN, int DUAL, int KTOT, int HOUT>
__global__ void __launch_bounds__(512, 1)
hmma_gemm(const float* __restrict__ A0, const float* __restrict__ A1,
          const float* __restrict__ B0, const float* __restrict__ B1,
          const float* __restrict__ bias0, const float* __restrict__ bias1,
          const float* __restrict__ addend,
          float* __restrict__ C0, float* __restrict__ C1, int M)
{
    constexpr int BN  = 32 * NTN;
    constexpr int KP  = 40;                     // padded row: 80 B
    constexpr int NCH = KTOT / 32;
    constexpr int S   = 3;                      // ring stages
    constexpr uint32_t A_OFF  = 0;
    constexpr uint32_t B_OFF  = 128u * KP * 2;              // 10240
    constexpr uint32_t SSTAGE = B_OFF + (uint32_t)BN * KP * 2;

    extern __shared__ char smc[];
    const uint32_t sb = smem_u32(smc);

    const int tid = threadIdx.x;
    const int wid = tid >> 5, lane = tid & 31;
    const int brow = blockIdx.y * 128;
    const int bcol = blockIdx.x * BN;

    if (wid < 8) {
        // ================= CONSUMERS =================
        const int g = lane >> 2, t = lane & 3;
        const int warp_m = wid >> 2, warp_n = wid & 3;

        float acc[4][NTN][4];
        #pragma unroll
        for (int i = 0; i < 4; i++)
            #pragma unroll
            for (int j = 0; j < NTN; j++)
                #pragma unroll
                for (int k = 0; k < 4; k++) acc[i][j][k] = 0.f;

        const uint32_t aFrag = sb + A_OFF
            + (uint32_t)(warp_m * 64 + (lane & 15)) * (KP * 2)
            + (uint32_t)((lane >> 4) << 4);
        const uint32_t bFragX4 = sb + B_OFF
            + (uint32_t)(warp_n * 8 * NTN + (lane >> 4) * 8 + (lane & 7)) * (KP * 2)
            + (uint32_t)(((lane >> 3) & 1) << 4);
        const uint32_t bFragX2 = sb + B_OFF
            + (uint32_t)(warp_n * 8 * NTN + (NTN - 1) * 8 + (lane & 7)) * (KP * 2)
            + (uint32_t)(((lane >> 3) & 1) << 4);

        uint32_t stBase = 0;
        for (int ch = 0; ch < NCH; ch++) {
            int s = ch % S;
            BAR_SYNC(1 + s);
            #pragma unroll
            for (int ks = 0; ks < 2; ks++) {
                uint32_t Bf[NTN][2];
                #pragma unroll
                for (int ntp = 0; ntp < NTN / 2; ntp++) {
                    uint32_t addr = bFragX4 + stBase
                        + (uint32_t)(ntp * 16 * KP * 2) + (uint32_t)(ks * 32);
                    uint32_t r[4];
                    ldm_x4(r, addr);
                    Bf[2*ntp][0] = r[0]; Bf[2*ntp][1] = r[1];
                    Bf[2*ntp+1][0] = r[2]; Bf[2*ntp+1][1] = r[3];
                }
                if (NTN & 1) {
                    uint32_t addr = bFragX2 + stBase + (uint32_t)(ks * 32);
                    ldm_x2(Bf[NTN-1], addr);
                }
                #pragma unroll
                for (int mt = 0; mt < 4; mt++) {
                    uint32_t Af[4];
                    uint32_t aa = aFrag + stBase
                        + (uint32_t)(mt * 16 * KP * 2) + (uint32_t)(ks * 32);
                    ldm_x4(Af, aa);
                    #pragma unroll
                    for (int nt = 0; nt < NTN; nt++)
                        mma_f16(acc[mt][nt], Af, Bf[nt]);
                }
            }
            BAR_ARRIVE(1 + S + s);
            stBase += SSTAGE;
            if (stBase == S * SSTAGE) stBase = 0;
        }

        // ---- epilogue ----
        #pragma unroll
        for (int mt = 0; mt < 4; mt++) {
            int r0 = brow + warp_m * 64 + mt * 16 + g;
            #pragma unroll
            for (int nt = 0; nt < NTN; nt++) {
                int c = bcol + warp_n * 8 * NTN + nt * 8 + 2 * t;
                float2 v0 = make_float2(acc[mt][nt][0], acc[mt][nt][1]);
                float2 v1 = make_float2(acc[mt][nt][2], acc[mt][nt][3]);
                if (DUAL) {
                    if (c < 128) {
                        float2 b = *reinterpret_cast<const float2*>(bias0 + c);
                        v0.x += b.x; v0.y += b.y; v1.x += b.x; v1.y += b.y;
                        if (r0 < M)
                            *reinterpret_cast<float2*>(C0 + (size_t)r0 * 128 + c) = v0;
                        if (r0 + 8 < M)
                            *reinterpret_cast<float2*>(C0 + (size_t)(r0 + 8) * 128 + c) = v1;
                    } else {
                        int cc = c - 128;
                        float2 b = *reinterpret_cast<const float2*>(bias1 + cc);
                        v0.x += b.x; v0.y += b.y; v1.x += b.x; v1.y += b.y;
                        if (r0 < M)
                            *reinterpret_cast<float2*>(C1 + (size_t)r0 * 64 + cc) = v0;
                        if (r0 + 8 < M)
                            *reinterpret_cast<float2*>(C1 + (size_t)(r0 + 8) * 64 + cc) = v1;
                    }
                } else {
                    float2 b = *reinterpret_cast<const float2*>(bias0 + c);
                    v0.x += b.x; v0.y += b.y; v1.x += b.x; v1.y += b.y;
                    if (HOUT) {
                        __half* H = reinterpret_cast<__half*>(C0);
                        __half2 h0 = __floats2half2_rn(v0.x, v0.y);
                        __half2 h1 = __floats2half2_rn(v1.x, v1.y);
                        if (r0 < M)
                            *reinterpret_cast<uint32_t*>(H + (size_t)r0 * 256 + c) =
                                *reinterpret_cast<uint32_t*>(&h0);
                        if (r0 + 8 < M)
                            *reinterpret_cast<uint32_t*>(H + (size_t)(r0 + 8) * 256 + c) =
                                *reinterpret_cast<uint32_t*>(&h1);
                    } else {
                        if (r0 < M) {
                            if (addend) {
                                float2 a = *reinterpret_cast<const float2*>(
                                    addend + (size_t)r0 * 256 + c);
                                v0.x += a.x; v0.y += a.y;
                            }
                            *reinterpret_cast<float2*>(C0 + (size_t)r0 * 256 + c) = v0;
                        }
                        if (r0 + 8 < M) {
                            if (addend) {
                                float2 a = *reinterpret_cast<const float2*>(
                                    addend + (size_t)(r0 + 8) * 256 + c);
                                v1.x += a.x; v1.y += a.y;
                            }
                            *reinterpret_cast<float2*>(C0 + (size_t)(r0 + 8) * 256 + c) = v1;
                        }
                    }
                }
            }
        }
    } else {
        // ================= PRODUCERS =================
        const int p = tid - 256;                  // 0..255
        const int bkq = p & 7, bnq = p >> 3;      // B task
        const bool bact = (p < 2 * BN);

        uint32_t stBase = 0;
        for (int ch = 0; ch < NCH; ch++) {
            int s = ch % S;
            const int k0 = ch * 32;
            if (ch >= S) BAR_SYNC(1 + S + s);

            // --- raw loads ---
            float4 rA[4];
            #pragma unroll
            for (int j = 0; j < 4; j++) {
                int idx = p + j * 256;            // 0..1023
                int m = idx >> 3, kq = idx & 7;
                int row = brow + m;
                float4 v = make_float4(0.f, 0.f, 0.f, 0.f);
                if (row < M) {
                    int kg = k0 + kq * 4;
                    const float* src;
                    if (DUAL)
                        src = (kg < 256) ? (A0 + (size_t)row * 256 + kg)
                                         : (A1 + (size_t)row * 256 + (kg - 256));
                    else
                        src = A0 + (size_t)row * KTOT + kg;
                    v = *reinterpret_cast<const float4*>(src);
                }
                rA[j] = v;
            }
            float4 rB[4];
            if (bact) {
                #pragma unroll
                for (int i = 0; i < 4; i++) {
                    int krow = k0 + bkq * 4 + i;
                    int n = bcol + bnq * 4;
                    const float* src;
                    if (DUAL)
                        src = (n < 128) ? (B0 + (size_t)krow * 128 + n)
                                        : (B1 + (size_t)krow * 64 + (n - 128));
                    else
                        src = B0 + (size_t)krow * 256 + n;
                    rB[i] = *reinterpret_cast<const float4*>(src);
                }
            }

            // --- convert + STS into stage s ---
            char* base = smc + stBase;
            #pragma unroll
            for (int j = 0; j < 4; j++) {
                int idx = p + j * 256;
                int m = idx >> 3, kq = idx & 7;
                uint2 av = cvt_h4(rA[j]);
                *reinterpret_cast<uint2*>(base + A_OFF + m * (KP*2) + kq * 8) = av;
            }
            if (bact) {
                #pragma unroll
                for (int j = 0; j < 4; j++) {
                    int n = bnq * 4 + j;
                    float4 kv = make_float4((&rB[0].x)[j], (&rB[1].x)[j],
                                            (&rB[2].x)[j], (&rB[3].x)[j]);
                    uint2 bb = cvt_h4(kv);
                    *reinterpret_cast<uint2*>(base + B_OFF + n * (KP*2) + bkq * 8) = bb;
                }
            }
            BAR_ARRIVE(1 + s);
            stBase += SSTAGE;
            if (stBase == S * SSTAGE) stBase = 0;
        }
    }
}

// ---------------------------------------------------------------------------
// Deformable sampling — vproj fp16; lane loads uint2 = 4 channels.
// ---------------------------------------------------------------------------
__device__ __forceinline__ void accum_h(float4& acc, float w, uint2 u) {
    float2 p0 = __half22float2(*reinterpret_cast<__half2*>(&u.x));
    float2 p1 = __half22float2(*reinterpret_cast<__half2*>(&u.y));
    acc.x = fmaf(w, p0.x, acc.x); acc.y = fmaf(w, p0.y, acc.y);
    acc.z = fmaf(w, p1.x, acc.z); acc.w = fmaf(w, p1.y, acc.w);
}

__global__ void __launch_bounds__(256)
deform_sample_k(const float* __restrict__ vproj,   // fp16 data
                const float* __restrict__ offr,
                const float* __restrict__ awr,
                const float* __restrict__ refp,
                float* __restrict__ samp)
{
    int wg   = (blockIdx.x * 256 + threadIdx.x) >> 5;
    int lane = threadIdx.x & 31;
    int q = wg >> 1;
    if (q >= NQ) return;
    int g = lane >> 3;
    int s = lane & 7;
    int h = ((wg & 1) << 2) | g;

    float rx = fmaf(refp[2*q+0], (float)WW, -0.5f);
    float ry = fmaf(refp[2*q+1], (float)HH, -0.5f);
    const float* offh = offr + (size_t)q*128 + h*16;
    const float* awh  = awr  + (size_t)q*64  + h*8;

    float4 acc = make_float4(0.f,0.f,0.f,0.f);

    #pragma unroll
    for (int nbq = 0; nbq < 2; nbq++) {
        float a0 = awh[nbq*4+0], a1 = awh[nbq*4+1];
        float a2 = awh[nbq*4+2], a3 = awh[nbq*4+3];
        float mx = fmaxf(fmaxf(a0,a1), fmaxf(a2,a3));
        float e0 = __expf(a0-mx), e1 = __expf(a1-mx);
        float e2 = __expf(a2-mx), e3 = __expf(a3-mx);
        float inv = 1.f / (e0+e1+e2+e3);
        float aws[4] = {e0*inv, e1*inv, e2*inv, e3*inv};

        const uint2* vb = reinterpret_cast<const uint2*>(vproj)
                        + ((size_t)nbq*NQ)*64 + h*8 + s;

        #pragma unroll
        for (int p = 0; p < 4; p++) {
            float x = rx + offh[nbq*8 + p*2 + 0];
            float y = ry + offh[nbq*8 + p*2 + 1];
            float xf = floorf(x), yf = floorf(y);
            float fx = x - xf, fy = y - yf;
            int x0 = (int)xf, y0 = (int)yf;
            int x1 = x0 + 1,  y1 = y0 + 1;

            float vx0 = ((unsigned)x0 < WW) ? 1.f : 0.f;
            float vx1 = ((unsigned)x1 < WW) ? 1.f : 0.f;
            float vy0 = ((unsigned)y0 < HH) ? 1.f : 0.f;
            float vy1 = ((unsigned)y1 < HH) ? 1.f : 0.f;
            int cx0 = min(max(x0,0), WW-1), cx1 = min(max(x1,0), WW-1);
            int cy0 = min(max(y0,0), HH-1), cy1 = min(max(y1,0), HH-1);

            float w   = aws[p];
            float gx1 = fx, gx0 = 1.f - fx;
            float gy1 = fy, gy0 = 1.f - fy;
            float w00 = w*gx0*gy0*vx0*vy0;
            float w01 = w*gx1*gy0*vx1*vy0;
            float w10 = w*gx0*gy1*vx0*vy1;
            float w11 = w*gx1*gy1*vx1*vy1;

            uint2 u00 = vb[(size_t)(cy0*WW + cx0) * 64];
            uint2 u01 = vb[(size_t)(cy0*WW + cx1) * 64];
            uint2 u10 = vb[(size_t)(cy1*WW + cx0) * 64];
            uint2 u11 = vb[(size_t)(cy1*WW + cx1) * 64];

            accum_h(acc, w00, u00);
            accum_h(acc, w01, u01);
            accum_h(acc, w10, u10);
            accum_h(acc, w11, u11);
        }
    }
    acc.x *= 0.5f; acc.y *= 0.5f; acc.z *= 0.5f; acc.w *= 0.5f;
    *reinterpret_cast<float4*>(samp + (size_t)q*DD + h*32 + s*4) = acc;
}

// ---------------------------------------------------------------------------
extern "C" void kernel_launch(void* const* d_in, const int* in_sizes, int n_in,
                              void* d_out, int out_size)
{
    const float* query = (const float*)d_in[0];
    const float* value = (const float*)d_in[1];
    const float* refp  = (const float*)d_in[2];
    const float* W_v  = (const float*)d_in[4];
    const float* b_v  = (const float*)d_in[5];
    const float* W_so = (const float*)d_in[6];
    const float* b_so = (const float*)d_in[7];
    const float* W_aw = (const float*)d_in[8];
    const float* b_aw = (const float*)d_in[9];
    const float* W_o  = (const float*)d_in[10];
    const float* b_o  = (const float*)d_in[11];
    float* out = (float*)d_out;

    float *vproj, *offp, *awp, *sampp;
    cudaGetSymbolAddress((void**)&vproj, g_vproj);
    cudaGetSymbolAddress((void**)&offp,  g_off);
    cudaGetSymbolAddress((void**)&awp,   g_aw);
    cudaGetSymbolAddress((void**)&sampp, g_samp);

    // stage: (128 + BN) * 80 bytes; 3 stages
    constexpr int SM128 = 3 * ((128 + 128) * 80);  // 61440 (NTN=4)
    constexpr int SM96  = 3 * ((128 + 96)  * 80);  // 53760 (NTN=3)
    cudaFuncSetAttribute(hmma_gemm<4,0,256,1>,
        cudaFuncAttributeMaxDynamicSharedMemorySize, SM128);
    cudaFuncSetAttribute(hmma_gemm<3,1,512,0>,
        cudaFuncAttributeMaxDynamicSharedMemorySize, SM96);
    cudaFuncSetAttribute(hmma_gemm<4,0,256,0>,
        cudaFuncAttributeMaxDynamicSharedMemorySize, SM128);

    // GEMM1: vproj(fp16) = value @ W_v + b_v    (80000 x 256 x 256)
    hmma_gemm<4,0,256,1><<<dim3(2, 625), 512, SM128>>>(
        value, nullptr, W_v, nullptr, b_v, nullptr, nullptr,
        vproj, nullptr, 2*NQ);

    // GEMM2+3: [value0|query] @ {W_so,W_aw}     (40000 x {128,64} x 512)
    hmma_gemm<3,1,512,0><<<dim3(2, 313), 512, SM96>>>(
        value, query, W_so, W_aw, b_so, b_aw, nullptr,
        offp, awp, NQ);

    // Sampling (fp16 vproj)
    deform_sample_k<<<(NQ*2 + 7)/8, 256>>>(vproj, offp, awp, refp, sampp);

    // GEMM5: out = samp @ W_o + b_o + query     (40000 x 256 x 256)
    hmma_gemm<4,0,256,0><<<dim3(2, 313), 512, SM128>>>(
        sampp, nullptr, W_o, nullptr, b_o, nullptr, query,
        out, nullptr, NQ);
}

// round 14
// speedup vs baseline: 3.2212x; 1.1800x over previous
#include <cuda_runtime.h>
#include <cuda_fp16.h>
#include <cstdint>
#include <cstddef>

#define HH   200
#define WW   200
#define NQ   40000
#define DD   256

__device__ float g_vproj[(size_t)2 * NQ * DD];   // used as fp16 (half occupied)
__device__ float g_off  [(size_t)NQ * 128];
__device__ float g_aw   [(size_t)NQ * 64];
__device__ float g_samp [(size_t)NQ * DD];       // used as fp16 (half occupied)

// ---------------------------------------------------------------------------
// helpers
// ---------------------------------------------------------------------------
__device__ __forceinline__ uint32_t smem_u32(const void* p) {
    uint32_t a;
    asm("{ .reg .u64 t; cvta.to.shared.u64 t, %1; cvt.u32.u64 %0, t; }"
        : "=r"(a) : "l"(p));
    return a;
}
__device__ __forceinline__ uint2 cvt_h4(float4 v) {
    __half2 h01 = __floats2half2_rn(v.x, v.y);
    __half2 h23 = __floats2half2_rn(v.z, v.w);
    uint2 r;
    r.x = *reinterpret_cast<uint32_t*>(&h01);
    r.y = *reinterpret_cast<uint32_t*>(&h23);
    return r;
}
__device__ __forceinline__ void mma_f16(float* c, const uint32_t* a, const uint32_t* b) {
    asm volatile(
        "mma.sync.aligned.m16n8k16.row.col.f32.f16.f16.f32 "
        "{%0,%1,%2,%3}, {%4,%5,%6,%7}, {%8,%9}, {%0,%1,%2,%3};"
        : "+f"(c[0]), "+f"(c[1]), "+f"(c[2]), "+f"(c[3])
        : "r"(a[0]), "r"(a[1]), "r"(a[2]), "r"(a[3]), "r"(b[0]), "r"(b[1]));
}
__device__ __forceinline__ void ldm_x4(uint32_t* r, uint32_t a) {
    asm volatile("ldmatrix.sync.aligned.m8n8.x4.shared.b16 {%0,%1,%2,%3}, [%4];"
        : "=r"(r[0]), "=r"(r[1]), "=r"(r[2]), "=r"(r[3]) : "r"(a));
}
__device__ __forceinline__ void ldm_x2(uint32_t* r, uint32_t a) {
    asm volatile("ldmatrix.sync.aligned.m8n8.x2.shared.b16 {%0,%1}, [%2];"
        : "=r"(r[0]), "=r"(r[1]) : "r"(a));
}
#define BAR_SYNC(id)   asm volatile("bar.sync %0, 512;"   :: "r"(id) : "memory")
#define BAR_ARRIVE(id) asm volatile("bar.arrive %0, 512;" :: "r"(id) : "memory")

// ---------------------------------------------------------------------------
// Warp-specialized plain-fp16 HMMA GEMM, software-pipelined producers.
// 512 threads: warps 0-7 consumers (2m x 4n, warp tile 64 x 8*NTN),
// warps 8-15 producers (double-reg-staged LDG -> cvt -> STS). 3-stage ring.
// K chunks of 32, KP=40 pad. Block covers 128 x BN (BN = 32*NTN).
// DUAL: A = concat(A0,A1) (stride 256 each fp32, KTOT=512); out cols (global)
// [0,128)->C0 (stride 128, bias0), [128,192)->C1 (stride 64, bias1).
// HOUT: C0 is __half* (stride 256). HIN: A0 is __half* (stride KTOT).
// ---------------------------------------------------------------------------
template<int NTN, int DUAL, int KTOT, int HOUT, int HIN>
__global__ void __launch_bounds__(512, 1)
hmma_gemm(const float* __restrict__ A0, const float* __restrict__ A1,
          const float* __restrict__ B0, const float* __restrict__ B1,
          const float* __restrict__ bias0, const float* __restrict__ bias1,
          const float* __restrict__ addend,
          float* __restrict__ C0, float* __restrict__ C1, int M)
{
    constexpr int BN  = 32 * NTN;
    constexpr int KP  = 40;                     // padded row: 80 B
    constexpr int NCH = KTOT / 32;
    constexpr int S   = 3;                      // ring stages
    constexpr uint32_t A_OFF  = 0;
    constexpr uint32_t B_OFF  = 128u * KP * 2;              // 10240
    constexpr uint32_t SSTAGE = B_OFF + (uint32_t)BN * KP * 2;

    extern __shared__ char smc[];
    const uint32_t sb = smem_u32(smc);

    const int tid = threadIdx.x;
    const int wid = tid >> 5, lane = tid & 31;
    const int brow = blockIdx.y * 128;
    const int bcol = blockIdx.x * BN;

    if (wid < 8) {
        // ================= CONSUMERS =================
        const int g = lane >> 2, t = lane & 3;
        const int warp_m = wid >> 2, warp_n = wid & 3;

        float acc[4][NTN][4];
        #pragma unroll
        for (int i = 0; i < 4; i++)
            #pragma unroll
            for (int j = 0; j < NTN; j++)
                #pragma unroll
                for (int k = 0; k < 4; k++) acc[i][j][k] = 0.f;

        const uint32_t aFrag = sb + A_OFF
            + (uint32_t)(warp_m * 64 + (lane & 15)) * (KP * 2)
            + (uint32_t)((lane >> 4) << 4);
        const uint32_t bFragX4 = sb + B_OFF
            + (uint32_t)(warp_n * 8 * NTN + (lane >> 4) * 8 + (lane & 7)) * (KP * 2)
            + (uint32_t)(((lane >> 3) & 1) << 4);
        const uint32_t bFragX2 = sb + B_OFF
            + (uint32_t)(warp_n * 8 * NTN + (NTN - 1) * 8 + (lane & 7)) * (KP * 2)
            + (uint32_t)(((lane >> 3) & 1) << 4);

        uint32_t stBase = 0;
        #pragma unroll
        for (int ch = 0; ch < NCH; ch++) {
            int s = ch % S;
            BAR_SYNC(1 + s);
            #pragma unroll
            for (int ks = 0; ks < 2; ks++) {
                uint32_t Bf[NTN][2];
                #pragma unroll
                for (int ntp = 0; ntp < NTN / 2; ntp++) {
                    uint32_t addr = bFragX4 + stBase
                        + (uint32_t)(ntp * 16 * KP * 2) + (uint32_t)(ks * 32);
                    uint32_t r[4];
                    ldm_x4(r, addr);
                    Bf[2*ntp][0] = r[0]; Bf[2*ntp][1] = r[1];
                    Bf[2*ntp+1][0] = r[2]; Bf[2*ntp+1][1] = r[3];
                }
                if (NTN & 1) {
                    uint32_t addr = bFragX2 + stBase + (uint32_t)(ks * 32);
                    ldm_x2(Bf[NTN-1], addr);
                }
                #pragma unroll
                for (int mt = 0; mt < 4; mt++) {
                    uint32_t Af[4];
                    uint32_t aa = aFrag + stBase
                        + (uint32_t)(mt * 16 * KP * 2) + (uint32_t)(ks * 32);
                    ldm_x4(Af, aa);
                    #pragma unroll
                    for (int nt = 0; nt < NTN; nt++)
                        mma_f16(acc[mt][nt], Af, Bf[nt]);
                }
            }
            BAR_ARRIVE(1 + S + s);
            stBase += SSTAGE;
            if (stBase == S * SSTAGE) stBase = 0;
        }

        // ---- epilogue ----
        #pragma unroll
        for (int mt = 0; mt < 4; mt++) {
            int r0 = brow + warp_m * 64 + mt * 16 + g;
            #pragma unroll
            for (int nt = 0; nt < NTN; nt++) {
                int c = bcol + warp_n * 8 * NTN + nt * 8 + 2 * t;
                float2 v0 = make_float2(acc[mt][nt][0], acc[mt][nt][1]);
                float2 v1 = make_float2(acc[mt][nt][2], acc[mt][nt][3]);
                if (DUAL) {
                    if (c < 128) {
                        float2 b = *reinterpret_cast<const float2*>(bias0 + c);
                        v0.x += b.x; v0.y += b.y; v1.x += b.x; v1.y += b.y;
                        if (r0 < M)
                            *reinterpret_cast<float2*>(C0 + (size_t)r0 * 128 + c) = v0;
                        if (r0 + 8 < M)
                            *reinterpret_cast<float2*>(C0 + (size_t)(r0 + 8) * 128 + c) = v1;
                    } else {
                        int cc = c - 128;
                        float2 b = *reinterpret_cast<const float2*>(bias1 + cc);
                        v0.x += b.x; v0.y += b.y; v1.x += b.x; v1.y += b.y;
                        if (r0 < M)
                            *reinterpret_cast<float2*>(C1 + (size_t)r0 * 64 + cc) = v0;
                        if (r0 + 8 < M)
                            *reinterpret_cast<float2*>(C1 + (size_t)(r0 + 8) * 64 + cc) = v1;
                    }
                } else {
                    float2 b = *reinterpret_cast<const float2*>(bias0 + c);
                    v0.x += b.x; v0.y += b.y; v1.x += b.x; v1.y += b.y;
                    if (HOUT) {
                        __half* H = reinterpret_cast<__half*>(C0);
                        __half2 h0 = __floats2half2_rn(v0.x, v0.y);
                        __half2 h1 = __floats2half2_rn(v1.x, v1.y);
                        if (r0 < M)
                            *reinterpret_cast<uint32_t*>(H + (size_t)r0 * 256 + c) =
                                *reinterpret_cast<uint32_t*>(&h0);
                        if (r0 + 8 < M)
                            *reinterpret_cast<uint32_t*>(H + (size_t)(r0 + 8) * 256 + c) =
                                *reinterpret_cast<uint32_t*>(&h1);
                    } else {
                        if (r0 < M) {
                            if (addend) {
                                float2 a = *reinterpret_cast<const float2*>(
                                    addend + (size_t)r0 * 256 + c);
                                v0.x += a.x; v0.y += a.y;
                            }
                            *reinterpret_cast<float2*>(C0 + (size_t)r0 * 256 + c) = v0;
                        }
                        if (r0 + 8 < M) {
                            if (addend) {
                                float2 a = *reinterpret_cast<const float2*>(
                                    addend + (size_t)(r0 + 8) * 256 + c);
                                v1.x += a.x; v1.y += a.y;
                            }
                            *reinterpret_cast<float2*>(C0 + (size_t)(r0 + 8) * 256 + c) = v1;
                        }
                    }
                }
            }
        }
    } else {
        // ===== PRODUCERS: double-reg-staged software pipeline =====
        const int p = tid - 256;                  // 0..255
        const int bkq = p & 7, bnq = p >> 3;      // B task
        const bool bact = (p < 2 * BN);

        float4 rA[2][4];
        uint4  rA16[2][2];
        float4 rB[2][4];

        auto gload = [&](int ch, int buf) {
            const int k0 = ch * 32;
            if (HIN) {
                const __half* A16 = reinterpret_cast<const __half*>(A0);
                #pragma unroll
                for (int j = 0; j < 2; j++) {
                    int idx2 = p + j * 256;             // 0..511
                    int m = idx2 >> 2, kc = idx2 & 3;   // 8 fp16 per task
                    int row = brow + m;
                    uint4 v = make_uint4(0, 0, 0, 0);
                    if (row < M)
                        v = *reinterpret_cast<const uint4*>(
                            A16 + (size_t)row * KTOT + k0 + kc * 8);
                    rA16[buf][j] = v;
                }
            } else {
                #pragma unroll
                for (int j = 0; j < 4; j++) {
                    int idx = p + j * 256;              // 0..1023
                    int m = idx >> 3, kq = idx & 7;
                    int row = brow + m;
                    float4 v = make_float4(0.f, 0.f, 0.f, 0.f);
                    if (row < M) {
                        int kg = k0 + kq * 4;
                        const float* src;
                        if (DUAL)
                            src = (kg < 256) ? (A0 + (size_t)row * 256 + kg)
                                             : (A1 + (size_t)row * 256 + (kg - 256));
                        else
                            src = A0 + (size_t)row * KTOT + kg;
                        v = *reinterpret_cast<const float4*>(src);
                    }
                    rA[buf][j] = v;
                }
            }
            if (bact) {
                #pragma unroll
                for (int i = 0; i < 4; i++) {
                    int krow = k0 + bkq * 4 + i;
                    int n = bcol + bnq * 4;
                    const float* src;
                    if (DUAL)
                        src = (n < 128) ? (B0 + (size_t)krow * 128 + n)
                                        : (B1 + (size_t)krow * 64 + (n - 128));
                    else
                        src = B0 + (size_t)krow * 256 + n;
                    rB[buf][i] = *reinterpret_cast<const float4*>(src);
                }
            }
        };
        auto csstore = [&](int buf, uint32_t stBase) {
            char* base = smc + stBase;
            if (HIN) {
                #pragma unroll
                for (int j = 0; j < 2; j++) {
                    int idx2 = p + j * 256;
                    int m = idx2 >> 2, kc = idx2 & 3;
                    *reinterpret_cast<uint4*>(base + A_OFF + m * (KP*2) + kc * 16)
                        = rA16[buf][j];
                }
            } else {
                #pragma unroll
                for (int j = 0; j < 4; j++) {
                    int idx = p + j * 256;
                    int m = idx >> 3, kq = idx & 7;
                    uint2 av = cvt_h4(rA[buf][j]);
                    *reinterpret_cast<uint2*>(base + A_OFF + m * (KP*2) + kq * 8) = av;
                }
            }
            if (bact) {
                #pragma unroll
                for (int j = 0; j < 4; j++) {
                    int n = bnq * 4 + j;
                    float4 kv = make_float4((&rB[buf][0].x)[j], (&rB[buf][1].x)[j],
                                            (&rB[buf][2].x)[j], (&rB[buf][3].x)[j]);
                    uint2 bb = cvt_h4(kv);
                    *reinterpret_cast<uint2*>(base + B_OFF + n * (KP*2) + bkq * 8) = bb;
                }
            }
        };

        gload(0, 0);
        uint32_t stBase = 0;
        #pragma unroll
        for (int ch = 0; ch < NCH; ch++) {
            int s = ch % S;
            if (ch + 1 < NCH) gload(ch + 1, (ch + 1) & 1);  // LDGs in flight
            if (ch >= S) BAR_SYNC(1 + S + s);
            csstore(ch & 1, stBase);
            BAR_ARRIVE(1 + s);
            stBase += SSTAGE;
            if (stBase == S * SSTAGE) stBase = 0;
        }
    }
}

// ---------------------------------------------------------------------------
// Deformable sampling — vproj fp16 in, samp fp16 out.
// ---------------------------------------------------------------------------
__device__ __forceinline__ void accum_h(float4& acc, float w, uint2 u) {
    float2 p0 = __half22float2(*reinterpret_cast<__half2*>(&u.x));
    float2 p1 = __half22float2(*reinterpret_cast<__half2*>(&u.y));
    acc.x = fmaf(w, p0.x, acc.x); acc.y = fmaf(w, p0.y, acc.y);
    acc.z = fmaf(w, p1.x, acc.z); acc.w = fmaf(w, p1.y, acc.w);
}

__global__ void __launch_bounds__(256)
deform_sample_k(const float* __restrict__ vproj,   // fp16 data
                const float* __restrict__ offr,
                const float* __restrict__ awr,
                const float* __restrict__ refp,
                float* __restrict__ samp)          // fp16 data out
{
    int wg   = (blockIdx.x * 256 + threadIdx.x) >> 5;
    int lane = threadIdx.x & 31;
    int q = wg >> 1;
    if (q >= NQ) return;
    int g = lane >> 3;
    int s = lane & 7;
    int h = ((wg & 1) << 2) | g;

    float rx = fmaf(refp[2*q+0], (float)WW, -0.5f);
    float ry = fmaf(refp[2*q+1], (float)HH, -0.5f);
    const float* offh = offr + (size_t)q*128 + h*16;
    const float* awh  = awr  + (size_t)q*64  + h*8;

    float4 acc = make_float4(0.f,0.f,0.f,0.f);

    #pragma unroll
    for (int nbq = 0; nbq < 2; nbq++) {
        float a0 = awh[nbq*4+0], a1 = awh[nbq*4+1];
        float a2 = awh[nbq*4+2], a3 = awh[nbq*4+3];
        float mx = fmaxf(fmaxf(a0,a1), fmaxf(a2,a3));
        float e0 = __expf(a0-mx), e1 = __expf(a1-mx);
        float e2 = __expf(a2-mx), e3 = __expf(a3-mx);
        float inv = 1.f / (e0+e1+e2+e3);
        float aws[4] = {e0*inv, e1*inv, e2*inv, e3*inv};

        const uint2* vb = reinterpret_cast<const uint2*>(vproj)
                        + ((size_t)nbq*NQ)*64 + h*8 + s;

        #pragma unroll
        for (int p = 0; p < 4; p++) {
            float x = rx + offh[nbq*8 + p*2 + 0];
            float y = ry + offh[nbq*8 + p*2 + 1];
            float xf = floorf(x), yf = floorf(y);
            float fx = x - xf, fy = y - yf;
            int x0 = (int)xf, y0 = (int)yf;
            int x1 = x0 + 1,  y1 = y0 + 1;

            float vx0 = ((unsigned)x0 < WW) ? 1.f : 0.f;
            float vx1 = ((unsigned)x1 < WW) ? 1.f : 0.f;
            float vy0 = ((unsigned)y0 < HH) ? 1.f : 0.f;
            float vy1 = ((unsigned)y1 < HH) ? 1.f : 0.f;
            int cx0 = min(max(x0,0), WW-1), cx1 = min(max(x1,0), WW-1);
            int cy0 = min(max(y0,0), HH-1), cy1 = min(max(y1,0), HH-1);

            float w   = aws[p];
            float gx1 = fx, gx0 = 1.f - fx;
            float gy1 = fy, gy0 = 1.f - fy;
            float w00 = w*gx0*gy0*vx0*vy0;
            float w01 = w*gx1*gy0*vx1*vy0;
            float w10 = w*gx0*gy1*vx0*vy1;
            float w11 = w*gx1*gy1*vx1*vy1;

            uint2 u00 = vb[(size_t)(cy0*WW + cx0) * 64];
            uint2 u01 = vb[(size_t)(cy0*WW + cx1) * 64];
            uint2 u10 = vb[(size_t)(cy1*WW + cx0) * 64];
            uint2 u11 = vb[(size_t)(cy1*WW + cx1) * 64];

            accum_h(acc, w00, u00);
            accum_h(acc, w01, u01);
            accum_h(acc, w10, u10);
            accum_h(acc, w11, u11);
        }
    }
    acc.x *= 0.5f; acc.y *= 0.5f; acc.z *= 0.5f; acc.w *= 0.5f;
    __half2 h0 = __floats2half2_rn(acc.x, acc.y);
    __half2 h1 = __floats2half2_rn(acc.z, acc.w);
    uint2 st;
    st.x = *reinterpret_cast<uint32_t*>(&h0);
    st.y = *reinterpret_cast<uint32_t*>(&h1);
    *reinterpret_cast<uint2*>(
        reinterpret_cast<__half*>(samp) + (size_t)q*DD + h*32 + s*4) = st;
}

// ---------------------------------------------------------------------------
extern "C" void kernel_launch(void* const* d_in, const int* in_sizes, int n_in,
                              void* d_out, int out_size)
{
    const float* query = (const float*)d_in[0];
    const float* value = (const float*)d_in[1];
    const float* refp  = (const float*)d_in[2];
    const float* W_v  = (const float*)d_in[4];
    const float* b_v  = (const float*)d_in[5];
    const float* W_so = (const float*)d_in[6];
    const float* b_so = (const float*)d_in[7];
    const float* W_aw = (const float*)d_in[8];
    const float* b_aw = (const float*)d_in[9];
    const float* W_o  = (const float*)d_in[10];
    const float* b_o  = (const float*)d_in[11];
    float* out = (float*)d_out;

    float *vproj, *offp, *awp, *sampp;
    cudaGetSymbolAddress((void**)&vproj, g_vproj);
    cudaGetSymbolAddress((void**)&offp,  g_off);
    cudaGetSymbolAddress((void**)&awp,   g_aw);
    cudaGetSymbolAddress((void**)&sampp, g_samp);

    // stage: (128 + BN) * 80 bytes; 3 stages
    constexpr int SM128 = 3 * ((128 + 128) * 80);  // 61440 (NTN=4)
    constexpr int SM96  = 3 * ((128 + 96)  * 80);  // 53760 (NTN=3)
    cudaFuncSetAttribute(hmma_gemm<4,0,256,1,0>,
        cudaFuncAttributeMaxDynamicSharedMemorySize, SM128);
    cudaFuncSetAttribute(hmma_gemm<3,1,512,0,0>,
        cudaFuncAttributeMaxDynamicSharedMemorySize, SM96);
    cudaFuncSetAttribute(hmma_gemm<4,0,256,0,1>,
        cudaFuncAttributeMaxDynamicSharedMemorySize, SM128);

    // GEMM1: vproj(fp16) = value @ W_v + b_v    (80000 x 256 x 256)
    hmma_gemm<4,0,256,1,0><<<dim3(2, 625), 512, SM128>>>(
        value, nullptr, W_v, nullptr, b_v, nullptr, nullptr,
        vproj, nullptr, 2*NQ);

    // GEMM2+3: [value0|query] @ {W_so,W_aw}     (40000 x {128,64} x 512)
    hmma_gemm<3,1,512,0,0><<<dim3(2, 313), 512, SM96>>>(
        value, query, W_so, W_aw, b_so, b_aw, nullptr,
        offp, awp, NQ);

    // Sampling (fp16 vproj -> fp16 samp)
    deform_sample_k<<<(NQ*2 + 7)/8, 256>>>(vproj, offp, awp, refp, sampp);

    // GEMM5: out = samp(fp16) @ W_o + b_o + query  (40000 x 256 x 256)
    hmma_gemm<4,0,256,0,1><<<dim3(2, 313), 512, SM128>>>(
        sampp, nullptr, W_o, nullptr, b_o, nullptr, query,
        out, nullptr, NQ);
}